// round 1
// baseline (speedup 1.0000x reference)
#include <cuda_runtime.h>
#include <cuda_bf16.h>
#include <math.h>

// Problem constants
#define B_SZ 2
#define S_SZ 2048
#define HID 4096
#define NH 32
#define HD 128
#define TOK (B_SZ * S_SZ)          // 4096 tokens
#define PROJ3 (3 * HID)            // 12288

// Scratch (static device globals — allocation-free rule)
__device__ float g_proj[(size_t)TOK * PROJ3];   // [4096, 12288] q|k|v
__device__ float g_attn[(size_t)TOK * HID];     // [4096, 4096] attention output

// ---------------------------------------------------------------------------
// SGEMM: C[M,N] = A[M,K] * B[N,K]^T   (A, B row-major, C row-major)
// 128x128 tile, BK=16, 256 threads, 8x8 per thread.
// ---------------------------------------------------------------------------
__global__ __launch_bounds__(256, 2)
void sgemm_nt(const float* __restrict__ A, const float* __restrict__ Bm,
              float* __restrict__ C, int M, int N, int K)
{
    __shared__ float As[16][128];
    __shared__ float Bs[16][128];

    const int tid = threadIdx.x;
    const int tx = tid & 15;         // col group
    const int ty = tid >> 4;         // row group
    const int m0 = blockIdx.y * 128;
    const int n0 = blockIdx.x * 128;

    const float* Ab = A + (size_t)m0 * K;
    const float* Bb = Bm + (size_t)n0 * K;

    float acc[8][8];
#pragma unroll
    for (int i = 0; i < 8; i++)
#pragma unroll
        for (int j = 0; j < 8; j++) acc[i][j] = 0.f;

    for (int k0 = 0; k0 < K; k0 += 16) {
        // load A,B tiles (transposed into smem: [k][row])
#pragma unroll
        for (int i = 0; i < 2; i++) {
            int f = tid * 2 + i;             // 0..511
            int row = f >> 2;                // 0..127
            int kk4 = (f & 3) * 4;           // 0,4,8,12
            float4 av = *(const float4*)&Ab[(size_t)row * K + k0 + kk4];
            As[kk4 + 0][row] = av.x; As[kk4 + 1][row] = av.y;
            As[kk4 + 2][row] = av.z; As[kk4 + 3][row] = av.w;
            float4 bv = *(const float4*)&Bb[(size_t)row * K + k0 + kk4];
            Bs[kk4 + 0][row] = bv.x; Bs[kk4 + 1][row] = bv.y;
            Bs[kk4 + 2][row] = bv.z; Bs[kk4 + 3][row] = bv.w;
        }
        __syncthreads();

#pragma unroll
        for (int kk = 0; kk < 16; kk++) {
            float a[8], b[8];
            float4 a0 = *(const float4*)&As[kk][ty * 8];
            float4 a1 = *(const float4*)&As[kk][ty * 8 + 4];
            float4 b0 = *(const float4*)&Bs[kk][tx * 8];
            float4 b1 = *(const float4*)&Bs[kk][tx * 8 + 4];
            a[0]=a0.x;a[1]=a0.y;a[2]=a0.z;a[3]=a0.w;a[4]=a1.x;a[5]=a1.y;a[6]=a1.z;a[7]=a1.w;
            b[0]=b0.x;b[1]=b0.y;b[2]=b0.z;b[3]=b0.w;b[4]=b1.x;b[5]=b1.y;b[6]=b1.z;b[7]=b1.w;
#pragma unroll
            for (int i = 0; i < 8; i++)
#pragma unroll
                for (int j = 0; j < 8; j++)
                    acc[i][j] = fmaf(a[i], b[j], acc[i][j]);
        }
        __syncthreads();
    }

    // epilogue
#pragma unroll
    for (int i = 0; i < 8; i++) {
        float* crow = C + (size_t)(m0 + ty * 8 + i) * N + n0 + tx * 8;
        float4 c0 = {acc[i][0], acc[i][1], acc[i][2], acc[i][3]};
        float4 c1 = {acc[i][4], acc[i][5], acc[i][6], acc[i][7]};
        *(float4*)crow = c0;
        *(float4*)(crow + 4) = c1;
    }
}

// ---------------------------------------------------------------------------
// RoPE (GPT-NeoX half-split) applied in-place to q and k slices of g_proj.
// One thread per (token, head, pair).
// ---------------------------------------------------------------------------
__global__ void rope_kernel(float* __restrict__ proj, const int* __restrict__ positions)
{
    int idx = blockIdx.x * blockDim.x + threadIdx.x;  // < 4096*32*64
    int i = idx & 63;            // pair index 0..63
    int h = (idx >> 6) & 31;     // head
    int t = idx >> 11;           // token 0..4095

    int pos = positions[t];
    // inv_freq = 10000^(-i/64) = 2^(-i * log2(10000)/64)
    float inv = exp2f(-(float)i * (13.287712379549449f / 64.0f));
    float freq = (float)pos * inv;
    float sn, cs;
    sincosf(freq, &sn, &cs);

    size_t qb = (size_t)t * PROJ3 + (size_t)h * HD + i;
    // q
    {
        float x1 = proj[qb], x2 = proj[qb + 64];
        proj[qb]      = x1 * cs - x2 * sn;
        proj[qb + 64] = x2 * cs + x1 * sn;
    }
    // k
    {
        size_t kb = qb + HID;
        float x1 = proj[kb], x2 = proj[kb + 64];
        proj[kb]      = x1 * cs - x2 * sn;
        proj[kb + 64] = x2 * cs + x1 * sn;
    }
}

// ---------------------------------------------------------------------------
// Flash-attention style causal attention (fp32).
// Grid: (S/64 q-blocks, B*NH). Block: 256 threads (16x16), 64x64 score tile.
// Each thread: 4x4 of S, 4 rows x 8 cols of O.
// ---------------------------------------------------------------------------
#define FL_SMEM_FLOATS (128*68 + 128*68 + 64*132 + 64*65)

__global__ __launch_bounds__(256, 1)
void flash_attn(const float* __restrict__ proj, float* __restrict__ attn)
{
    extern __shared__ float sm[];
    float* qt = sm;                      // [128][68] Q^T (d-major)
    float* kt = sm + 128 * 68;           // [128][68] K^T
    float* vs = sm + 2 * 128 * 68;       // [64][132] V
    float* ps = sm + 2 * 128 * 68 + 64 * 132;  // [64][65] P

    const int tid = threadIdx.x;
    const int tx = tid & 15;
    const int ty = tid >> 4;
    const int r0 = ty * 4;               // local q rows r0..r0+3
    const int c0 = tx * 4;               // local k cols c0..c0+3 (score phase)
    const int ox0 = tx * 8;              // O cols ox0..ox0+7

    const int qb = blockIdx.x;           // q block (0..31)
    const int bh = blockIdx.y;           // 0..63
    const int b = bh >> 5;
    const int h = bh & 31;
    const int tok0 = b * S_SZ + qb * 64;

    const float scale = 0.08838834764831845f;  // 1/sqrt(128)

    // Load Q tile (scaled) transposed into qt[d][row]
    const float* qg = proj + (size_t)tok0 * PROJ3 + (size_t)h * HD;
#pragma unroll
    for (int j = 0; j < 8; j++) {
        int f = tid + j * 256;           // 0..2047
        int row = f >> 5;                // 0..63
        int d0 = (f & 31) * 4;
        float4 v = *(const float4*)(qg + (size_t)row * PROJ3 + d0);
        qt[(d0 + 0) * 68 + row] = v.x * scale;
        qt[(d0 + 1) * 68 + row] = v.y * scale;
        qt[(d0 + 2) * 68 + row] = v.z * scale;
        qt[(d0 + 3) * 68 + row] = v.w * scale;
    }

    float acc[4][8];
    float m_old[4], l_run[4];
#pragma unroll
    for (int ri = 0; ri < 4; ri++) {
        m_old[ri] = -1e30f;
        l_run[ri] = 0.f;
#pragma unroll
        for (int c = 0; c < 8; c++) acc[ri][c] = 0.f;
    }

    for (int kb = 0; kb <= qb; kb++) {
        __syncthreads();  // previous iteration done reading kt/vs/ps

        // Load K tile transposed, V tile natural
        const float* kg = proj + (size_t)(b * S_SZ + kb * 64) * PROJ3 + HID + (size_t)h * HD;
        const float* vg = kg + HID;
#pragma unroll
        for (int j = 0; j < 8; j++) {
            int f = tid + j * 256;
            int row = f >> 5;
            int d0 = (f & 31) * 4;
            float4 kv = *(const float4*)(kg + (size_t)row * PROJ3 + d0);
            kt[(d0 + 0) * 68 + row] = kv.x;
            kt[(d0 + 1) * 68 + row] = kv.y;
            kt[(d0 + 2) * 68 + row] = kv.z;
            kt[(d0 + 3) * 68 + row] = kv.w;
            float4 vv = *(const float4*)(vg + (size_t)row * PROJ3 + d0);
            *(float4*)&vs[row * 132 + d0] = vv;
        }
        __syncthreads();

        // S = Q K^T (4x4 per thread)
        float s[4][4];
#pragma unroll
        for (int ri = 0; ri < 4; ri++)
#pragma unroll
            for (int ci = 0; ci < 4; ci++) s[ri][ci] = 0.f;

#pragma unroll 4
        for (int d = 0; d < 128; d++) {
            float4 a = *(const float4*)&qt[d * 68 + r0];
            float4 bb = *(const float4*)&kt[d * 68 + c0];
            s[0][0] = fmaf(a.x, bb.x, s[0][0]); s[0][1] = fmaf(a.x, bb.y, s[0][1]);
            s[0][2] = fmaf(a.x, bb.z, s[0][2]); s[0][3] = fmaf(a.x, bb.w, s[0][3]);
            s[1][0] = fmaf(a.y, bb.x, s[1][0]); s[1][1] = fmaf(a.y, bb.y, s[1][1]);
            s[1][2] = fmaf(a.y, bb.z, s[1][2]); s[1][3] = fmaf(a.y, bb.w, s[1][3]);
            s[2][0] = fmaf(a.z, bb.x, s[2][0]); s[2][1] = fmaf(a.z, bb.y, s[2][1]);
            s[2][2] = fmaf(a.z, bb.z, s[2][2]); s[2][3] = fmaf(a.z, bb.w, s[2][3]);
            s[3][0] = fmaf(a.w, bb.x, s[3][0]); s[3][1] = fmaf(a.w, bb.y, s[3][1]);
            s[3][2] = fmaf(a.w, bb.z, s[3][2]); s[3][3] = fmaf(a.w, bb.w, s[3][3]);
        }

        // causal mask on the diagonal block
        if (kb == qb) {
#pragma unroll
            for (int ri = 0; ri < 4; ri++)
#pragma unroll
                for (int ci = 0; ci < 4; ci++)
                    if (c0 + ci > r0 + ri) s[ri][ci] = -1e30f;
        }

        // online softmax
        float m_new[4], alpha[4], psum[4];
#pragma unroll
        for (int ri = 0; ri < 4; ri++) {
            float mx = fmaxf(fmaxf(s[ri][0], s[ri][1]), fmaxf(s[ri][2], s[ri][3]));
            mx = fmaxf(mx, __shfl_xor_sync(0xffffffffu, mx, 1));
            mx = fmaxf(mx, __shfl_xor_sync(0xffffffffu, mx, 2));
            mx = fmaxf(mx, __shfl_xor_sync(0xffffffffu, mx, 4));
            mx = fmaxf(mx, __shfl_xor_sync(0xffffffffu, mx, 8));
            m_new[ri] = fmaxf(m_old[ri], mx);
            alpha[ri] = __expf(m_old[ri] - m_new[ri]);

            float rs = 0.f;
#pragma unroll
            for (int ci = 0; ci < 4; ci++) {
                float p = __expf(s[ri][ci] - m_new[ri]);
                s[ri][ci] = p;
                rs += p;
            }
            rs += __shfl_xor_sync(0xffffffffu, rs, 1);
            rs += __shfl_xor_sync(0xffffffffu, rs, 2);
            rs += __shfl_xor_sync(0xffffffffu, rs, 4);
            rs += __shfl_xor_sync(0xffffffffu, rs, 8);
            psum[ri] = rs;
        }

        // write P to smem, rescale O accumulators
#pragma unroll
        for (int ri = 0; ri < 4; ri++) {
            ps[(r0 + ri) * 65 + c0 + 0] = s[ri][0];
            ps[(r0 + ri) * 65 + c0 + 1] = s[ri][1];
            ps[(r0 + ri) * 65 + c0 + 2] = s[ri][2];
            ps[(r0 + ri) * 65 + c0 + 3] = s[ri][3];
            float a = alpha[ri];
#pragma unroll
            for (int c = 0; c < 8; c++) acc[ri][c] *= a;
            l_run[ri] = l_run[ri] * a + psum[ri];
            m_old[ri] = m_new[ri];
        }
        __syncthreads();

        // O += P V
#pragma unroll 2
        for (int kk = 0; kk < 64; kk++) {
            float p0 = ps[(r0 + 0) * 65 + kk];
            float p1 = ps[(r0 + 1) * 65 + kk];
            float p2 = ps[(r0 + 2) * 65 + kk];
            float p3 = ps[(r0 + 3) * 65 + kk];
            float4 v0 = *(const float4*)&vs[kk * 132 + ox0];
            float4 v1 = *(const float4*)&vs[kk * 132 + ox0 + 4];
            acc[0][0]=fmaf(p0,v0.x,acc[0][0]); acc[0][1]=fmaf(p0,v0.y,acc[0][1]);
            acc[0][2]=fmaf(p0,v0.z,acc[0][2]); acc[0][3]=fmaf(p0,v0.w,acc[0][3]);
            acc[0][4]=fmaf(p0,v1.x,acc[0][4]); acc[0][5]=fmaf(p0,v1.y,acc[0][5]);
            acc[0][6]=fmaf(p0,v1.z,acc[0][6]); acc[0][7]=fmaf(p0,v1.w,acc[0][7]);
            acc[1][0]=fmaf(p1,v0.x,acc[1][0]); acc[1][1]=fmaf(p1,v0.y,acc[1][1]);
            acc[1][2]=fmaf(p1,v0.z,acc[1][2]); acc[1][3]=fmaf(p1,v0.w,acc[1][3]);
            acc[1][4]=fmaf(p1,v1.x,acc[1][4]); acc[1][5]=fmaf(p1,v1.y,acc[1][5]);
            acc[1][6]=fmaf(p1,v1.z,acc[1][6]); acc[1][7]=fmaf(p1,v1.w,acc[1][7]);
            acc[2][0]=fmaf(p2,v0.x,acc[2][0]); acc[2][1]=fmaf(p2,v0.y,acc[2][1]);
            acc[2][2]=fmaf(p2,v0.z,acc[2][2]); acc[2][3]=fmaf(p2,v0.w,acc[2][3]);
            acc[2][4]=fmaf(p2,v1.x,acc[2][4]); acc[2][5]=fmaf(p2,v1.y,acc[2][5]);
            acc[2][6]=fmaf(p2,v1.z,acc[2][6]); acc[2][7]=fmaf(p2,v1.w,acc[2][7]);
            acc[3][0]=fmaf(p3,v0.x,acc[3][0]); acc[3][1]=fmaf(p3,v0.y,acc[3][1]);
            acc[3][2]=fmaf(p3,v0.z,acc[3][2]); acc[3][3]=fmaf(p3,v0.w,acc[3][3]);
            acc[3][4]=fmaf(p3,v1.x,acc[3][4]); acc[3][5]=fmaf(p3,v1.y,acc[3][5]);
            acc[3][6]=fmaf(p3,v1.z,acc[3][6]); acc[3][7]=fmaf(p3,v1.w,acc[3][7]);
        }
    }

    // epilogue: normalize and store to g_attn [token][h*128 + col]
#pragma unroll
    for (int ri = 0; ri < 4; ri++) {
        float inv_l = 1.f / l_run[ri];
        float* orow = attn + (size_t)(tok0 + r0 + ri) * HID + (size_t)h * HD + ox0;
        float4 o0 = {acc[ri][0] * inv_l, acc[ri][1] * inv_l, acc[ri][2] * inv_l, acc[ri][3] * inv_l};
        float4 o1 = {acc[ri][4] * inv_l, acc[ri][5] * inv_l, acc[ri][6] * inv_l, acc[ri][7] * inv_l};
        *(float4*)orow = o0;
        *(float4*)(orow + 4) = o1;
    }
}

// ---------------------------------------------------------------------------
// Launch
// ---------------------------------------------------------------------------
extern "C" void kernel_launch(void* const* d_in, const int* in_sizes, int n_in,
                              void* d_out, int out_size)
{
    const float* hidden = (const float*)d_in[0];   // [2,2048,4096]
    const int* positions = (const int*)d_in[1];    // [2,2048]
    const float* W_pack = (const float*)d_in[2];   // [12288,4096]
    const float* W_o = (const float*)d_in[3];      // [4096,4096]
    float* out = (float*)d_out;                    // [2,2048,4096]

    void* pp; cudaGetSymbolAddress(&pp, g_proj);
    void* ap; cudaGetSymbolAddress(&ap, g_attn);
    float* proj = (float*)pp;
    float* attn = (float*)ap;

    // 1) QKV projection: proj = hidden @ W_pack^T  [4096 x 12288]
    {
        dim3 grid(PROJ3 / 128, TOK / 128);
        sgemm_nt<<<grid, 256>>>(hidden, W_pack, proj, TOK, PROJ3, HID);
    }

    // 2) RoPE on q,k
    {
        int total = TOK * NH * 64;
        rope_kernel<<<total / 256, 256>>>(proj, positions);
    }

    // 3) Causal attention
    {
        static const size_t smem = FL_SMEM_FLOATS * sizeof(float);
        cudaFuncSetAttribute(flash_attn, cudaFuncAttributeMaxDynamicSharedMemorySize, (int)smem);
        dim3 grid(S_SZ / 64, B_SZ * NH);
        flash_attn<<<grid, 256, smem>>>(proj, attn);
    }

    // 4) Output projection: out = attn @ W_o^T  [4096 x 4096]
    {
        dim3 grid(HID / 128, TOK / 128);
        sgemm_nt<<<grid, 256>>>(attn, W_o, out, TOK, HID, HID);
    }
}

// round 3
// speedup vs baseline: 1.9154x; 1.9154x over previous
#include <cuda_runtime.h>
#include <cuda_bf16.h>
#include <math.h>
#include <stdint.h>

// Problem constants
#define B_SZ 2
#define S_SZ 2048
#define HID 4096
#define NH 32
#define HD 128
#define TOK (B_SZ * S_SZ)          // 4096 tokens
#define PROJ3 (3 * HID)            // 12288

// Scratch (static device globals — allocation-free rule)
__device__ float g_proj[(size_t)TOK * PROJ3];   // [4096, 12288] q|k|v (fp32)
__device__ float g_attn[(size_t)TOK * HID];     // [4096, 4096] attention output (fp32)
// bf16 hi/lo splits for tensor-core GEMMs
__device__ __nv_bfloat16 g_Ah[(size_t)TOK * HID];
__device__ __nv_bfloat16 g_Al[(size_t)TOK * HID];
__device__ __nv_bfloat16 g_Wph[(size_t)PROJ3 * HID];
__device__ __nv_bfloat16 g_Wpl[(size_t)PROJ3 * HID];
__device__ __nv_bfloat16 g_Woh[(size_t)HID * HID];
__device__ __nv_bfloat16 g_Wol[(size_t)HID * HID];
__device__ __nv_bfloat16 g_Xh[(size_t)TOK * HID];
__device__ __nv_bfloat16 g_Xl[(size_t)TOK * HID];

// ---------------------------------------------------------------------------
// Inline PTX helpers (arch-portable: cp.async + ldmatrix + mma.sync only)
// ---------------------------------------------------------------------------
__device__ __forceinline__ uint32_t smem_u32(const void* p) {
    uint32_t a;
    asm("{ .reg .u64 t; cvta.to.shared.u64 t, %1; cvt.u32.u64 %0, t; }" : "=r"(a) : "l"(p));
    return a;
}
__device__ __forceinline__ void cp16(uint32_t dst, const void* src) {
    asm volatile("cp.async.cg.shared.global [%0], [%1], 16;" :: "r"(dst), "l"(src) : "memory");
}
__device__ __forceinline__ void cp_commit() { asm volatile("cp.async.commit_group;" ::: "memory"); }
template <int N>
__device__ __forceinline__ void cp_wait() {
    asm volatile("cp.async.wait_group %0;" :: "n"(N) : "memory");
}
__device__ __forceinline__ void ldsm4(uint32_t r[4], uint32_t addr) {
    asm volatile("ldmatrix.sync.aligned.m8n8.x4.shared.b16 {%0,%1,%2,%3}, [%4];"
                 : "=r"(r[0]), "=r"(r[1]), "=r"(r[2]), "=r"(r[3]) : "r"(addr));
}
__device__ __forceinline__ void mma16816(float c[4], const uint32_t a[4], const uint32_t b[2]) {
    asm volatile(
        "mma.sync.aligned.m16n8k16.row.col.f32.bf16.bf16.f32 "
        "{%0,%1,%2,%3}, {%4,%5,%6,%7}, {%8,%9}, {%0,%1,%2,%3};"
        : "+f"(c[0]), "+f"(c[1]), "+f"(c[2]), "+f"(c[3])
        : "r"(a[0]), "r"(a[1]), "r"(a[2]), "r"(a[3]), "r"(b[0]), "r"(b[1]));
}

// ---------------------------------------------------------------------------
// fp32 -> bf16 hi/lo split.  Each thread handles 8 elements.
// ---------------------------------------------------------------------------
__global__ void split_bf16(const float* __restrict__ x, __nv_bfloat16* __restrict__ hi,
                           __nv_bfloat16* __restrict__ lo, int n8)
{
    int i = blockIdx.x * blockDim.x + threadIdx.x;
    if (i >= n8) return;
    const float4* xp = (const float4*)x + (size_t)i * 2;
    float4 a = xp[0], b = xp[1];
    float v[8] = {a.x, a.y, a.z, a.w, b.x, b.y, b.z, b.w};
    __nv_bfloat16 h[8], l[8];
#pragma unroll
    for (int j = 0; j < 8; j++) {
        h[j] = __float2bfloat16_rn(v[j]);
        l[j] = __float2bfloat16_rn(v[j] - __bfloat162float(h[j]));
    }
    *((uint4*)hi + i) = *(const uint4*)h;
    *((uint4*)lo + i) = *(const uint4*)l;
}

// ---------------------------------------------------------------------------
// HMMA bf16x3 GEMM: C[M,N] = (Ah+Al)[M,K] @ (Bh+Bl)[N,K]^T  (drop Al*Bl term)
// CTA tile 128x128, BK=32, 3-stage cp.async pipeline, 256 thr (8 warps 2x4),
// warp tile 64x32 via mma.sync m16n8k16.
// ---------------------------------------------------------------------------
#define BM 128
#define BN 128
#define BK 32
#define STAGES 3
#define PADK 40                       // halves per smem row (32 + 8 pad)
#define TILEB (128 * PADK * 2)        // bytes per [128][40] bf16 tile = 10240
#define STAGEB (4 * TILEB)            // Ah, Al, Bh, Bl = 40960
#define GEMM_SMEM (STAGES * STAGEB)   // 122880

__global__ __launch_bounds__(256, 1)
void gemm_bf16x3(const __nv_bfloat16* __restrict__ Ah, const __nv_bfloat16* __restrict__ Al,
                 const __nv_bfloat16* __restrict__ Bh, const __nv_bfloat16* __restrict__ Bl,
                 float* __restrict__ C, int N, int K)
{
    extern __shared__ char smraw[];
    const uint32_t sbase = smem_u32(smraw);

    const int tid = threadIdx.x;
    const int wid = tid >> 5;
    const int lane = tid & 31;
    const int wm = wid >> 2;          // 0..1  (64 rows each)
    const int wn = wid & 3;           // 0..3  (32 cols each)
    const int m0 = blockIdx.y * BM;
    const int n0 = blockIdx.x * BN;
    const int NCH = K >> 5;           // K/32 chunks

    // ---- async loader for one chunk into stage buffer ----
    auto load_chunk = [&](int c, int stg) {
        const uint32_t sb = sbase + stg * STAGEB;
        const int kc = c * BK;
        // 512 16B-chunks per tile; 256 threads x 2
#pragma unroll
        for (int i = 0; i < 2; i++) {
            int op = tid + i * 256;       // 0..511
            int row = op >> 2;            // 0..127
            int ck = op & 3;              // 16B chunk in row
            uint32_t soff = (uint32_t)(row * PADK * 2 + ck * 16);
            size_t goff = (size_t)row * K + kc + ck * 8;
            cp16(sb + soff,              Ah + (size_t)m0 * K + goff);
            cp16(sb + TILEB + soff,      Al + (size_t)m0 * K + goff);
            cp16(sb + 2 * TILEB + soff,  Bh + (size_t)n0 * K + goff);
            cp16(sb + 3 * TILEB + soff,  Bl + (size_t)n0 * K + goff);
        }
        cp_commit();
    };

    float c[4][4][4];
#pragma unroll
    for (int i = 0; i < 4; i++)
#pragma unroll
        for (int j = 0; j < 4; j++)
#pragma unroll
            for (int q = 0; q < 4; q++) c[i][j][q] = 0.f;

    // prologue: stages 0,1
    load_chunk(0, 0);
    load_chunk(1, 1);

    // per-lane ldmatrix address components
    const int a_row = (lane & 15);                    // + frag base
    const int a_col = ((lane >> 4) & 1) * 8;          // halves
    const int b_row = (lane & 7) + ((lane & 16) ? 8 : 0);
    const int b_col = ((lane & 8) ? 8 : 0);

    for (int cch = 0; cch < NCH; cch++) {
        cp_wait<1>();
        __syncthreads();

        // prefetch chunk c+2 (or commit empty group to keep accounting uniform)
        if (cch + 2 < NCH) load_chunk(cch + 2, (cch + 2) % STAGES);
        else cp_commit();

        const uint32_t sb = sbase + (cch % STAGES) * STAGEB;
        const uint32_t aHb = sb;
        const uint32_t aLb = sb + TILEB;
        const uint32_t bHb = sb + 2 * TILEB;
        const uint32_t bLb = sb + 3 * TILEB;

#pragma unroll
        for (int s = 0; s < 2; s++) {                 // k-steps of 16
            uint32_t ah[16], al[16], bh[8], bl[8];
#pragma unroll
            for (int i = 0; i < 4; i++) {
                int row = wm * 64 + i * 16 + a_row;
                uint32_t off = (uint32_t)((row * PADK + s * 16 + a_col) * 2);
                ldsm4(&ah[i * 4], aHb + off);
                ldsm4(&al[i * 4], aLb + off);
            }
#pragma unroll
            for (int j2 = 0; j2 < 2; j2++) {
                int row = wn * 32 + j2 * 16 + b_row;
                uint32_t off = (uint32_t)((row * PADK + s * 16 + b_col) * 2);
                ldsm4(&bh[j2 * 4], bHb + off);
                ldsm4(&bl[j2 * 4], bLb + off);
            }
            // term 1: Ah*Bh
#pragma unroll
            for (int i = 0; i < 4; i++)
#pragma unroll
                for (int j = 0; j < 4; j++)
                    mma16816(c[i][j], &ah[i * 4], &bh[j * 2]);
            // term 2: Ah*Bl
#pragma unroll
            for (int i = 0; i < 4; i++)
#pragma unroll
                for (int j = 0; j < 4; j++)
                    mma16816(c[i][j], &ah[i * 4], &bl[j * 2]);
            // term 3: Al*Bh
#pragma unroll
            for (int i = 0; i < 4; i++)
#pragma unroll
                for (int j = 0; j < 4; j++)
                    mma16816(c[i][j], &al[i * 4], &bh[j * 2]);
        }
        __syncthreads();
    }

    // epilogue
    const int g = lane >> 2;
    const int tq = lane & 3;
#pragma unroll
    for (int i = 0; i < 4; i++) {
        int row0 = m0 + wm * 64 + i * 16 + g;
#pragma unroll
        for (int j = 0; j < 4; j++) {
            int col = n0 + wn * 32 + j * 8 + tq * 2;
            float2 v0 = {c[i][j][0], c[i][j][1]};
            float2 v1 = {c[i][j][2], c[i][j][3]};
            *(float2*)&C[(size_t)row0 * N + col] = v0;
            *(float2*)&C[(size_t)(row0 + 8) * N + col] = v1;
        }
    }
}

// ---------------------------------------------------------------------------
// RoPE (GPT-NeoX half-split) applied in-place to q and k slices of g_proj.
// ---------------------------------------------------------------------------
__global__ void rope_kernel(float* __restrict__ proj, const int* __restrict__ positions)
{
    int idx = blockIdx.x * blockDim.x + threadIdx.x;
    int i = idx & 63;
    int h = (idx >> 6) & 31;
    int t = idx >> 11;

    int pos = positions[t];
    float inv = exp2f(-(float)i * (13.287712379549449f / 64.0f));
    float freq = (float)pos * inv;
    float sn, cs;
    sincosf(freq, &sn, &cs);

    size_t qb = (size_t)t * PROJ3 + (size_t)h * HD + i;
    {
        float x1 = proj[qb], x2 = proj[qb + 64];
        proj[qb]      = x1 * cs - x2 * sn;
        proj[qb + 64] = x2 * cs + x1 * sn;
    }
    {
        size_t kb = qb + HID;
        float x1 = proj[kb], x2 = proj[kb + 64];
        proj[kb]      = x1 * cs - x2 * sn;
        proj[kb + 64] = x2 * cs + x1 * sn;
    }
}

// ---------------------------------------------------------------------------
// Flash-attention style causal attention (fp32) — unchanged (passing, ~1.7ms).
// ---------------------------------------------------------------------------
#define FL_SMEM_FLOATS (128*68 + 128*68 + 64*132 + 64*65)

__global__ __launch_bounds__(256, 1)
void flash_attn(const float* __restrict__ proj, float* __restrict__ attn)
{
    extern __shared__ float sm[];
    float* qt = sm;
    float* kt = sm + 128 * 68;
    float* vs = sm + 2 * 128 * 68;
    float* ps = sm + 2 * 128 * 68 + 64 * 132;

    const int tid = threadIdx.x;
    const int tx = tid & 15;
    const int ty = tid >> 4;
    const int r0 = ty * 4;
    const int c0 = tx * 4;
    const int ox0 = tx * 8;

    const int qb = blockIdx.x;
    const int bh = blockIdx.y;
    const int b = bh >> 5;
    const int h = bh & 31;
    const int tok0 = b * S_SZ + qb * 64;

    const float scale = 0.08838834764831845f;

    const float* qg = proj + (size_t)tok0 * PROJ3 + (size_t)h * HD;
#pragma unroll
    for (int j = 0; j < 8; j++) {
        int f = tid + j * 256;
        int row = f >> 5;
        int d0 = (f & 31) * 4;
        float4 v = *(const float4*)(qg + (size_t)row * PROJ3 + d0);
        qt[(d0 + 0) * 68 + row] = v.x * scale;
        qt[(d0 + 1) * 68 + row] = v.y * scale;
        qt[(d0 + 2) * 68 + row] = v.z * scale;
        qt[(d0 + 3) * 68 + row] = v.w * scale;
    }

    float acc[4][8];
    float m_old[4], l_run[4];
#pragma unroll
    for (int ri = 0; ri < 4; ri++) {
        m_old[ri] = -1e30f;
        l_run[ri] = 0.f;
#pragma unroll
        for (int c = 0; c < 8; c++) acc[ri][c] = 0.f;
    }

    for (int kb = 0; kb <= qb; kb++) {
        __syncthreads();

        const float* kg = proj + (size_t)(b * S_SZ + kb * 64) * PROJ3 + HID + (size_t)h * HD;
        const float* vg = kg + HID;
#pragma unroll
        for (int j = 0; j < 8; j++) {
            int f = tid + j * 256;
            int row = f >> 5;
            int d0 = (f & 31) * 4;
            float4 kv = *(const float4*)(kg + (size_t)row * PROJ3 + d0);
            kt[(d0 + 0) * 68 + row] = kv.x;
            kt[(d0 + 1) * 68 + row] = kv.y;
            kt[(d0 + 2) * 68 + row] = kv.z;
            kt[(d0 + 3) * 68 + row] = kv.w;
            float4 vv = *(const float4*)(vg + (size_t)row * PROJ3 + d0);
            *(float4*)&vs[row * 132 + d0] = vv;
        }
        __syncthreads();

        float s[4][4];
#pragma unroll
        for (int ri = 0; ri < 4; ri++)
#pragma unroll
            for (int ci = 0; ci < 4; ci++) s[ri][ci] = 0.f;

#pragma unroll 4
        for (int d = 0; d < 128; d++) {
            float4 a = *(const float4*)&qt[d * 68 + r0];
            float4 bb = *(const float4*)&kt[d * 68 + c0];
            s[0][0] = fmaf(a.x, bb.x, s[0][0]); s[0][1] = fmaf(a.x, bb.y, s[0][1]);
            s[0][2] = fmaf(a.x, bb.z, s[0][2]); s[0][3] = fmaf(a.x, bb.w, s[0][3]);
            s[1][0] = fmaf(a.y, bb.x, s[1][0]); s[1][1] = fmaf(a.y, bb.y, s[1][1]);
            s[1][2] = fmaf(a.y, bb.z, s[1][2]); s[1][3] = fmaf(a.y, bb.w, s[1][3]);
            s[2][0] = fmaf(a.z, bb.x, s[2][0]); s[2][1] = fmaf(a.z, bb.y, s[2][1]);
            s[2][2] = fmaf(a.z, bb.z, s[2][2]); s[2][3] = fmaf(a.z, bb.w, s[2][3]);
            s[3][0] = fmaf(a.w, bb.x, s[3][0]); s[3][1] = fmaf(a.w, bb.y, s[3][1]);
            s[3][2] = fmaf(a.w, bb.z, s[3][2]); s[3][3] = fmaf(a.w, bb.w, s[3][3]);
        }

        if (kb == qb) {
#pragma unroll
            for (int ri = 0; ri < 4; ri++)
#pragma unroll
                for (int ci = 0; ci < 4; ci++)
                    if (c0 + ci > r0 + ri) s[ri][ci] = -1e30f;
        }

        float m_new[4], alpha[4], psum[4];
#pragma unroll
        for (int ri = 0; ri < 4; ri++) {
            float mx = fmaxf(fmaxf(s[ri][0], s[ri][1]), fmaxf(s[ri][2], s[ri][3]));
            mx = fmaxf(mx, __shfl_xor_sync(0xffffffffu, mx, 1));
            mx = fmaxf(mx, __shfl_xor_sync(0xffffffffu, mx, 2));
            mx = fmaxf(mx, __shfl_xor_sync(0xffffffffu, mx, 4));
            mx = fmaxf(mx, __shfl_xor_sync(0xffffffffu, mx, 8));
            m_new[ri] = fmaxf(m_old[ri], mx);
            alpha[ri] = __expf(m_old[ri] - m_new[ri]);

            float rs = 0.f;
#pragma unroll
            for (int ci = 0; ci < 4; ci++) {
                float p = __expf(s[ri][ci] - m_new[ri]);
                s[ri][ci] = p;
                rs += p;
            }
            rs += __shfl_xor_sync(0xffffffffu, rs, 1);
            rs += __shfl_xor_sync(0xffffffffu, rs, 2);
            rs += __shfl_xor_sync(0xffffffffu, rs, 4);
            rs += __shfl_xor_sync(0xffffffffu, rs, 8);
            psum[ri] = rs;
        }

#pragma unroll
        for (int ri = 0; ri < 4; ri++) {
            ps[(r0 + ri) * 65 + c0 + 0] = s[ri][0];
            ps[(r0 + ri) * 65 + c0 + 1] = s[ri][1];
            ps[(r0 + ri) * 65 + c0 + 2] = s[ri][2];
            ps[(r0 + ri) * 65 + c0 + 3] = s[ri][3];
            float a = alpha[ri];
#pragma unroll
            for (int c = 0; c < 8; c++) acc[ri][c] *= a;
            l_run[ri] = l_run[ri] * a + psum[ri];
            m_old[ri] = m_new[ri];
        }
        __syncthreads();

#pragma unroll 2
        for (int kk = 0; kk < 64; kk++) {
            float p0 = ps[(r0 + 0) * 65 + kk];
            float p1 = ps[(r0 + 1) * 65 + kk];
            float p2 = ps[(r0 + 2) * 65 + kk];
            float p3 = ps[(r0 + 3) * 65 + kk];
            float4 v0 = *(const float4*)&vs[kk * 132 + ox0];
            float4 v1 = *(const float4*)&vs[kk * 132 + ox0 + 4];
            acc[0][0]=fmaf(p0,v0.x,acc[0][0]); acc[0][1]=fmaf(p0,v0.y,acc[0][1]);
            acc[0][2]=fmaf(p0,v0.z,acc[0][2]); acc[0][3]=fmaf(p0,v0.w,acc[0][3]);
            acc[0][4]=fmaf(p0,v1.x,acc[0][4]); acc[0][5]=fmaf(p0,v1.y,acc[0][5]);
            acc[0][6]=fmaf(p0,v1.z,acc[0][6]); acc[0][7]=fmaf(p0,v1.w,acc[0][7]);
            acc[1][0]=fmaf(p1,v0.x,acc[1][0]); acc[1][1]=fmaf(p1,v0.y,acc[1][1]);
            acc[1][2]=fmaf(p1,v0.z,acc[1][2]); acc[1][3]=fmaf(p1,v0.w,acc[1][3]);
            acc[1][4]=fmaf(p1,v1.x,acc[1][4]); acc[1][5]=fmaf(p1,v1.y,acc[1][5]);
            acc[1][6]=fmaf(p1,v1.z,acc[1][6]); acc[1][7]=fmaf(p1,v1.w,acc[1][7]);
            acc[2][0]=fmaf(p2,v0.x,acc[2][0]); acc[2][1]=fmaf(p2,v0.y,acc[2][1]);
            acc[2][2]=fmaf(p2,v0.z,acc[2][2]); acc[2][3]=fmaf(p2,v0.w,acc[2][3]);
            acc[2][4]=fmaf(p2,v1.x,acc[2][4]); acc[2][5]=fmaf(p2,v1.y,acc[2][5]);
            acc[2][6]=fmaf(p2,v1.z,acc[2][6]); acc[2][7]=fmaf(p2,v1.w,acc[2][7]);
            acc[3][0]=fmaf(p3,v0.x,acc[3][0]); acc[3][1]=fmaf(p3,v0.y,acc[3][1]);
            acc[3][2]=fmaf(p3,v0.z,acc[3][2]); acc[3][3]=fmaf(p3,v0.w,acc[3][3]);
            acc[3][4]=fmaf(p3,v1.x,acc[3][4]); acc[3][5]=fmaf(p3,v1.y,acc[3][5]);
            acc[3][6]=fmaf(p3,v1.z,acc[3][6]); acc[3][7]=fmaf(p3,v1.w,acc[3][7]);
        }
    }

#pragma unroll
    for (int ri = 0; ri < 4; ri++) {
        float inv_l = 1.f / l_run[ri];
        float* orow = attn + (size_t)(tok0 + r0 + ri) * HID + (size_t)h * HD + ox0;
        float4 o0 = {acc[ri][0] * inv_l, acc[ri][1] * inv_l, acc[ri][2] * inv_l, acc[ri][3] * inv_l};
        float4 o1 = {acc[ri][4] * inv_l, acc[ri][5] * inv_l, acc[ri][6] * inv_l, acc[ri][7] * inv_l};
        *(float4*)orow = o0;
        *(float4*)(orow + 4) = o1;
    }
}

// ---------------------------------------------------------------------------
// Launch
// ---------------------------------------------------------------------------
extern "C" void kernel_launch(void* const* d_in, const int* in_sizes, int n_in,
                              void* d_out, int out_size)
{
    const float* hidden = (const float*)d_in[0];
    const int* positions = (const int*)d_in[1];
    const float* W_pack = (const float*)d_in[2];
    const float* W_o = (const float*)d_in[3];
    float* out = (float*)d_out;

    void* pp; cudaGetSymbolAddress(&pp, g_proj);
    void* ap; cudaGetSymbolAddress(&ap, g_attn);
    float* proj = (float*)pp;
    float* attn = (float*)ap;

    void* v_ah; cudaGetSymbolAddress(&v_ah, g_Ah);
    void* v_al; cudaGetSymbolAddress(&v_al, g_Al);
    void* v_wph; cudaGetSymbolAddress(&v_wph, g_Wph);
    void* v_wpl; cudaGetSymbolAddress(&v_wpl, g_Wpl);
    void* v_woh; cudaGetSymbolAddress(&v_woh, g_Woh);
    void* v_wol; cudaGetSymbolAddress(&v_wol, g_Wol);
    void* v_xh; cudaGetSymbolAddress(&v_xh, g_Xh);
    void* v_xl; cudaGetSymbolAddress(&v_xl, g_Xl);

    cudaFuncSetAttribute(gemm_bf16x3, cudaFuncAttributeMaxDynamicSharedMemorySize, GEMM_SMEM);
    cudaFuncSetAttribute(flash_attn, cudaFuncAttributeMaxDynamicSharedMemorySize,
                         FL_SMEM_FLOATS * sizeof(float));

    // 0) fp32 -> bf16 hi/lo splits for GEMM inputs
    {
        int n8 = TOK * HID / 8;
        split_bf16<<<(n8 + 255) / 256, 256>>>(hidden, (__nv_bfloat16*)v_ah, (__nv_bfloat16*)v_al, n8);
        int w8 = PROJ3 * HID / 8;
        split_bf16<<<(w8 + 255) / 256, 256>>>(W_pack, (__nv_bfloat16*)v_wph, (__nv_bfloat16*)v_wpl, w8);
        int o8 = HID * HID / 8;
        split_bf16<<<(o8 + 255) / 256, 256>>>(W_o, (__nv_bfloat16*)v_woh, (__nv_bfloat16*)v_wol, o8);
    }

    // 1) QKV projection: proj = hidden @ W_pack^T  [4096 x 12288]
    {
        dim3 grid(PROJ3 / BN, TOK / BM);  // 96 x 32
        gemm_bf16x3<<<grid, 256, GEMM_SMEM>>>((const __nv_bfloat16*)v_ah, (const __nv_bfloat16*)v_al,
                                              (const __nv_bfloat16*)v_wph, (const __nv_bfloat16*)v_wpl,
                                              proj, PROJ3, HID);
    }

    // 2) RoPE on q,k
    {
        int total = TOK * NH * 64;
        rope_kernel<<<total / 256, 256>>>(proj, positions);
    }

    // 3) Causal attention (fp32)
    {
        dim3 grid(S_SZ / 64, B_SZ * NH);
        flash_attn<<<grid, 256, FL_SMEM_FLOATS * sizeof(float)>>>(proj, attn);
    }

    // 4) split attention output, then out = attn @ W_o^T
    {
        int n8 = TOK * HID / 8;
        split_bf16<<<(n8 + 255) / 256, 256>>>(attn, (__nv_bfloat16*)v_xh, (__nv_bfloat16*)v_xl, n8);
        dim3 grid(HID / BN, TOK / BM);  // 32 x 32
        gemm_bf16x3<<<grid, 256, GEMM_SMEM>>>((const __nv_bfloat16*)v_xh, (const __nv_bfloat16*)v_xl,
                                              (const __nv_bfloat16*)v_woh, (const __nv_bfloat16*)v_wol,
                                              out, HID, HID);
    }
}

// round 4
// speedup vs baseline: 2.4921x; 1.3011x over previous
#include <cuda_runtime.h>
#include <cuda_fp16.h>
#include <cuda_bf16.h>
#include <math.h>
#include <stdint.h>

// Problem constants
#define B_SZ 2
#define S_SZ 2048
#define HID 4096
#define NH 32
#define HD 128
#define TOK (B_SZ * S_SZ)          // 4096 tokens
#define PROJ3 (3 * HID)            // 12288

// Scratch (static device globals — allocation-free rule)
__device__ float g_proj[(size_t)TOK * PROJ3];   // [4096, 12288] q|k|v (fp32)
__device__ float g_attn[(size_t)TOK * HID];     // [4096, 4096] attention output (fp32)
// fp16 operands: activations split hi/lo (exact), weights rounded once
__device__ __half g_Ah[(size_t)TOK * HID];
__device__ __half g_Al[(size_t)TOK * HID];
__device__ __half g_Wp[(size_t)PROJ3 * HID];
__device__ __half g_Wo[(size_t)HID * HID];
__device__ __half g_Xh[(size_t)TOK * HID];
__device__ __half g_Xl[(size_t)TOK * HID];

// ---------------------------------------------------------------------------
// Inline PTX helpers (arch-portable: cp.async + ldmatrix + mma.sync only)
// ---------------------------------------------------------------------------
__device__ __forceinline__ uint32_t smem_u32(const void* p) {
    uint32_t a;
    asm("{ .reg .u64 t; cvta.to.shared.u64 t, %1; cvt.u32.u64 %0, t; }" : "=r"(a) : "l"(p));
    return a;
}
__device__ __forceinline__ void cp16(uint32_t dst, const void* src) {
    asm volatile("cp.async.cg.shared.global [%0], [%1], 16;" :: "r"(dst), "l"(src) : "memory");
}
__device__ __forceinline__ void cp_commit() { asm volatile("cp.async.commit_group;" ::: "memory"); }
template <int N>
__device__ __forceinline__ void cp_wait() {
    asm volatile("cp.async.wait_group %0;" :: "n"(N) : "memory");
}
__device__ __forceinline__ void ldsm4(uint32_t r[4], uint32_t addr) {
    asm volatile("ldmatrix.sync.aligned.m8n8.x4.shared.b16 {%0,%1,%2,%3}, [%4];"
                 : "=r"(r[0]), "=r"(r[1]), "=r"(r[2]), "=r"(r[3]) : "r"(addr));
}
__device__ __forceinline__ void mma16816(float c[4], const uint32_t a[4], const uint32_t b[2]) {
    asm volatile(
        "mma.sync.aligned.m16n8k16.row.col.f32.f16.f16.f32 "
        "{%0,%1,%2,%3}, {%4,%5,%6,%7}, {%8,%9}, {%0,%1,%2,%3};"
        : "+f"(c[0]), "+f"(c[1]), "+f"(c[2]), "+f"(c[3])
        : "r"(a[0]), "r"(a[1]), "r"(a[2]), "r"(a[3]), "r"(b[0]), "r"(b[1]));
}

// ---------------------------------------------------------------------------
// fp32 -> fp16 hi/lo split (exact to ~2^-24). 8 elements/thread.
// ---------------------------------------------------------------------------
__global__ void split_f16(const float* __restrict__ x, __half* __restrict__ hi,
                          __half* __restrict__ lo, int n8)
{
    int i = blockIdx.x * blockDim.x + threadIdx.x;
    if (i >= n8) return;
    const float4* xp = (const float4*)x + (size_t)i * 2;
    float4 a = xp[0], b = xp[1];
    float v[8] = {a.x, a.y, a.z, a.w, b.x, b.y, b.z, b.w};
    __half h[8], l[8];
#pragma unroll
    for (int j = 0; j < 8; j++) {
        h[j] = __float2half_rn(v[j]);
        l[j] = __float2half_rn(v[j] - __half2float(h[j]));
    }
    *((uint4*)hi + i) = *(const uint4*)h;
    *((uint4*)lo + i) = *(const uint4*)l;
}

// fp32 -> fp16 round (weights). 8 elements/thread.
__global__ void conv_f16(const float* __restrict__ x, __half* __restrict__ y, int n8)
{
    int i = blockIdx.x * blockDim.x + threadIdx.x;
    if (i >= n8) return;
    const float4* xp = (const float4*)x + (size_t)i * 2;
    float4 a = xp[0], b = xp[1];
    float v[8] = {a.x, a.y, a.z, a.w, b.x, b.y, b.z, b.w};
    __half h[8];
#pragma unroll
    for (int j = 0; j < 8; j++) h[j] = __float2half_rn(v[j]);
    *((uint4*)y + i) = *(const uint4*)h;
}

// ---------------------------------------------------------------------------
// HMMA fp16x2 GEMM: C[M,N] = (Ah+Al)[M,K] @ B[N,K]^T  (B pre-rounded fp16)
// CTA tile 128x256, BK=32, 4-stage cp.async pipeline, 256 thr (8 warps 2x4),
// warp tile 64x64 via mma.sync m16n8k16, 2 accumulation terms.
// ---------------------------------------------------------------------------
#define BM 128
#define BN 256
#define BK 32
#define STAGES 4
#define PADK 40                         // halves per smem row (32 + 8 pad)
#define TILEA (128 * PADK * 2)          // 10240 B
#define TILEB_ (256 * PADK * 2)         // 20480 B
#define STAGEB (2 * TILEA + TILEB_)     // 40960 B
#define GEMM_SMEM (STAGES * STAGEB)     // 163840 B

__global__ __launch_bounds__(256, 1)
void gemm_f16x2(const __half* __restrict__ Ah, const __half* __restrict__ Al,
                const __half* __restrict__ Bh, float* __restrict__ C, int N, int K)
{
    extern __shared__ char smraw[];
    const uint32_t sbase = smem_u32(smraw);

    const int tid = threadIdx.x;
    const int wid = tid >> 5;
    const int lane = tid & 31;
    const int wm = wid >> 2;          // 0..1  (64 rows)
    const int wn = wid & 3;           // 0..3  (64 cols)
    const int m0 = blockIdx.y * BM;
    const int n0 = blockIdx.x * BN;
    const int NCH = K >> 5;

    auto load_chunk = [&](int c, int stg) {
        const uint32_t sb = sbase + stg * STAGEB;
        const int kc = c * BK;
#pragma unroll
        for (int i = 0; i < 2; i++) {
            int op = tid + i * 256;       // 0..511
            int row = op >> 2;
            int ck = op & 3;
            uint32_t soff = (uint32_t)(row * PADK * 2 + ck * 16);
            size_t goff = (size_t)(m0 + row) * K + kc + ck * 8;
            cp16(sb + soff, Ah + goff);
            cp16(sb + TILEA + soff, Al + goff);
        }
#pragma unroll
        for (int i = 0; i < 4; i++) {
            int op = tid + i * 256;       // 0..1023
            int row = op >> 2;
            int ck = op & 3;
            uint32_t soff = (uint32_t)(row * PADK * 2 + ck * 16);
            cp16(sb + 2 * TILEA + soff, Bh + (size_t)(n0 + row) * K + kc + ck * 8);
        }
        cp_commit();
    };

    float c[4][8][4];
#pragma unroll
    for (int i = 0; i < 4; i++)
#pragma unroll
        for (int j = 0; j < 8; j++)
#pragma unroll
            for (int q = 0; q < 4; q++) c[i][j][q] = 0.f;

    // prologue: 3 chunks in flight
    load_chunk(0, 0);
    load_chunk(1, 1);
    load_chunk(2, 2);

    const int a_row = (lane & 15);
    const int a_col = ((lane >> 4) & 1) * 8;
    const int b_row = (lane & 7) + ((lane & 16) ? 8 : 0);
    const int b_col = ((lane & 8) ? 8 : 0);

    for (int cch = 0; cch < NCH; cch++) {
        cp_wait<2>();
        __syncthreads();   // chunk cch resident; all warps finished chunk cch-1

        if (cch + 3 < NCH) load_chunk(cch + 3, (cch + 3) & 3);
        else cp_commit();

        const uint32_t sb = sbase + (cch & 3) * STAGEB;
        const uint32_t sAh = sb;
        const uint32_t sAl = sb + TILEA;
        const uint32_t sB = sb + 2 * TILEA;

#pragma unroll
        for (int s = 0; s < 2; s++) {
            uint32_t ah[16], al[16], bh[16];
#pragma unroll
            for (int i = 0; i < 4; i++) {
                int row = wm * 64 + i * 16 + a_row;
                uint32_t off = (uint32_t)((row * PADK + s * 16 + a_col) * 2);
                ldsm4(&ah[i * 4], sAh + off);
                ldsm4(&al[i * 4], sAl + off);
            }
#pragma unroll
            for (int j2 = 0; j2 < 4; j2++) {
                int row = wn * 64 + j2 * 16 + b_row;
                uint32_t off = (uint32_t)((row * PADK + s * 16 + b_col) * 2);
                ldsm4(&bh[j2 * 4], sB + off);
            }
#pragma unroll
            for (int i = 0; i < 4; i++)
#pragma unroll
                for (int j = 0; j < 8; j++)
                    mma16816(c[i][j], &ah[i * 4], &bh[j * 2]);
#pragma unroll
            for (int i = 0; i < 4; i++)
#pragma unroll
                for (int j = 0; j < 8; j++)
                    mma16816(c[i][j], &al[i * 4], &bh[j * 2]);
        }
    }

    // epilogue
    const int g = lane >> 2;
    const int tq = lane & 3;
#pragma unroll
    for (int i = 0; i < 4; i++) {
        int row0 = m0 + wm * 64 + i * 16 + g;
#pragma unroll
        for (int j = 0; j < 8; j++) {
            int col = n0 + wn * 64 + j * 8 + tq * 2;
            float2 v0 = {c[i][j][0], c[i][j][1]};
            float2 v1 = {c[i][j][2], c[i][j][3]};
            *(float2*)&C[(size_t)row0 * N + col] = v0;
            *(float2*)&C[(size_t)(row0 + 8) * N + col] = v1;
        }
    }
}

// ---------------------------------------------------------------------------
// RoPE (GPT-NeoX half-split) applied in-place to q and k slices of g_proj.
// ---------------------------------------------------------------------------
__global__ void rope_kernel(float* __restrict__ proj, const int* __restrict__ positions)
{
    int idx = blockIdx.x * blockDim.x + threadIdx.x;
    int i = idx & 63;
    int h = (idx >> 6) & 31;
    int t = idx >> 11;

    int pos = positions[t];
    float inv = exp2f(-(float)i * (13.287712379549449f / 64.0f));
    float freq = (float)pos * inv;
    float sn, cs;
    sincosf(freq, &sn, &cs);

    size_t qb = (size_t)t * PROJ3 + (size_t)h * HD + i;
    {
        float x1 = proj[qb], x2 = proj[qb + 64];
        proj[qb]      = x1 * cs - x2 * sn;
        proj[qb + 64] = x2 * cs + x1 * sn;
    }
    {
        size_t kb = qb + HID;
        float x1 = proj[kb], x2 = proj[kb + 64];
        proj[kb]      = x1 * cs - x2 * sn;
        proj[kb + 64] = x2 * cs + x1 * sn;
    }
}

// ---------------------------------------------------------------------------
// Flash-attention style causal attention (fp32) — unchanged (passing).
// ---------------------------------------------------------------------------
#define FL_SMEM_FLOATS (128*68 + 128*68 + 64*132 + 64*65)

__global__ __launch_bounds__(256, 1)
void flash_attn(const float* __restrict__ proj, float* __restrict__ attn)
{
    extern __shared__ float sm[];
    float* qt = sm;
    float* kt = sm + 128 * 68;
    float* vs = sm + 2 * 128 * 68;
    float* ps = sm + 2 * 128 * 68 + 64 * 132;

    const int tid = threadIdx.x;
    const int tx = tid & 15;
    const int ty = tid >> 4;
    const int r0 = ty * 4;
    const int c0 = tx * 4;
    const int ox0 = tx * 8;

    const int qb = blockIdx.x;
    const int bh = blockIdx.y;
    const int b = bh >> 5;
    const int h = bh & 31;
    const int tok0 = b * S_SZ + qb * 64;

    const float scale = 0.08838834764831845f;

    const float* qg = proj + (size_t)tok0 * PROJ3 + (size_t)h * HD;
#pragma unroll
    for (int j = 0; j < 8; j++) {
        int f = tid + j * 256;
        int row = f >> 5;
        int d0 = (f & 31) * 4;
        float4 v = *(const float4*)(qg + (size_t)row * PROJ3 + d0);
        qt[(d0 + 0) * 68 + row] = v.x * scale;
        qt[(d0 + 1) * 68 + row] = v.y * scale;
        qt[(d0 + 2) * 68 + row] = v.z * scale;
        qt[(d0 + 3) * 68 + row] = v.w * scale;
    }

    float acc[4][8];
    float m_old[4], l_run[4];
#pragma unroll
    for (int ri = 0; ri < 4; ri++) {
        m_old[ri] = -1e30f;
        l_run[ri] = 0.f;
#pragma unroll
        for (int c = 0; c < 8; c++) acc[ri][c] = 0.f;
    }

    for (int kb = 0; kb <= qb; kb++) {
        __syncthreads();

        const float* kg = proj + (size_t)(b * S_SZ + kb * 64) * PROJ3 + HID + (size_t)h * HD;
        const float* vg = kg + HID;
#pragma unroll
        for (int j = 0; j < 8; j++) {
            int f = tid + j * 256;
            int row = f >> 5;
            int d0 = (f & 31) * 4;
            float4 kv = *(const float4*)(kg + (size_t)row * PROJ3 + d0);
            kt[(d0 + 0) * 68 + row] = kv.x;
            kt[(d0 + 1) * 68 + row] = kv.y;
            kt[(d0 + 2) * 68 + row] = kv.z;
            kt[(d0 + 3) * 68 + row] = kv.w;
            float4 vv = *(const float4*)(vg + (size_t)row * PROJ3 + d0);
            *(float4*)&vs[row * 132 + d0] = vv;
        }
        __syncthreads();

        float s[4][4];
#pragma unroll
        for (int ri = 0; ri < 4; ri++)
#pragma unroll
            for (int ci = 0; ci < 4; ci++) s[ri][ci] = 0.f;

#pragma unroll 4
        for (int d = 0; d < 128; d++) {
            float4 a = *(const float4*)&qt[d * 68 + r0];
            float4 bb = *(const float4*)&kt[d * 68 + c0];
            s[0][0] = fmaf(a.x, bb.x, s[0][0]); s[0][1] = fmaf(a.x, bb.y, s[0][1]);
            s[0][2] = fmaf(a.x, bb.z, s[0][2]); s[0][3] = fmaf(a.x, bb.w, s[0][3]);
            s[1][0] = fmaf(a.y, bb.x, s[1][0]); s[1][1] = fmaf(a.y, bb.y, s[1][1]);
            s[1][2] = fmaf(a.y, bb.z, s[1][2]); s[1][3] = fmaf(a.y, bb.w, s[1][3]);
            s[2][0] = fmaf(a.z, bb.x, s[2][0]); s[2][1] = fmaf(a.z, bb.y, s[2][1]);
            s[2][2] = fmaf(a.z, bb.z, s[2][2]); s[2][3] = fmaf(a.z, bb.w, s[2][3]);
            s[3][0] = fmaf(a.w, bb.x, s[3][0]); s[3][1] = fmaf(a.w, bb.y, s[3][1]);
            s[3][2] = fmaf(a.w, bb.z, s[3][2]); s[3][3] = fmaf(a.w, bb.w, s[3][3]);
        }

        if (kb == qb) {
#pragma unroll
            for (int ri = 0; ri < 4; ri++)
#pragma unroll
                for (int ci = 0; ci < 4; ci++)
                    if (c0 + ci > r0 + ri) s[ri][ci] = -1e30f;
        }

        float m_new[4], alpha[4], psum[4];
#pragma unroll
        for (int ri = 0; ri < 4; ri++) {
            float mx = fmaxf(fmaxf(s[ri][0], s[ri][1]), fmaxf(s[ri][2], s[ri][3]));
            mx = fmaxf(mx, __shfl_xor_sync(0xffffffffu, mx, 1));
            mx = fmaxf(mx, __shfl_xor_sync(0xffffffffu, mx, 2));
            mx = fmaxf(mx, __shfl_xor_sync(0xffffffffu, mx, 4));
            mx = fmaxf(mx, __shfl_xor_sync(0xffffffffu, mx, 8));
            m_new[ri] = fmaxf(m_old[ri], mx);
            alpha[ri] = __expf(m_old[ri] - m_new[ri]);

            float rs = 0.f;
#pragma unroll
            for (int ci = 0; ci < 4; ci++) {
                float p = __expf(s[ri][ci] - m_new[ri]);
                s[ri][ci] = p;
                rs += p;
            }
            rs += __shfl_xor_sync(0xffffffffu, rs, 1);
            rs += __shfl_xor_sync(0xffffffffu, rs, 2);
            rs += __shfl_xor_sync(0xffffffffu, rs, 4);
            rs += __shfl_xor_sync(0xffffffffu, rs, 8);
            psum[ri] = rs;
        }

#pragma unroll
        for (int ri = 0; ri < 4; ri++) {
            ps[(r0 + ri) * 65 + c0 + 0] = s[ri][0];
            ps[(r0 + ri) * 65 + c0 + 1] = s[ri][1];
            ps[(r0 + ri) * 65 + c0 + 2] = s[ri][2];
            ps[(r0 + ri) * 65 + c0 + 3] = s[ri][3];
            float a = alpha[ri];
#pragma unroll
            for (int c = 0; c < 8; c++) acc[ri][c] *= a;
            l_run[ri] = l_run[ri] * a + psum[ri];
            m_old[ri] = m_new[ri];
        }
        __syncthreads();

#pragma unroll 2
        for (int kk = 0; kk < 64; kk++) {
            float p0 = ps[(r0 + 0) * 65 + kk];
            float p1 = ps[(r0 + 1) * 65 + kk];
            float p2 = ps[(r0 + 2) * 65 + kk];
            float p3 = ps[(r0 + 3) * 65 + kk];
            float4 v0 = *(const float4*)&vs[kk * 132 + ox0];
            float4 v1 = *(const float4*)&vs[kk * 132 + ox0 + 4];
            acc[0][0]=fmaf(p0,v0.x,acc[0][0]); acc[0][1]=fmaf(p0,v0.y,acc[0][1]);
            acc[0][2]=fmaf(p0,v0.z,acc[0][2]); acc[0][3]=fmaf(p0,v0.w,acc[0][3]);
            acc[0][4]=fmaf(p0,v1.x,acc[0][4]); acc[0][5]=fmaf(p0,v1.y,acc[0][5]);
            acc[0][6]=fmaf(p0,v1.z,acc[0][6]); acc[0][7]=fmaf(p0,v1.w,acc[0][7]);
            acc[1][0]=fmaf(p1,v0.x,acc[1][0]); acc[1][1]=fmaf(p1,v0.y,acc[1][1]);
            acc[1][2]=fmaf(p1,v0.z,acc[1][2]); acc[1][3]=fmaf(p1,v0.w,acc[1][3]);
            acc[1][4]=fmaf(p1,v1.x,acc[1][4]); acc[1][5]=fmaf(p1,v1.y,acc[1][5]);
            acc[1][6]=fmaf(p1,v1.z,acc[1][6]); acc[1][7]=fmaf(p1,v1.w,acc[1][7]);
            acc[2][0]=fmaf(p2,v0.x,acc[2][0]); acc[2][1]=fmaf(p2,v0.y,acc[2][1]);
            acc[2][2]=fmaf(p2,v0.z,acc[2][2]); acc[2][3]=fmaf(p2,v0.w,acc[2][3]);
            acc[2][4]=fmaf(p2,v1.x,acc[2][4]); acc[2][5]=fmaf(p2,v1.y,acc[2][5]);
            acc[2][6]=fmaf(p2,v1.z,acc[2][6]); acc[2][7]=fmaf(p2,v1.w,acc[2][7]);
            acc[3][0]=fmaf(p3,v0.x,acc[3][0]); acc[3][1]=fmaf(p3,v0.y,acc[3][1]);
            acc[3][2]=fmaf(p3,v0.z,acc[3][2]); acc[3][3]=fmaf(p3,v0.w,acc[3][3]);
            acc[3][4]=fmaf(p3,v1.x,acc[3][4]); acc[3][5]=fmaf(p3,v1.y,acc[3][5]);
            acc[3][6]=fmaf(p3,v1.z,acc[3][6]); acc[3][7]=fmaf(p3,v1.w,acc[3][7]);
        }
    }

#pragma unroll
    for (int ri = 0; ri < 4; ri++) {
        float inv_l = 1.f / l_run[ri];
        float* orow = attn + (size_t)(tok0 + r0 + ri) * HID + (size_t)h * HD + ox0;
        float4 o0 = {acc[ri][0] * inv_l, acc[ri][1] * inv_l, acc[ri][2] * inv_l, acc[ri][3] * inv_l};
        float4 o1 = {acc[ri][4] * inv_l, acc[ri][5] * inv_l, acc[ri][6] * inv_l, acc[ri][7] * inv_l};
        *(float4*)orow = o0;
        *(float4*)(orow + 4) = o1;
    }
}

// ---------------------------------------------------------------------------
// Launch
// ---------------------------------------------------------------------------
extern "C" void kernel_launch(void* const* d_in, const int* in_sizes, int n_in,
                              void* d_out, int out_size)
{
    const float* hidden = (const float*)d_in[0];
    const int* positions = (const int*)d_in[1];
    const float* W_pack = (const float*)d_in[2];
    const float* W_o = (const float*)d_in[3];
    float* out = (float*)d_out;

    void* pp; cudaGetSymbolAddress(&pp, g_proj);
    void* ap; cudaGetSymbolAddress(&ap, g_attn);
    float* proj = (float*)pp;
    float* attn = (float*)ap;

    void* v_ah; cudaGetSymbolAddress(&v_ah, g_Ah);
    void* v_al; cudaGetSymbolAddress(&v_al, g_Al);
    void* v_wp; cudaGetSymbolAddress(&v_wp, g_Wp);
    void* v_wo; cudaGetSymbolAddress(&v_wo, g_Wo);
    void* v_xh; cudaGetSymbolAddress(&v_xh, g_Xh);
    void* v_xl; cudaGetSymbolAddress(&v_xl, g_Xl);

    cudaFuncSetAttribute(gemm_f16x2, cudaFuncAttributeMaxDynamicSharedMemorySize, GEMM_SMEM);
    cudaFuncSetAttribute(flash_attn, cudaFuncAttributeMaxDynamicSharedMemorySize,
                         FL_SMEM_FLOATS * sizeof(float));

    // 0) operand prep: activations hi/lo split (exact), weights rounded to fp16
    {
        int n8 = TOK * HID / 8;
        split_f16<<<(n8 + 255) / 256, 256>>>(hidden, (__half*)v_ah, (__half*)v_al, n8);
        int w8 = PROJ3 * HID / 8;
        conv_f16<<<(w8 + 255) / 256, 256>>>(W_pack, (__half*)v_wp, w8);
        int o8 = HID * HID / 8;
        conv_f16<<<(o8 + 255) / 256, 256>>>(W_o, (__half*)v_wo, o8);
    }

    // 1) QKV projection: proj = hidden @ W_pack^T  [4096 x 12288]
    {
        dim3 grid(PROJ3 / BN, TOK / BM);  // 48 x 32
        gemm_f16x2<<<grid, 256, GEMM_SMEM>>>((const __half*)v_ah, (const __half*)v_al,
                                             (const __half*)v_wp, proj, PROJ3, HID);
    }

    // 2) RoPE on q,k
    {
        int total = TOK * NH * 64;
        rope_kernel<<<total / 256, 256>>>(proj, positions);
    }

    // 3) Causal attention (fp32)
    {
        dim3 grid(S_SZ / 64, B_SZ * NH);
        flash_attn<<<grid, 256, FL_SMEM_FLOATS * sizeof(float)>>>(proj, attn);
    }

    // 4) split attention output, then out = attn @ W_o^T
    {
        int n8 = TOK * HID / 8;
        split_f16<<<(n8 + 255) / 256, 256>>>(attn, (__half*)v_xh, (__half*)v_xl, n8);
        dim3 grid(HID / BN, TOK / BM);  // 16 x 32
        gemm_f16x2<<<grid, 256, GEMM_SMEM>>>((const __half*)v_xh, (const __half*)v_xl,
                                             (const __half*)v_wo, out, HID, HID);
    }
}

// round 5
// speedup vs baseline: 4.1783x; 1.6766x over previous
#include <cuda_runtime.h>
#include <cuda_fp16.h>
#include <math.h>
#include <stdint.h>

// Problem constants
#define B_SZ 2
#define S_SZ 2048
#define HID 4096
#define NH 32
#define HD 128
#define TOK (B_SZ * S_SZ)          // 4096 tokens
#define PROJ3 (3 * HID)            // 12288

// Scratch (static device globals — allocation-free rule)
__device__ float g_proj[(size_t)TOK * PROJ3];   // [4096, 12288] q|k|v (fp32)
// fp16 operands for GEMMs
__device__ __half g_Ah[(size_t)TOK * HID];
__device__ __half g_Al[(size_t)TOK * HID];
__device__ __half g_Wp[(size_t)PROJ3 * HID];
__device__ __half g_Wo[(size_t)HID * HID];
__device__ __half g_Xh[(size_t)TOK * HID];
__device__ __half g_Xl[(size_t)TOK * HID];
// head-major fp16 attention operands [b*NH+h][s][d]
__device__ __half g_Qh[(size_t)TOK * HID];
__device__ __half g_Ql[(size_t)TOK * HID];
__device__ __half g_Kh[(size_t)TOK * HID];
__device__ __half g_Vh[(size_t)TOK * HID];
__device__ __half g_Vl[(size_t)TOK * HID];

// ---------------------------------------------------------------------------
// Inline PTX helpers
// ---------------------------------------------------------------------------
__device__ __forceinline__ uint32_t smem_u32(const void* p) {
    uint32_t a;
    asm("{ .reg .u64 t; cvta.to.shared.u64 t, %1; cvt.u32.u64 %0, t; }" : "=r"(a) : "l"(p));
    return a;
}
__device__ __forceinline__ void cp16(uint32_t dst, const void* src) {
    asm volatile("cp.async.cg.shared.global [%0], [%1], 16;" :: "r"(dst), "l"(src) : "memory");
}
__device__ __forceinline__ void cp_commit() { asm volatile("cp.async.commit_group;" ::: "memory"); }
template <int N>
__device__ __forceinline__ void cp_wait() {
    asm volatile("cp.async.wait_group %0;" :: "n"(N) : "memory");
}
__device__ __forceinline__ void ldsm4(uint32_t r[4], uint32_t addr) {
    asm volatile("ldmatrix.sync.aligned.m8n8.x4.shared.b16 {%0,%1,%2,%3}, [%4];"
                 : "=r"(r[0]), "=r"(r[1]), "=r"(r[2]), "=r"(r[3]) : "r"(addr));
}
__device__ __forceinline__ void ldsm4t(uint32_t r[4], uint32_t addr) {
    asm volatile("ldmatrix.sync.aligned.m8n8.x4.trans.shared.b16 {%0,%1,%2,%3}, [%4];"
                 : "=r"(r[0]), "=r"(r[1]), "=r"(r[2]), "=r"(r[3]) : "r"(addr));
}
__device__ __forceinline__ void mma16816(float c[4], const uint32_t a[4], const uint32_t b[2]) {
    asm volatile(
        "mma.sync.aligned.m16n8k16.row.col.f32.f16.f16.f32 "
        "{%0,%1,%2,%3}, {%4,%5,%6,%7}, {%8,%9}, {%0,%1,%2,%3};"
        : "+f"(c[0]), "+f"(c[1]), "+f"(c[2]), "+f"(c[3])
        : "r"(a[0]), "r"(a[1]), "r"(a[2]), "r"(a[3]), "r"(b[0]), "r"(b[1]));
}
__device__ __forceinline__ uint32_t packh2(float a, float b) {
    __half2 h = __floats2half2_rn(a, b);
    return *(uint32_t*)&h;
}

// ---------------------------------------------------------------------------
// fp32 -> fp16 hi/lo split (exact to ~2^-24). 8 elements/thread.
// ---------------------------------------------------------------------------
__global__ void split_f16(const float* __restrict__ x, __half* __restrict__ hi,
                          __half* __restrict__ lo, int n8)
{
    int i = blockIdx.x * blockDim.x + threadIdx.x;
    if (i >= n8) return;
    const float4* xp = (const float4*)x + (size_t)i * 2;
    float4 a = xp[0], b = xp[1];
    float v[8] = {a.x, a.y, a.z, a.w, b.x, b.y, b.z, b.w};
    __half h[8], l[8];
#pragma unroll
    for (int j = 0; j < 8; j++) {
        h[j] = __float2half_rn(v[j]);
        l[j] = __float2half_rn(v[j] - __half2float(h[j]));
    }
    *((uint4*)hi + i) = *(const uint4*)h;
    *((uint4*)lo + i) = *(const uint4*)l;
}

__global__ void conv_f16(const float* __restrict__ x, __half* __restrict__ y, int n8)
{
    int i = blockIdx.x * blockDim.x + threadIdx.x;
    if (i >= n8) return;
    const float4* xp = (const float4*)x + (size_t)i * 2;
    float4 a = xp[0], b = xp[1];
    float v[8] = {a.x, a.y, a.z, a.w, b.x, b.y, b.z, b.w};
    __half h[8];
#pragma unroll
    for (int j = 0; j < 8; j++) h[j] = __float2half_rn(v[j]);
    *((uint4*)y + i) = *(const uint4*)h;
}

// ---------------------------------------------------------------------------
// HMMA fp16x2 GEMM (unchanged from R4): C = (Ah+Al) @ B^T
// ---------------------------------------------------------------------------
#define BM 128
#define BN 256
#define BK 32
#define STAGES 4
#define PADK 40
#define TILEA (128 * PADK * 2)
#define TILEB_ (256 * PADK * 2)
#define STAGEB (2 * TILEA + TILEB_)
#define GEMM_SMEM (STAGES * STAGEB)

__global__ __launch_bounds__(256, 1)
void gemm_f16x2(const __half* __restrict__ Ah, const __half* __restrict__ Al,
                const __half* __restrict__ Bh, float* __restrict__ C, int N, int K)
{
    extern __shared__ char smraw[];
    const uint32_t sbase = smem_u32(smraw);

    const int tid = threadIdx.x;
    const int wid = tid >> 5;
    const int lane = tid & 31;
    const int wm = wid >> 2;
    const int wn = wid & 3;
    const int m0 = blockIdx.y * BM;
    const int n0 = blockIdx.x * BN;
    const int NCH = K >> 5;

    auto load_chunk = [&](int c, int stg) {
        const uint32_t sb = sbase + stg * STAGEB;
        const int kc = c * BK;
#pragma unroll
        for (int i = 0; i < 2; i++) {
            int op = tid + i * 256;
            int row = op >> 2;
            int ck = op & 3;
            uint32_t soff = (uint32_t)(row * PADK * 2 + ck * 16);
            size_t goff = (size_t)(m0 + row) * K + kc + ck * 8;
            cp16(sb + soff, Ah + goff);
            cp16(sb + TILEA + soff, Al + goff);
        }
#pragma unroll
        for (int i = 0; i < 4; i++) {
            int op = tid + i * 256;
            int row = op >> 2;
            int ck = op & 3;
            uint32_t soff = (uint32_t)(row * PADK * 2 + ck * 16);
            cp16(sb + 2 * TILEA + soff, Bh + (size_t)(n0 + row) * K + kc + ck * 8);
        }
        cp_commit();
    };

    float c[4][8][4];
#pragma unroll
    for (int i = 0; i < 4; i++)
#pragma unroll
        for (int j = 0; j < 8; j++)
#pragma unroll
            for (int q = 0; q < 4; q++) c[i][j][q] = 0.f;

    load_chunk(0, 0);
    load_chunk(1, 1);
    load_chunk(2, 2);

    const int a_row = (lane & 15);
    const int a_col = ((lane >> 4) & 1) * 8;
    const int b_row = (lane & 7) + ((lane & 16) ? 8 : 0);
    const int b_col = ((lane & 8) ? 8 : 0);

    for (int cch = 0; cch < NCH; cch++) {
        cp_wait<2>();
        __syncthreads();

        if (cch + 3 < NCH) load_chunk(cch + 3, (cch + 3) & 3);
        else cp_commit();

        const uint32_t sb = sbase + (cch & 3) * STAGEB;
        const uint32_t sAh = sb;
        const uint32_t sAl = sb + TILEA;
        const uint32_t sB = sb + 2 * TILEA;

#pragma unroll
        for (int s = 0; s < 2; s++) {
            uint32_t ah[16], al[16], bh[16];
#pragma unroll
            for (int i = 0; i < 4; i++) {
                int row = wm * 64 + i * 16 + a_row;
                uint32_t off = (uint32_t)((row * PADK + s * 16 + a_col) * 2);
                ldsm4(&ah[i * 4], sAh + off);
                ldsm4(&al[i * 4], sAl + off);
            }
#pragma unroll
            for (int j2 = 0; j2 < 4; j2++) {
                int row = wn * 64 + j2 * 16 + b_row;
                uint32_t off = (uint32_t)((row * PADK + s * 16 + b_col) * 2);
                ldsm4(&bh[j2 * 4], sB + off);
            }
#pragma unroll
            for (int i = 0; i < 4; i++)
#pragma unroll
                for (int j = 0; j < 8; j++)
                    mma16816(c[i][j], &ah[i * 4], &bh[j * 2]);
#pragma unroll
            for (int i = 0; i < 4; i++)
#pragma unroll
                for (int j = 0; j < 8; j++)
                    mma16816(c[i][j], &al[i * 4], &bh[j * 2]);
        }
    }

    const int g = lane >> 2;
    const int tq = lane & 3;
#pragma unroll
    for (int i = 0; i < 4; i++) {
        int row0 = m0 + wm * 64 + i * 16 + g;
#pragma unroll
        for (int j = 0; j < 8; j++) {
            int col = n0 + wn * 64 + j * 8 + tq * 2;
            float2 v0 = {c[i][j][0], c[i][j][1]};
            float2 v1 = {c[i][j][2], c[i][j][3]};
            *(float2*)&C[(size_t)row0 * N + col] = v0;
            *(float2*)&C[(size_t)(row0 + 8) * N + col] = v1;
        }
    }
}

// ---------------------------------------------------------------------------
// RoPE + head-major fp16 conversion.
// Reads g_proj fp32, writes Qh,Ql (scaled, hi/lo), Kh (rounded), Vh,Vl (hi/lo)
// in [b*NH+h][s][d] layout. One thread per (token, head, pair i<64).
// ---------------------------------------------------------------------------
__global__ void rope_split(const float* __restrict__ proj, const int* __restrict__ positions,
                           __half* __restrict__ Qh, __half* __restrict__ Ql,
                           __half* __restrict__ Kh,
                           __half* __restrict__ Vh, __half* __restrict__ Vl)
{
    int idx = blockIdx.x * blockDim.x + threadIdx.x;
    int i = idx & 63;
    int h = (idx >> 6) & 31;
    int t = idx >> 11;                 // token 0..4095
    int b = t >> 11;                   // S=2048
    int s = t & 2047;

    int pos = positions[t];
    float inv = exp2f(-(float)i * (13.287712379549449f / 64.0f));
    float freq = (float)pos * inv;
    float sn, cs;
    sincosf(freq, &sn, &cs);

    const float scale = 0.08838834764831845f;  // 1/sqrt(128)

    size_t src = (size_t)t * PROJ3 + (size_t)h * HD + i;
    size_t dst = ((size_t)(b * NH + h) * S_SZ + s) * HD + i;

    // q (scaled, hi/lo)
    {
        float x1 = proj[src], x2 = proj[src + 64];
        float r1 = (x1 * cs - x2 * sn) * scale;
        float r2 = (x2 * cs + x1 * sn) * scale;
        __half h1 = __float2half_rn(r1), h2 = __float2half_rn(r2);
        Qh[dst] = h1; Qh[dst + 64] = h2;
        Ql[dst] = __float2half_rn(r1 - __half2float(h1));
        Ql[dst + 64] = __float2half_rn(r2 - __half2float(h2));
    }
    // k (rounded)
    {
        float x1 = proj[src + HID], x2 = proj[src + HID + 64];
        float r1 = x1 * cs - x2 * sn;
        float r2 = x2 * cs + x1 * sn;
        Kh[dst] = __float2half_rn(r1);
        Kh[dst + 64] = __float2half_rn(r2);
    }
    // v (hi/lo)
    {
        float v1 = proj[src + 2 * HID], v2 = proj[src + 2 * HID + 64];
        __half h1 = __float2half_rn(v1), h2 = __float2half_rn(v2);
        Vh[dst] = h1; Vh[dst + 64] = h2;
        Vl[dst] = __float2half_rn(v1 - __half2float(h1));
        Vl[dst + 64] = __float2half_rn(v2 - __half2float(h2));
    }
}

// ---------------------------------------------------------------------------
// HMMA flash attention, causal. Br=128 (8 warps x 16 rows), Bc=64.
// S = (Qh+Ql) @ Kh^T ; O = P @ (Vh+Vl). fp32 accumulators, online softmax.
// Epilogue writes Xh/Xl fp16 hi/lo directly (input to O-proj GEMM).
// ---------------------------------------------------------------------------
#define ATT_PAD 136                     // halves per smem row (128 + 8)
#define KVROWB (ATT_PAD * 2)            // 272 bytes
#define KTILE (64 * KVROWB)             // 17408
#define ASTG (3 * KTILE)                // K, Vh, Vl
#define ATT_SMEM (3 * ASTG)             // 3 stages = 156672

__global__ __launch_bounds__(256, 1)
void flash_attn_hmma(const __half* __restrict__ Qh, const __half* __restrict__ Ql,
                     const __half* __restrict__ Kh,
                     const __half* __restrict__ Vh, const __half* __restrict__ Vl,
                     __half* __restrict__ Xh, __half* __restrict__ Xl)
{
    extern __shared__ char smraw[];
    const uint32_t sbase = smem_u32(smraw);

    const int tid = threadIdx.x;
    const int wid = tid >> 5;
    const int lane = tid & 31;
    const int g = lane >> 2;
    const int tq = lane & 3;

    const int qb = 15 - (int)blockIdx.x;   // heavy tiles first
    const int bh = blockIdx.y;             // 0..63
    const int b = bh >> 5;
    const int h = bh & 31;
    const size_t hb = (size_t)bh * S_SZ * HD;
    const int row0 = qb * 128;             // q row base within sequence
    const int wr = wid * 16;               // warp row offset
    const int nkb = 2 * qb + 2;            // kv blocks of 64

    // ---- load Q fragments (hi and lo) via smem staging ----
    uint32_t qhf[8][4], qlf[8][4];
    {
        const __half* qsrc[2] = {Qh + hb + (size_t)row0 * HD, Ql + hb + (size_t)row0 * HD};
#pragma unroll
        for (int t2 = 0; t2 < 2; t2++) {
#pragma unroll
            for (int i = 0; i < 8; i++) {
                int op = tid + i * 256;        // 0..2047
                int r = op >> 4;
                int ck = op & 15;
                cp16(sbase + (uint32_t)(r * KVROWB + ck * 16),
                     qsrc[t2] + (size_t)r * HD + ck * 8);
            }
            cp_commit();
            cp_wait<0>();
            __syncthreads();
#pragma unroll
            for (int ks = 0; ks < 8; ks++) {
                uint32_t off = (uint32_t)((wr + (lane & 15)) * KVROWB +
                                          (ks * 16 + ((lane >> 4) << 3)) * 2);
                ldsm4(t2 ? qlf[ks] : qhf[ks], sbase + off);
            }
            __syncthreads();
        }
    }

    float o[16][4];
#pragma unroll
    for (int j = 0; j < 16; j++)
#pragma unroll
        for (int q = 0; q < 4; q++) o[j][q] = 0.f;
    float m_old0 = -1e30f, m_old1 = -1e30f, l0 = 0.f, l1 = 0.f;

    auto kvload = [&](int kb, int stg) {
        const uint32_t sb = sbase + stg * ASTG;
        const size_t src0 = hb + (size_t)kb * 64 * HD;
#pragma unroll
        for (int i = 0; i < 4; i++) {
            int op = tid + i * 256;           // 0..1023
            int r = op >> 4;
            int ck = op & 15;
            uint32_t soff = (uint32_t)(r * KVROWB + ck * 16);
            size_t goff = src0 + (size_t)r * HD + ck * 8;
            cp16(sb + soff, Kh + goff);
            cp16(sb + KTILE + soff, Vh + goff);
            cp16(sb + 2 * KTILE + soff, Vl + goff);
        }
        cp_commit();
    };

    kvload(0, 0);
    kvload(1, 1);    // nkb >= 2 always

    const int r_g = row0 + wr + g;   // global q row for this lane's row "g"

    for (int kb = 0; kb < nkb; kb++) {
        cp_wait<1>();
        __syncthreads();
        if (kb + 2 < nkb) kvload(kb + 2, (kb + 2) % 3);
        else cp_commit();

        const uint32_t sK = sbase + (kb % 3) * ASTG;
        const uint32_t sVh = sK + KTILE;
        const uint32_t sVl = sK + 2 * KTILE;

        // ---- S = Q K^T ----
        float s[8][4];
#pragma unroll
        for (int j = 0; j < 8; j++)
#pragma unroll
            for (int q = 0; q < 4; q++) s[j][q] = 0.f;

#pragma unroll
        for (int ks = 0; ks < 8; ks++) {
            uint32_t bk[16];
#pragma unroll
            for (int j2 = 0; j2 < 4; j2++) {
                int r = j2 * 16 + (lane & 7) + ((lane & 16) ? 8 : 0);
                uint32_t off = (uint32_t)(r * KVROWB + (ks * 16 + ((lane & 8) ? 8 : 0)) * 2);
                ldsm4(&bk[j2 * 4], sK + off);
            }
#pragma unroll
            for (int j = 0; j < 8; j++) mma16816(s[j], qhf[ks], &bk[j * 2]);
#pragma unroll
            for (int j = 0; j < 8; j++) mma16816(s[j], qlf[ks], &bk[j * 2]);
        }

        // ---- causal mask ----
        const int kv0 = kb * 64;
        if (kv0 + 63 > row0 + wr) {
#pragma unroll
            for (int j = 0; j < 8; j++) {
                int cc = kv0 + j * 8 + 2 * tq;
                if (cc > r_g) s[j][0] = -1e30f;
                if (cc + 1 > r_g) s[j][1] = -1e30f;
                if (cc > r_g + 8) s[j][2] = -1e30f;
                if (cc + 1 > r_g + 8) s[j][3] = -1e30f;
            }
        }

        // ---- online softmax (rows g and g+8) ----
        float mx0 = -1e30f, mx1 = -1e30f;
#pragma unroll
        for (int j = 0; j < 8; j++) {
            mx0 = fmaxf(mx0, fmaxf(s[j][0], s[j][1]));
            mx1 = fmaxf(mx1, fmaxf(s[j][2], s[j][3]));
        }
        mx0 = fmaxf(mx0, __shfl_xor_sync(0xffffffffu, mx0, 1));
        mx0 = fmaxf(mx0, __shfl_xor_sync(0xffffffffu, mx0, 2));
        mx1 = fmaxf(mx1, __shfl_xor_sync(0xffffffffu, mx1, 1));
        mx1 = fmaxf(mx1, __shfl_xor_sync(0xffffffffu, mx1, 2));

        float mn0 = fmaxf(m_old0, mx0);
        float mn1 = fmaxf(m_old1, mx1);
        float a0 = __expf(m_old0 - mn0);
        float a1 = __expf(m_old1 - mn1);

        float sum0 = 0.f, sum1 = 0.f;
        uint32_t pa[4][4];
#pragma unroll
        for (int ks = 0; ks < 4; ks++) {
            float p00 = __expf(s[2 * ks][0] - mn0);
            float p01 = __expf(s[2 * ks][1] - mn0);
            float p02 = __expf(s[2 * ks][2] - mn1);
            float p03 = __expf(s[2 * ks][3] - mn1);
            float p10 = __expf(s[2 * ks + 1][0] - mn0);
            float p11 = __expf(s[2 * ks + 1][1] - mn0);
            float p12 = __expf(s[2 * ks + 1][2] - mn1);
            float p13 = __expf(s[2 * ks + 1][3] - mn1);
            sum0 += p00 + p01 + p10 + p11;
            sum1 += p02 + p03 + p12 + p13;
            pa[ks][0] = packh2(p00, p01);
            pa[ks][1] = packh2(p02, p03);
            pa[ks][2] = packh2(p10, p11);
            pa[ks][3] = packh2(p12, p13);
        }
        sum0 += __shfl_xor_sync(0xffffffffu, sum0, 1);
        sum0 += __shfl_xor_sync(0xffffffffu, sum0, 2);
        sum1 += __shfl_xor_sync(0xffffffffu, sum1, 1);
        sum1 += __shfl_xor_sync(0xffffffffu, sum1, 2);

        l0 = l0 * a0 + sum0;
        l1 = l1 * a1 + sum1;
        m_old0 = mn0;
        m_old1 = mn1;

#pragma unroll
        for (int j = 0; j < 16; j++) {
            o[j][0] *= a0; o[j][1] *= a0;
            o[j][2] *= a1; o[j][3] *= a1;
        }

        // ---- O += P V  (Vh + Vl) ----
#pragma unroll
        for (int ks = 0; ks < 4; ks++) {
#pragma unroll
            for (int jj = 0; jj < 8; jj++) {
                int krow = ks * 16 + (lane & 15);
                uint32_t off = (uint32_t)(krow * KVROWB + (jj * 16 + ((lane & 16) ? 8 : 0)) * 2);
                uint32_t bv[4];
                ldsm4t(bv, sVh + off);
                mma16816(o[jj * 2], pa[ks], &bv[0]);
                mma16816(o[jj * 2 + 1], pa[ks], &bv[2]);
                ldsm4t(bv, sVl + off);
                mma16816(o[jj * 2], pa[ks], &bv[0]);
                mma16816(o[jj * 2 + 1], pa[ks], &bv[2]);
            }
        }
    }

    // ---- epilogue: normalize, split hi/lo, store to Xh/Xl [tok][h*128+d] ----
    const float il0 = 1.f / l0;
    const float il1 = 1.f / l1;
    const int tok0 = b * S_SZ + row0 + wr;
#pragma unroll
    for (int j = 0; j < 16; j++) {
        int col = h * HD + j * 8 + 2 * tq;
        size_t i0 = (size_t)(tok0 + g) * HID + col;
        size_t i1 = (size_t)(tok0 + g + 8) * HID + col;
        float v0 = o[j][0] * il0, v1 = o[j][1] * il0;
        float v2 = o[j][2] * il1, v3 = o[j][3] * il1;
        __half h0 = __float2half_rn(v0), h1v = __float2half_rn(v1);
        __half h2 = __float2half_rn(v2), h3 = __float2half_rn(v3);
        __half l0h = __float2half_rn(v0 - __half2float(h0));
        __half l1h = __float2half_rn(v1 - __half2float(h1v));
        __half l2h = __float2half_rn(v2 - __half2float(h2));
        __half l3h = __float2half_rn(v3 - __half2float(h3));
        *(uint32_t*)&Xh[i0] = packh2(__half2float(h0), 0) * 0;  // placeholder avoided below
        // direct packed stores:
        __half2 hh0 = __halves2half2(h0, h1v);
        __half2 hh1 = __halves2half2(h2, h3);
        __half2 ll0 = __halves2half2(l0h, l1h);
        __half2 ll1 = __halves2half2(l2h, l3h);
        *(__half2*)&Xh[i0] = hh0;
        *(__half2*)&Xh[i1] = hh1;
        *(__half2*)&Xl[i0] = ll0;
        *(__half2*)&Xl[i1] = ll1;
    }
}

// ---------------------------------------------------------------------------
// Launch
// ---------------------------------------------------------------------------
extern "C" void kernel_launch(void* const* d_in, const int* in_sizes, int n_in,
                              void* d_out, int out_size)
{
    const float* hidden = (const float*)d_in[0];
    const int* positions = (const int*)d_in[1];
    const float* W_pack = (const float*)d_in[2];
    const float* W_o = (const float*)d_in[3];
    float* out = (float*)d_out;

    void* pp; cudaGetSymbolAddress(&pp, g_proj);
    float* proj = (float*)pp;

    void* v_ah; cudaGetSymbolAddress(&v_ah, g_Ah);
    void* v_al; cudaGetSymbolAddress(&v_al, g_Al);
    void* v_wp; cudaGetSymbolAddress(&v_wp, g_Wp);
    void* v_wo; cudaGetSymbolAddress(&v_wo, g_Wo);
    void* v_xh; cudaGetSymbolAddress(&v_xh, g_Xh);
    void* v_xl; cudaGetSymbolAddress(&v_xl, g_Xl);
    void* v_qh; cudaGetSymbolAddress(&v_qh, g_Qh);
    void* v_ql; cudaGetSymbolAddress(&v_ql, g_Ql);
    void* v_kh; cudaGetSymbolAddress(&v_kh, g_Kh);
    void* v_vh; cudaGetSymbolAddress(&v_vh, g_Vh);
    void* v_vl; cudaGetSymbolAddress(&v_vl, g_Vl);

    cudaFuncSetAttribute(gemm_f16x2, cudaFuncAttributeMaxDynamicSharedMemorySize, GEMM_SMEM);
    cudaFuncSetAttribute(flash_attn_hmma, cudaFuncAttributeMaxDynamicSharedMemorySize, ATT_SMEM);

    // 0) operand prep
    {
        int n8 = TOK * HID / 8;
        split_f16<<<(n8 + 255) / 256, 256>>>(hidden, (__half*)v_ah, (__half*)v_al, n8);
        int w8 = PROJ3 * HID / 8;
        conv_f16<<<(w8 + 255) / 256, 256>>>(W_pack, (__half*)v_wp, w8);
        int o8 = HID * HID / 8;
        conv_f16<<<(o8 + 255) / 256, 256>>>(W_o, (__half*)v_wo, o8);
    }

    // 1) QKV projection: proj = hidden @ W_pack^T
    {
        dim3 grid(PROJ3 / BN, TOK / BM);
        gemm_f16x2<<<grid, 256, GEMM_SMEM>>>((const __half*)v_ah, (const __half*)v_al,
                                             (const __half*)v_wp, proj, PROJ3, HID);
    }

    // 2) RoPE + fp16 conversion to head-major layout
    {
        int total = TOK * NH * 64;
        rope_split<<<total / 256, 256>>>(proj, positions,
                                         (__half*)v_qh, (__half*)v_ql, (__half*)v_kh,
                                         (__half*)v_vh, (__half*)v_vl);
    }

    // 3) Causal attention on tensor cores; writes Xh/Xl directly
    {
        dim3 grid(S_SZ / 128, B_SZ * NH);  // 16 x 64
        flash_attn_hmma<<<grid, 256, ATT_SMEM>>>((const __half*)v_qh, (const __half*)v_ql,
                                                 (const __half*)v_kh,
                                                 (const __half*)v_vh, (const __half*)v_vl,
                                                 (__half*)v_xh, (__half*)v_xl);
    }

    // 4) out = attn @ W_o^T
    {
        dim3 grid(HID / BN, TOK / BM);
        gemm_f16x2<<<grid, 256, GEMM_SMEM>>>((const __half*)v_xh, (const __half*)v_xl,
                                             (const __half*)v_wo, out, HID, HID);
    }
}

// round 6
// speedup vs baseline: 4.3708x; 1.0461x over previous
#include <cuda_runtime.h>
#include <cuda_fp16.h>
#include <math.h>
#include <stdint.h>

// Problem constants
#define B_SZ 2
#define S_SZ 2048
#define HID 4096
#define NH 32
#define HD 128
#define TOK (B_SZ * S_SZ)          // 4096 tokens
#define PROJ3 (3 * HID)            // 12288

// Scratch (static device globals — allocation-free rule)
__device__ float g_proj[(size_t)TOK * PROJ3];   // [4096, 12288] q|k|v (fp32)
// fp16 operands for GEMMs
__device__ __half g_Ah[(size_t)TOK * HID];
__device__ __half g_Al[(size_t)TOK * HID];
__device__ __half g_Wp[(size_t)PROJ3 * HID];
__device__ __half g_Wo[(size_t)HID * HID];
__device__ __half g_Xh[(size_t)TOK * HID];
__device__ __half g_Xl[(size_t)TOK * HID];
// head-major fp16 attention operands [b*NH+h][s][d]
__device__ __half g_Qh[(size_t)TOK * HID];
__device__ __half g_Ql[(size_t)TOK * HID];
__device__ __half g_Kh[(size_t)TOK * HID];
__device__ __half g_Vh[(size_t)TOK * HID];
__device__ __half g_Vl[(size_t)TOK * HID];

// ---------------------------------------------------------------------------
// Inline PTX helpers
// ---------------------------------------------------------------------------
__device__ __forceinline__ uint32_t smem_u32(const void* p) {
    uint32_t a;
    asm("{ .reg .u64 t; cvta.to.shared.u64 t, %1; cvt.u32.u64 %0, t; }" : "=r"(a) : "l"(p));
    return a;
}
__device__ __forceinline__ void cp16(uint32_t dst, const void* src) {
    asm volatile("cp.async.cg.shared.global [%0], [%1], 16;" :: "r"(dst), "l"(src) : "memory");
}
__device__ __forceinline__ void cp_commit() { asm volatile("cp.async.commit_group;" ::: "memory"); }
template <int N>
__device__ __forceinline__ void cp_wait() {
    asm volatile("cp.async.wait_group %0;" :: "n"(N) : "memory");
}
__device__ __forceinline__ void ldsm4(uint32_t r[4], uint32_t addr) {
    asm volatile("ldmatrix.sync.aligned.m8n8.x4.shared.b16 {%0,%1,%2,%3}, [%4];"
                 : "=r"(r[0]), "=r"(r[1]), "=r"(r[2]), "=r"(r[3]) : "r"(addr));
}
__device__ __forceinline__ void ldsm4t(uint32_t r[4], uint32_t addr) {
    asm volatile("ldmatrix.sync.aligned.m8n8.x4.trans.shared.b16 {%0,%1,%2,%3}, [%4];"
                 : "=r"(r[0]), "=r"(r[1]), "=r"(r[2]), "=r"(r[3]) : "r"(addr));
}
__device__ __forceinline__ void mma16816(float c[4], const uint32_t a[4], const uint32_t b[2]) {
    asm volatile(
        "mma.sync.aligned.m16n8k16.row.col.f32.f16.f16.f32 "
        "{%0,%1,%2,%3}, {%4,%5,%6,%7}, {%8,%9}, {%0,%1,%2,%3};"
        : "+f"(c[0]), "+f"(c[1]), "+f"(c[2]), "+f"(c[3])
        : "r"(a[0]), "r"(a[1]), "r"(a[2]), "r"(a[3]), "r"(b[0]), "r"(b[1]));
}
__device__ __forceinline__ uint32_t packh2(float a, float b) {
    __half2 h = __floats2half2_rn(a, b);
    return *(uint32_t*)&h;
}

// ---------------------------------------------------------------------------
// fp32 -> fp16 hi/lo split (exact to ~2^-24). 8 elements/thread.
// ---------------------------------------------------------------------------
__global__ void split_f16(const float* __restrict__ x, __half* __restrict__ hi,
                          __half* __restrict__ lo, int n8)
{
    int i = blockIdx.x * blockDim.x + threadIdx.x;
    if (i >= n8) return;
    const float4* xp = (const float4*)x + (size_t)i * 2;
    float4 a = xp[0], b = xp[1];
    float v[8] = {a.x, a.y, a.z, a.w, b.x, b.y, b.z, b.w};
    __half h[8], l[8];
#pragma unroll
    for (int j = 0; j < 8; j++) {
        h[j] = __float2half_rn(v[j]);
        l[j] = __float2half_rn(v[j] - __half2float(h[j]));
    }
    *((uint4*)hi + i) = *(const uint4*)h;
    *((uint4*)lo + i) = *(const uint4*)l;
}

__global__ void conv_f16(const float* __restrict__ x, __half* __restrict__ y, int n8)
{
    int i = blockIdx.x * blockDim.x + threadIdx.x;
    if (i >= n8) return;
    const float4* xp = (const float4*)x + (size_t)i * 2;
    float4 a = xp[0], b = xp[1];
    float v[8] = {a.x, a.y, a.z, a.w, b.x, b.y, b.z, b.w};
    __half h[8];
#pragma unroll
    for (int j = 0; j < 8; j++) h[j] = __float2half_rn(v[j]);
    *((uint4*)y + i) = *(const uint4*)h;
}

// ---------------------------------------------------------------------------
// HMMA fp16x2 GEMM: C = (Ah+Al) @ B^T.
// CTA tile 128x128, BK=32, 3-stage cp.async, 8 warps (2x4), warp tile 64x32.
// 2 CTAs per SM (regs capped at 128, smem 90KB/CTA).
// ---------------------------------------------------------------------------
#define BM 128
#define BN 128
#define BK 32
#define STAGES 3
#define PADK 40                        // halves per smem row (32 + 8 pad)
#define TILEA (128 * PADK * 2)         // 10240 B per [128][40] fp16 tile
#define STAGEB (3 * TILEA)             // Ah, Al, B = 30720 B
#define GEMM_SMEM (STAGES * STAGEB)    // 92160 B

__global__ __launch_bounds__(256, 2)
void gemm_f16x2(const __half* __restrict__ Ah, const __half* __restrict__ Al,
                const __half* __restrict__ Bh, float* __restrict__ C, int N, int K)
{
    extern __shared__ char smraw[];
    const uint32_t sbase = smem_u32(smraw);

    const int tid = threadIdx.x;
    const int wid = tid >> 5;
    const int lane = tid & 31;
    const int wm = wid >> 2;          // 0..1 (64 rows)
    const int wn = wid & 3;           // 0..3 (32 cols)
    const int m0 = blockIdx.y * BM;
    const int n0 = blockIdx.x * BN;
    const int NCH = K >> 5;

    auto load_chunk = [&](int c, int stg) {
        const uint32_t sb = sbase + stg * STAGEB;
        const int kc = c * BK;
#pragma unroll
        for (int i = 0; i < 2; i++) {
            int op = tid + i * 256;       // 0..511
            int row = op >> 2;
            int ck = op & 3;
            uint32_t soff = (uint32_t)(row * PADK * 2 + ck * 16);
            size_t aoff = (size_t)(m0 + row) * K + kc + ck * 8;
            cp16(sb + soff, Ah + aoff);
            cp16(sb + TILEA + soff, Al + aoff);
            cp16(sb + 2 * TILEA + soff, Bh + (size_t)(n0 + row) * K + kc + ck * 8);
        }
        cp_commit();
    };

    float c[4][4][4];
#pragma unroll
    for (int i = 0; i < 4; i++)
#pragma unroll
        for (int j = 0; j < 4; j++)
#pragma unroll
            for (int q = 0; q < 4; q++) c[i][j][q] = 0.f;

    load_chunk(0, 0);
    load_chunk(1, 1);

    const int a_row = (lane & 15);
    const int a_col = ((lane >> 4) & 1) * 8;
    const int b_row = (lane & 7) + ((lane & 16) ? 8 : 0);
    const int b_col = ((lane & 8) ? 8 : 0);

    for (int cch = 0; cch < NCH; cch++) {
        cp_wait<1>();
        __syncthreads();

        if (cch + 2 < NCH) load_chunk(cch + 2, (cch + 2) % 3);
        else cp_commit();

        const uint32_t sb = sbase + (cch % 3) * STAGEB;
        const uint32_t sAh = sb;
        const uint32_t sAl = sb + TILEA;
        const uint32_t sB = sb + 2 * TILEA;

#pragma unroll
        for (int s = 0; s < 2; s++) {
            uint32_t bh[8];
#pragma unroll
            for (int j2 = 0; j2 < 2; j2++) {
                int row = wn * 32 + j2 * 16 + b_row;
                uint32_t off = (uint32_t)((row * PADK + s * 16 + b_col) * 2);
                ldsm4(&bh[j2 * 4], sB + off);
            }
            // term 1: Ah * B
            {
                uint32_t af[16];
#pragma unroll
                for (int i = 0; i < 4; i++) {
                    int row = wm * 64 + i * 16 + a_row;
                    uint32_t off = (uint32_t)((row * PADK + s * 16 + a_col) * 2);
                    ldsm4(&af[i * 4], sAh + off);
                }
#pragma unroll
                for (int i = 0; i < 4; i++)
#pragma unroll
                    for (int j = 0; j < 4; j++)
                        mma16816(c[i][j], &af[i * 4], &bh[j * 2]);
            }
            // term 2: Al * B
            {
                uint32_t af[16];
#pragma unroll
                for (int i = 0; i < 4; i++) {
                    int row = wm * 64 + i * 16 + a_row;
                    uint32_t off = (uint32_t)((row * PADK + s * 16 + a_col) * 2);
                    ldsm4(&af[i * 4], sAl + off);
                }
#pragma unroll
                for (int i = 0; i < 4; i++)
#pragma unroll
                    for (int j = 0; j < 4; j++)
                        mma16816(c[i][j], &af[i * 4], &bh[j * 2]);
            }
        }
        __syncthreads();
    }

    const int g = lane >> 2;
    const int tq = lane & 3;
#pragma unroll
    for (int i = 0; i < 4; i++) {
        int row0 = m0 + wm * 64 + i * 16 + g;
#pragma unroll
        for (int j = 0; j < 4; j++) {
            int col = n0 + wn * 32 + j * 8 + tq * 2;
            float2 v0 = {c[i][j][0], c[i][j][1]};
            float2 v1 = {c[i][j][2], c[i][j][3]};
            *(float2*)&C[(size_t)row0 * N + col] = v0;
            *(float2*)&C[(size_t)(row0 + 8) * N + col] = v1;
        }
    }
}

// ---------------------------------------------------------------------------
// RoPE + head-major fp16 conversion. (unchanged from R5)
// ---------------------------------------------------------------------------
__global__ void rope_split(const float* __restrict__ proj, const int* __restrict__ positions,
                           __half* __restrict__ Qh, __half* __restrict__ Ql,
                           __half* __restrict__ Kh,
                           __half* __restrict__ Vh, __half* __restrict__ Vl)
{
    int idx = blockIdx.x * blockDim.x + threadIdx.x;
    int i = idx & 63;
    int h = (idx >> 6) & 31;
    int t = idx >> 11;                 // token 0..4095
    int b = t >> 11;
    int s = t & 2047;

    int pos = positions[t];
    float inv = exp2f(-(float)i * (13.287712379549449f / 64.0f));
    float freq = (float)pos * inv;
    float sn, cs;
    sincosf(freq, &sn, &cs);

    const float scale = 0.08838834764831845f;  // 1/sqrt(128)

    size_t src = (size_t)t * PROJ3 + (size_t)h * HD + i;
    size_t dst = ((size_t)(b * NH + h) * S_SZ + s) * HD + i;

    {
        float x1 = proj[src], x2 = proj[src + 64];
        float r1 = (x1 * cs - x2 * sn) * scale;
        float r2 = (x2 * cs + x1 * sn) * scale;
        __half h1 = __float2half_rn(r1), h2 = __float2half_rn(r2);
        Qh[dst] = h1; Qh[dst + 64] = h2;
        Ql[dst] = __float2half_rn(r1 - __half2float(h1));
        Ql[dst + 64] = __float2half_rn(r2 - __half2float(h2));
    }
    {
        float x1 = proj[src + HID], x2 = proj[src + HID + 64];
        Kh[dst] = __float2half_rn(x1 * cs - x2 * sn);
        Kh[dst + 64] = __float2half_rn(x2 * cs + x1 * sn);
    }
    {
        float v1 = proj[src + 2 * HID], v2 = proj[src + 2 * HID + 64];
        __half h1 = __float2half_rn(v1), h2 = __float2half_rn(v2);
        Vh[dst] = h1; Vh[dst + 64] = h2;
        Vl[dst] = __float2half_rn(v1 - __half2float(h1));
        Vl[dst + 64] = __float2half_rn(v2 - __half2float(h2));
    }
}

// ---------------------------------------------------------------------------
// HMMA flash attention, causal. (unchanged from R5 except cleaned epilogue)
// ---------------------------------------------------------------------------
#define ATT_PAD 136
#define KVROWB (ATT_PAD * 2)            // 272 bytes
#define KTILE (64 * KVROWB)             // 17408
#define ASTG (3 * KTILE)
#define ATT_SMEM (3 * ASTG)             // 156672

__global__ __launch_bounds__(256, 1)
void flash_attn_hmma(const __half* __restrict__ Qh, const __half* __restrict__ Ql,
                     const __half* __restrict__ Kh,
                     const __half* __restrict__ Vh, const __half* __restrict__ Vl,
                     __half* __restrict__ Xh, __half* __restrict__ Xl)
{
    extern __shared__ char smraw[];
    const uint32_t sbase = smem_u32(smraw);

    const int tid = threadIdx.x;
    const int wid = tid >> 5;
    const int lane = tid & 31;
    const int g = lane >> 2;
    const int tq = lane & 3;

    const int qb = 15 - (int)blockIdx.x;
    const int bh = blockIdx.y;
    const int b = bh >> 5;
    const int h = bh & 31;
    const size_t hb = (size_t)bh * S_SZ * HD;
    const int row0 = qb * 128;
    const int wr = wid * 16;
    const int nkb = 2 * qb + 2;

    uint32_t qhf[8][4], qlf[8][4];
    {
        const __half* qsrc[2] = {Qh + hb + (size_t)row0 * HD, Ql + hb + (size_t)row0 * HD};
#pragma unroll
        for (int t2 = 0; t2 < 2; t2++) {
#pragma unroll
            for (int i = 0; i < 8; i++) {
                int op = tid + i * 256;
                int r = op >> 4;
                int ck = op & 15;
                cp16(sbase + (uint32_t)(r * KVROWB + ck * 16),
                     qsrc[t2] + (size_t)r * HD + ck * 8);
            }
            cp_commit();
            cp_wait<0>();
            __syncthreads();
#pragma unroll
            for (int ks = 0; ks < 8; ks++) {
                uint32_t off = (uint32_t)((wr + (lane & 15)) * KVROWB +
                                          (ks * 16 + ((lane >> 4) << 3)) * 2);
                ldsm4(t2 ? qlf[ks] : qhf[ks], sbase + off);
            }
            __syncthreads();
        }
    }

    float o[16][4];
#pragma unroll
    for (int j = 0; j < 16; j++)
#pragma unroll
        for (int q = 0; q < 4; q++) o[j][q] = 0.f;
    float m_old0 = -1e30f, m_old1 = -1e30f, l0 = 0.f, l1 = 0.f;

    auto kvload = [&](int kb, int stg) {
        const uint32_t sb = sbase + stg * ASTG;
        const size_t src0 = hb + (size_t)kb * 64 * HD;
#pragma unroll
        for (int i = 0; i < 4; i++) {
            int op = tid + i * 256;
            int r = op >> 4;
            int ck = op & 15;
            uint32_t soff = (uint32_t)(r * KVROWB + ck * 16);
            size_t goff = src0 + (size_t)r * HD + ck * 8;
            cp16(sb + soff, Kh + goff);
            cp16(sb + KTILE + soff, Vh + goff);
            cp16(sb + 2 * KTILE + soff, Vl + goff);
        }
        cp_commit();
    };

    kvload(0, 0);
    kvload(1, 1);

    const int r_g = row0 + wr + g;

    for (int kb = 0; kb < nkb; kb++) {
        cp_wait<1>();
        __syncthreads();
        if (kb + 2 < nkb) kvload(kb + 2, (kb + 2) % 3);
        else cp_commit();

        const uint32_t sK = sbase + (kb % 3) * ASTG;
        const uint32_t sVh = sK + KTILE;
        const uint32_t sVl = sK + 2 * KTILE;

        float s[8][4];
#pragma unroll
        for (int j = 0; j < 8; j++)
#pragma unroll
            for (int q = 0; q < 4; q++) s[j][q] = 0.f;

#pragma unroll
        for (int ks = 0; ks < 8; ks++) {
            uint32_t bk[16];
#pragma unroll
            for (int j2 = 0; j2 < 4; j2++) {
                int r = j2 * 16 + (lane & 7) + ((lane & 16) ? 8 : 0);
                uint32_t off = (uint32_t)(r * KVROWB + (ks * 16 + ((lane & 8) ? 8 : 0)) * 2);
                ldsm4(&bk[j2 * 4], sK + off);
            }
#pragma unroll
            for (int j = 0; j < 8; j++) mma16816(s[j], qhf[ks], &bk[j * 2]);
#pragma unroll
            for (int j = 0; j < 8; j++) mma16816(s[j], qlf[ks], &bk[j * 2]);
        }

        const int kv0 = kb * 64;
        if (kv0 + 63 > row0 + wr) {
#pragma unroll
            for (int j = 0; j < 8; j++) {
                int cc = kv0 + j * 8 + 2 * tq;
                if (cc > r_g) s[j][0] = -1e30f;
                if (cc + 1 > r_g) s[j][1] = -1e30f;
                if (cc > r_g + 8) s[j][2] = -1e30f;
                if (cc + 1 > r_g + 8) s[j][3] = -1e30f;
            }
        }

        float mx0 = -1e30f, mx1 = -1e30f;
#pragma unroll
        for (int j = 0; j < 8; j++) {
            mx0 = fmaxf(mx0, fmaxf(s[j][0], s[j][1]));
            mx1 = fmaxf(mx1, fmaxf(s[j][2], s[j][3]));
        }
        mx0 = fmaxf(mx0, __shfl_xor_sync(0xffffffffu, mx0, 1));
        mx0 = fmaxf(mx0, __shfl_xor_sync(0xffffffffu, mx0, 2));
        mx1 = fmaxf(mx1, __shfl_xor_sync(0xffffffffu, mx1, 1));
        mx1 = fmaxf(mx1, __shfl_xor_sync(0xffffffffu, mx1, 2));

        float mn0 = fmaxf(m_old0, mx0);
        float mn1 = fmaxf(m_old1, mx1);
        float a0 = __expf(m_old0 - mn0);
        float a1 = __expf(m_old1 - mn1);

        float sum0 = 0.f, sum1 = 0.f;
        uint32_t pa[4][4];
#pragma unroll
        for (int ks = 0; ks < 4; ks++) {
            float p00 = __expf(s[2 * ks][0] - mn0);
            float p01 = __expf(s[2 * ks][1] - mn0);
            float p02 = __expf(s[2 * ks][2] - mn1);
            float p03 = __expf(s[2 * ks][3] - mn1);
            float p10 = __expf(s[2 * ks + 1][0] - mn0);
            float p11 = __expf(s[2 * ks + 1][1] - mn0);
            float p12 = __expf(s[2 * ks + 1][2] - mn1);
            float p13 = __expf(s[2 * ks + 1][3] - mn1);
            sum0 += p00 + p01 + p10 + p11;
            sum1 += p02 + p03 + p12 + p13;
            pa[ks][0] = packh2(p00, p01);
            pa[ks][1] = packh2(p02, p03);
            pa[ks][2] = packh2(p10, p11);
            pa[ks][3] = packh2(p12, p13);
        }
        sum0 += __shfl_xor_sync(0xffffffffu, sum0, 1);
        sum0 += __shfl_xor_sync(0xffffffffu, sum0, 2);
        sum1 += __shfl_xor_sync(0xffffffffu, sum1, 1);
        sum1 += __shfl_xor_sync(0xffffffffu, sum1, 2);

        l0 = l0 * a0 + sum0;
        l1 = l1 * a1 + sum1;
        m_old0 = mn0;
        m_old1 = mn1;

#pragma unroll
        for (int j = 0; j < 16; j++) {
            o[j][0] *= a0; o[j][1] *= a0;
            o[j][2] *= a1; o[j][3] *= a1;
        }

#pragma unroll
        for (int ks = 0; ks < 4; ks++) {
#pragma unroll
            for (int jj = 0; jj < 8; jj++) {
                int krow = ks * 16 + (lane & 15);
                uint32_t off = (uint32_t)(krow * KVROWB + (jj * 16 + ((lane & 16) ? 8 : 0)) * 2);
                uint32_t bv[4];
                ldsm4t(bv, sVh + off);
                mma16816(o[jj * 2], pa[ks], &bv[0]);
                mma16816(o[jj * 2 + 1], pa[ks], &bv[2]);
                ldsm4t(bv, sVl + off);
                mma16816(o[jj * 2], pa[ks], &bv[0]);
                mma16816(o[jj * 2 + 1], pa[ks], &bv[2]);
            }
        }
    }

    const float il0 = 1.f / l0;
    const float il1 = 1.f / l1;
    const int tok0 = b * S_SZ + row0 + wr;
#pragma unroll
    for (int j = 0; j < 16; j++) {
        int col = h * HD + j * 8 + 2 * tq;
        size_t i0 = (size_t)(tok0 + g) * HID + col;
        size_t i1 = (size_t)(tok0 + g + 8) * HID + col;
        float v0 = o[j][0] * il0, v1 = o[j][1] * il0;
        float v2 = o[j][2] * il1, v3 = o[j][3] * il1;
        __half h0 = __float2half_rn(v0), h1v = __float2half_rn(v1);
        __half h2 = __float2half_rn(v2), h3 = __float2half_rn(v3);
        __half2 hh0 = __halves2half2(h0, h1v);
        __half2 hh1 = __halves2half2(h2, h3);
        __half2 ll0 = __halves2half2(__float2half_rn(v0 - __half2float(h0)),
                                     __float2half_rn(v1 - __half2float(h1v)));
        __half2 ll1 = __halves2half2(__float2half_rn(v2 - __half2float(h2)),
                                     __float2half_rn(v3 - __half2float(h3)));
        *(__half2*)&Xh[i0] = hh0;
        *(__half2*)&Xh[i1] = hh1;
        *(__half2*)&Xl[i0] = ll0;
        *(__half2*)&Xl[i1] = ll1;
    }
}

// ---------------------------------------------------------------------------
// Launch
// ---------------------------------------------------------------------------
extern "C" void kernel_launch(void* const* d_in, const int* in_sizes, int n_in,
                              void* d_out, int out_size)
{
    const float* hidden = (const float*)d_in[0];
    const int* positions = (const int*)d_in[1];
    const float* W_pack = (const float*)d_in[2];
    const float* W_o = (const float*)d_in[3];
    float* out = (float*)d_out;

    void* pp; cudaGetSymbolAddress(&pp, g_proj);
    float* proj = (float*)pp;

    void* v_ah; cudaGetSymbolAddress(&v_ah, g_Ah);
    void* v_al; cudaGetSymbolAddress(&v_al, g_Al);
    void* v_wp; cudaGetSymbolAddress(&v_wp, g_Wp);
    void* v_wo; cudaGetSymbolAddress(&v_wo, g_Wo);
    void* v_xh; cudaGetSymbolAddress(&v_xh, g_Xh);
    void* v_xl; cudaGetSymbolAddress(&v_xl, g_Xl);
    void* v_qh; cudaGetSymbolAddress(&v_qh, g_Qh);
    void* v_ql; cudaGetSymbolAddress(&v_ql, g_Ql);
    void* v_kh; cudaGetSymbolAddress(&v_kh, g_Kh);
    void* v_vh; cudaGetSymbolAddress(&v_vh, g_Vh);
    void* v_vl; cudaGetSymbolAddress(&v_vl, g_Vl);

    cudaFuncSetAttribute(gemm_f16x2, cudaFuncAttributeMaxDynamicSharedMemorySize, GEMM_SMEM);
    cudaFuncSetAttribute(flash_attn_hmma, cudaFuncAttributeMaxDynamicSharedMemorySize, ATT_SMEM);

    // 0) operand prep
    {
        int n8 = TOK * HID / 8;
        split_f16<<<(n8 + 255) / 256, 256>>>(hidden, (__half*)v_ah, (__half*)v_al, n8);
        int w8 = PROJ3 * HID / 8;
        conv_f16<<<(w8 + 255) / 256, 256>>>(W_pack, (__half*)v_wp, w8);
        int o8 = HID * HID / 8;
        conv_f16<<<(o8 + 255) / 256, 256>>>(W_o, (__half*)v_wo, o8);
    }

    // 1) QKV projection: proj = hidden @ W_pack^T
    {
        dim3 grid(PROJ3 / BN, TOK / BM);  // 96 x 32
        gemm_f16x2<<<grid, 256, GEMM_SMEM>>>((const __half*)v_ah, (const __half*)v_al,
                                             (const __half*)v_wp, proj, PROJ3, HID);
    }

    // 2) RoPE + fp16 conversion to head-major layout
    {
        int total = TOK * NH * 64;
        rope_split<<<total / 256, 256>>>(proj, positions,
                                         (__half*)v_qh, (__half*)v_ql, (__half*)v_kh,
                                         (__half*)v_vh, (__half*)v_vl);
    }

    // 3) Causal attention on tensor cores; writes Xh/Xl directly
    {
        dim3 grid(S_SZ / 128, B_SZ * NH);  // 16 x 64
        flash_attn_hmma<<<grid, 256, ATT_SMEM>>>((const __half*)v_qh, (const __half*)v_ql,
                                                 (const __half*)v_kh,
                                                 (const __half*)v_vh, (const __half*)v_vl,
                                                 (__half*)v_xh, (__half*)v_xl);
    }

    // 4) out = attn @ W_o^T
    {
        dim3 grid(HID / BN, TOK / BM);  // 32 x 32
        gemm_f16x2<<<grid, 256, GEMM_SMEM>>>((const __half*)v_xh, (const __half*)v_xl,
                                             (const __half*)v_wo, out, HID, HID);
    }
}

// round 7
// speedup vs baseline: 6.8343x; 1.5636x over previous
#include <cuda_runtime.h>
#include <cuda_fp16.h>
#include <math.h>
#include <stdint.h>

// Problem constants
#define B_SZ 2
#define S_SZ 2048
#define HID 4096
#define NH 32
#define HD 128
#define TOK (B_SZ * S_SZ)          // 4096 tokens
#define PROJ3 (3 * HID)            // 12288

// Scratch (static device globals — allocation-free rule)
__device__ float g_proj[(size_t)TOK * PROJ3];   // [4096, 12288] q|k|v (fp32)
// fp16 operands for GEMMs (single-term: A rounded, B rounded)
__device__ __half g_Ah[(size_t)TOK * HID];
__device__ __half g_Wp[(size_t)PROJ3 * HID];
__device__ __half g_Wo[(size_t)HID * HID];
__device__ __half g_Xh[(size_t)TOK * HID];
// head-major fp16 attention operands [b*NH+h][s][d]
__device__ __half g_Qh[(size_t)TOK * HID];
__device__ __half g_Ql[(size_t)TOK * HID];
__device__ __half g_Kh[(size_t)TOK * HID];
__device__ __half g_Vh[(size_t)TOK * HID];
__device__ __half g_Vl[(size_t)TOK * HID];

// ---------------------------------------------------------------------------
// Inline PTX helpers
// ---------------------------------------------------------------------------
__device__ __forceinline__ uint32_t smem_u32(const void* p) {
    uint32_t a;
    asm("{ .reg .u64 t; cvta.to.shared.u64 t, %1; cvt.u32.u64 %0, t; }" : "=r"(a) : "l"(p));
    return a;
}
__device__ __forceinline__ void cp16(uint32_t dst, const void* src) {
    asm volatile("cp.async.cg.shared.global [%0], [%1], 16;" :: "r"(dst), "l"(src) : "memory");
}
__device__ __forceinline__ void cp_commit() { asm volatile("cp.async.commit_group;" ::: "memory"); }
template <int N>
__device__ __forceinline__ void cp_wait() {
    asm volatile("cp.async.wait_group %0;" :: "n"(N) : "memory");
}
__device__ __forceinline__ void ldsm4(uint32_t r[4], uint32_t addr) {
    asm volatile("ldmatrix.sync.aligned.m8n8.x4.shared.b16 {%0,%1,%2,%3}, [%4];"
                 : "=r"(r[0]), "=r"(r[1]), "=r"(r[2]), "=r"(r[3]) : "r"(addr));
}
__device__ __forceinline__ void ldsm4t(uint32_t r[4], uint32_t addr) {
    asm volatile("ldmatrix.sync.aligned.m8n8.x4.trans.shared.b16 {%0,%1,%2,%3}, [%4];"
                 : "=r"(r[0]), "=r"(r[1]), "=r"(r[2]), "=r"(r[3]) : "r"(addr));
}
__device__ __forceinline__ void mma16816(float c[4], const uint32_t a[4], const uint32_t b[2]) {
    asm volatile(
        "mma.sync.aligned.m16n8k16.row.col.f32.f16.f16.f32 "
        "{%0,%1,%2,%3}, {%4,%5,%6,%7}, {%8,%9}, {%0,%1,%2,%3};"
        : "+f"(c[0]), "+f"(c[1]), "+f"(c[2]), "+f"(c[3])
        : "r"(a[0]), "r"(a[1]), "r"(a[2]), "r"(a[3]), "r"(b[0]), "r"(b[1]));
}
__device__ __forceinline__ uint32_t packh2(float a, float b) {
    __half2 h = __floats2half2_rn(a, b);
    return *(uint32_t*)&h;
}

// ---------------------------------------------------------------------------
// fp32 -> fp16 round. 8 elements/thread.
// ---------------------------------------------------------------------------
__global__ void conv_f16(const float* __restrict__ x, __half* __restrict__ y, int n8)
{
    int i = blockIdx.x * blockDim.x + threadIdx.x;
    if (i >= n8) return;
    const float4* xp = (const float4*)x + (size_t)i * 2;
    float4 a = xp[0], b = xp[1];
    float v[8] = {a.x, a.y, a.z, a.w, b.x, b.y, b.z, b.w};
    __half h[8];
#pragma unroll
    for (int j = 0; j < 8; j++) h[j] = __float2half_rn(v[j]);
    *((uint4*)y + i) = *(const uint4*)h;
}

// ---------------------------------------------------------------------------
// HMMA fp16 GEMM (single term): C[M,N] = A[M,K] @ B[N,K]^T, fp32 accum.
// CTA tile 128x128, BK=32, 4-stage cp.async, 8 warps (2x4), warp tile 64x32.
// 2 CTAs per SM.
// ---------------------------------------------------------------------------
#define BM 128
#define BN 128
#define BK 32
#define STAGES 4
#define PADK 40                        // halves per smem row (32 + 8 pad)
#define TILEA (128 * PADK * 2)         // 10240 B per [128][40] fp16 tile
#define STAGEB (2 * TILEA)             // A, B = 20480 B
#define GEMM_SMEM (STAGES * STAGEB)    // 81920 B

__global__ __launch_bounds__(256, 2)
void gemm_f16(const __half* __restrict__ Ah, const __half* __restrict__ Bh,
              float* __restrict__ C, int N, int K)
{
    extern __shared__ char smraw[];
    const uint32_t sbase = smem_u32(smraw);

    const int tid = threadIdx.x;
    const int wid = tid >> 5;
    const int lane = tid & 31;
    const int wm = wid >> 2;          // 0..1 (64 rows)
    const int wn = wid & 3;           // 0..3 (32 cols)
    const int m0 = blockIdx.y * BM;
    const int n0 = blockIdx.x * BN;
    const int NCH = K >> 5;

    auto load_chunk = [&](int c, int stg) {
        const uint32_t sb = sbase + stg * STAGEB;
        const int kc = c * BK;
#pragma unroll
        for (int i = 0; i < 2; i++) {
            int op = tid + i * 256;       // 0..511
            int row = op >> 2;
            int ck = op & 3;
            uint32_t soff = (uint32_t)(row * PADK * 2 + ck * 16);
            cp16(sb + soff, Ah + (size_t)(m0 + row) * K + kc + ck * 8);
            cp16(sb + TILEA + soff, Bh + (size_t)(n0 + row) * K + kc + ck * 8);
        }
        cp_commit();
    };

    float c[4][4][4];
#pragma unroll
    for (int i = 0; i < 4; i++)
#pragma unroll
        for (int j = 0; j < 4; j++)
#pragma unroll
            for (int q = 0; q < 4; q++) c[i][j][q] = 0.f;

    load_chunk(0, 0);
    load_chunk(1, 1);
    load_chunk(2, 2);

    const int a_row = (lane & 15);
    const int a_col = ((lane >> 4) & 1) * 8;
    const int b_row = (lane & 7) + ((lane & 16) ? 8 : 0);
    const int b_col = ((lane & 8) ? 8 : 0);

    for (int cch = 0; cch < NCH; cch++) {
        cp_wait<2>();
        __syncthreads();

        if (cch + 3 < NCH) load_chunk(cch + 3, (cch + 3) & 3);
        else cp_commit();

        const uint32_t sb = sbase + (cch & 3) * STAGEB;
        const uint32_t sA = sb;
        const uint32_t sB = sb + TILEA;

#pragma unroll
        for (int s = 0; s < 2; s++) {
            uint32_t af[16], bf[8];
#pragma unroll
            for (int i = 0; i < 4; i++) {
                int row = wm * 64 + i * 16 + a_row;
                uint32_t off = (uint32_t)((row * PADK + s * 16 + a_col) * 2);
                ldsm4(&af[i * 4], sA + off);
            }
#pragma unroll
            for (int j2 = 0; j2 < 2; j2++) {
                int row = wn * 32 + j2 * 16 + b_row;
                uint32_t off = (uint32_t)((row * PADK + s * 16 + b_col) * 2);
                ldsm4(&bf[j2 * 4], sB + off);
            }
#pragma unroll
            for (int i = 0; i < 4; i++)
#pragma unroll
                for (int j = 0; j < 4; j++)
                    mma16816(c[i][j], &af[i * 4], &bf[j * 2]);
        }
        __syncthreads();
    }

    const int g = lane >> 2;
    const int tq = lane & 3;
#pragma unroll
    for (int i = 0; i < 4; i++) {
        int row0 = m0 + wm * 64 + i * 16 + g;
#pragma unroll
        for (int j = 0; j < 4; j++) {
            int col = n0 + wn * 32 + j * 8 + tq * 2;
            float2 v0 = {c[i][j][0], c[i][j][1]};
            float2 v1 = {c[i][j][2], c[i][j][3]};
            *(float2*)&C[(size_t)row0 * N + col] = v0;
            *(float2*)&C[(size_t)(row0 + 8) * N + col] = v1;
        }
    }
}

// ---------------------------------------------------------------------------
// RoPE + head-major fp16 conversion (Q hi/lo, K rounded, V hi/lo).
// ---------------------------------------------------------------------------
__global__ void rope_split(const float* __restrict__ proj, const int* __restrict__ positions,
                           __half* __restrict__ Qh, __half* __restrict__ Ql,
                           __half* __restrict__ Kh,
                           __half* __restrict__ Vh, __half* __restrict__ Vl)
{
    int idx = blockIdx.x * blockDim.x + threadIdx.x;
    int i = idx & 63;
    int h = (idx >> 6) & 31;
    int t = idx >> 11;                 // token 0..4095
    int b = t >> 11;
    int s = t & 2047;

    int pos = positions[t];
    float inv = exp2f(-(float)i * (13.287712379549449f / 64.0f));
    float freq = (float)pos * inv;
    float sn, cs;
    sincosf(freq, &sn, &cs);

    const float scale = 0.08838834764831845f;  // 1/sqrt(128)

    size_t src = (size_t)t * PROJ3 + (size_t)h * HD + i;
    size_t dst = ((size_t)(b * NH + h) * S_SZ + s) * HD + i;

    {
        float x1 = proj[src], x2 = proj[src + 64];
        float r1 = (x1 * cs - x2 * sn) * scale;
        float r2 = (x2 * cs + x1 * sn) * scale;
        __half h1 = __float2half_rn(r1), h2 = __float2half_rn(r2);
        Qh[dst] = h1; Qh[dst + 64] = h2;
        Ql[dst] = __float2half_rn(r1 - __half2float(h1));
        Ql[dst + 64] = __float2half_rn(r2 - __half2float(h2));
    }
    {
        float x1 = proj[src + HID], x2 = proj[src + HID + 64];
        Kh[dst] = __float2half_rn(x1 * cs - x2 * sn);
        Kh[dst + 64] = __float2half_rn(x2 * cs + x1 * sn);
    }
    {
        float v1 = proj[src + 2 * HID], v2 = proj[src + 2 * HID + 64];
        __half h1 = __float2half_rn(v1), h2 = __float2half_rn(v2);
        Vh[dst] = h1; Vh[dst + 64] = h2;
        Vl[dst] = __float2half_rn(v1 - __half2float(h1));
        Vl[dst + 64] = __float2half_rn(v2 - __half2float(h2));
    }
}

// ---------------------------------------------------------------------------
// HMMA flash attention, causal. Br=128 (8 warps x 16 rows), Bc=64.
// S = (Qh+Ql) @ Kh^T ; O = P @ (Vh+Vl). Epilogue writes Xh (fp16 rounded).
// ---------------------------------------------------------------------------
#define ATT_PAD 136
#define KVROWB (ATT_PAD * 2)            // 272 bytes
#define KTILE (64 * KVROWB)             // 17408
#define ASTG (3 * KTILE)
#define ATT_SMEM (3 * ASTG)             // 156672

__global__ __launch_bounds__(256, 1)
void flash_attn_hmma(const __half* __restrict__ Qh, const __half* __restrict__ Ql,
                     const __half* __restrict__ Kh,
                     const __half* __restrict__ Vh, const __half* __restrict__ Vl,
                     __half* __restrict__ Xh)
{
    extern __shared__ char smraw[];
    const uint32_t sbase = smem_u32(smraw);

    const int tid = threadIdx.x;
    const int wid = tid >> 5;
    const int lane = tid & 31;
    const int g = lane >> 2;
    const int tq = lane & 3;

    const int qb = 15 - (int)blockIdx.x;
    const int bh = blockIdx.y;
    const int b = bh >> 5;
    const int h = bh & 31;
    const size_t hb = (size_t)bh * S_SZ * HD;
    const int row0 = qb * 128;
    const int wr = wid * 16;
    const int nkb = 2 * qb + 2;

    uint32_t qhf[8][4], qlf[8][4];
    {
        const __half* qsrc[2] = {Qh + hb + (size_t)row0 * HD, Ql + hb + (size_t)row0 * HD};
#pragma unroll
        for (int t2 = 0; t2 < 2; t2++) {
#pragma unroll
            for (int i = 0; i < 8; i++) {
                int op = tid + i * 256;
                int r = op >> 4;
                int ck = op & 15;
                cp16(sbase + (uint32_t)(r * KVROWB + ck * 16),
                     qsrc[t2] + (size_t)r * HD + ck * 8);
            }
            cp_commit();
            cp_wait<0>();
            __syncthreads();
#pragma unroll
            for (int ks = 0; ks < 8; ks++) {
                uint32_t off = (uint32_t)((wr + (lane & 15)) * KVROWB +
                                          (ks * 16 + ((lane >> 4) << 3)) * 2);
                ldsm4(t2 ? qlf[ks] : qhf[ks], sbase + off);
            }
            __syncthreads();
        }
    }

    float o[16][4];
#pragma unroll
    for (int j = 0; j < 16; j++)
#pragma unroll
        for (int q = 0; q < 4; q++) o[j][q] = 0.f;
    float m_old0 = -1e30f, m_old1 = -1e30f, l0 = 0.f, l1 = 0.f;

    auto kvload = [&](int kb, int stg) {
        const uint32_t sb = sbase + stg * ASTG;
        const size_t src0 = hb + (size_t)kb * 64 * HD;
#pragma unroll
        for (int i = 0; i < 4; i++) {
            int op = tid + i * 256;
            int r = op >> 4;
            int ck = op & 15;
            uint32_t soff = (uint32_t)(r * KVROWB + ck * 16);
            size_t goff = src0 + (size_t)r * HD + ck * 8;
            cp16(sb + soff, Kh + goff);
            cp16(sb + KTILE + soff, Vh + goff);
            cp16(sb + 2 * KTILE + soff, Vl + goff);
        }
        cp_commit();
    };

    kvload(0, 0);
    kvload(1, 1);

    const int r_g = row0 + wr + g;

    for (int kb = 0; kb < nkb; kb++) {
        cp_wait<1>();
        __syncthreads();
        if (kb + 2 < nkb) kvload(kb + 2, (kb + 2) % 3);
        else cp_commit();

        const uint32_t sK = sbase + (kb % 3) * ASTG;
        const uint32_t sVh = sK + KTILE;
        const uint32_t sVl = sK + 2 * KTILE;

        float s[8][4];
#pragma unroll
        for (int j = 0; j < 8; j++)
#pragma unroll
            for (int q = 0; q < 4; q++) s[j][q] = 0.f;

#pragma unroll
        for (int ks = 0; ks < 8; ks++) {
            uint32_t bk[16];
#pragma unroll
            for (int j2 = 0; j2 < 4; j2++) {
                int r = j2 * 16 + (lane & 7) + ((lane & 16) ? 8 : 0);
                uint32_t off = (uint32_t)(r * KVROWB + (ks * 16 + ((lane & 8) ? 8 : 0)) * 2);
                ldsm4(&bk[j2 * 4], sK + off);
            }
#pragma unroll
            for (int j = 0; j < 8; j++) mma16816(s[j], qhf[ks], &bk[j * 2]);
#pragma unroll
            for (int j = 0; j < 8; j++) mma16816(s[j], qlf[ks], &bk[j * 2]);
        }

        const int kv0 = kb * 64;
        if (kv0 + 63 > row0 + wr) {
#pragma unroll
            for (int j = 0; j < 8; j++) {
                int cc = kv0 + j * 8 + 2 * tq;
                if (cc > r_g) s[j][0] = -1e30f;
                if (cc + 1 > r_g) s[j][1] = -1e30f;
                if (cc > r_g + 8) s[j][2] = -1e30f;
                if (cc + 1 > r_g + 8) s[j][3] = -1e30f;
            }
        }

        float mx0 = -1e30f, mx1 = -1e30f;
#pragma unroll
        for (int j = 0; j < 8; j++) {
            mx0 = fmaxf(mx0, fmaxf(s[j][0], s[j][1]));
            mx1 = fmaxf(mx1, fmaxf(s[j][2], s[j][3]));
        }
        mx0 = fmaxf(mx0, __shfl_xor_sync(0xffffffffu, mx0, 1));
        mx0 = fmaxf(mx0, __shfl_xor_sync(0xffffffffu, mx0, 2));
        mx1 = fmaxf(mx1, __shfl_xor_sync(0xffffffffu, mx1, 1));
        mx1 = fmaxf(mx1, __shfl_xor_sync(0xffffffffu, mx1, 2));

        float mn0 = fmaxf(m_old0, mx0);
        float mn1 = fmaxf(m_old1, mx1);
        float a0 = __expf(m_old0 - mn0);
        float a1 = __expf(m_old1 - mn1);

        float sum0 = 0.f, sum1 = 0.f;
        uint32_t pa[4][4];
#pragma unroll
        for (int ks = 0; ks < 4; ks++) {
            float p00 = __expf(s[2 * ks][0] - mn0);
            float p01 = __expf(s[2 * ks][1] - mn0);
            float p02 = __expf(s[2 * ks][2] - mn1);
            float p03 = __expf(s[2 * ks][3] - mn1);
            float p10 = __expf(s[2 * ks + 1][0] - mn0);
            float p11 = __expf(s[2 * ks + 1][1] - mn0);
            float p12 = __expf(s[2 * ks + 1][2] - mn1);
            float p13 = __expf(s[2 * ks + 1][3] - mn1);
            sum0 += p00 + p01 + p10 + p11;
            sum1 += p02 + p03 + p12 + p13;
            pa[ks][0] = packh2(p00, p01);
            pa[ks][1] = packh2(p02, p03);
            pa[ks][2] = packh2(p10, p11);
            pa[ks][3] = packh2(p12, p13);
        }
        sum0 += __shfl_xor_sync(0xffffffffu, sum0, 1);
        sum0 += __shfl_xor_sync(0xffffffffu, sum0, 2);
        sum1 += __shfl_xor_sync(0xffffffffu, sum1, 1);
        sum1 += __shfl_xor_sync(0xffffffffu, sum1, 2);

        l0 = l0 * a0 + sum0;
        l1 = l1 * a1 + sum1;
        m_old0 = mn0;
        m_old1 = mn1;

#pragma unroll
        for (int j = 0; j < 16; j++) {
            o[j][0] *= a0; o[j][1] *= a0;
            o[j][2] *= a1; o[j][3] *= a1;
        }

#pragma unroll
        for (int ks = 0; ks < 4; ks++) {
#pragma unroll
            for (int jj = 0; jj < 8; jj++) {
                int krow = ks * 16 + (lane & 15);
                uint32_t off = (uint32_t)(krow * KVROWB + (jj * 16 + ((lane & 16) ? 8 : 0)) * 2);
                uint32_t bv[4];
                ldsm4t(bv, sVh + off);
                mma16816(o[jj * 2], pa[ks], &bv[0]);
                mma16816(o[jj * 2 + 1], pa[ks], &bv[2]);
                ldsm4t(bv, sVl + off);
                mma16816(o[jj * 2], pa[ks], &bv[0]);
                mma16816(o[jj * 2 + 1], pa[ks], &bv[2]);
            }
        }
    }

    const float il0 = 1.f / l0;
    const float il1 = 1.f / l1;
    const int tok0 = b * S_SZ + row0 + wr;
#pragma unroll
    for (int j = 0; j < 16; j++) {
        int col = h * HD + j * 8 + 2 * tq;
        size_t i0 = (size_t)(tok0 + g) * HID + col;
        size_t i1 = (size_t)(tok0 + g + 8) * HID + col;
        *(uint32_t*)&Xh[i0] = packh2(o[j][0] * il0, o[j][1] * il0);
        *(uint32_t*)&Xh[i1] = packh2(o[j][2] * il1, o[j][3] * il1);
    }
}

// ---------------------------------------------------------------------------
// Launch
// ---------------------------------------------------------------------------
extern "C" void kernel_launch(void* const* d_in, const int* in_sizes, int n_in,
                              void* d_out, int out_size)
{
    const float* hidden = (const float*)d_in[0];
    const int* positions = (const int*)d_in[1];
    const float* W_pack = (const float*)d_in[2];
    const float* W_o = (const float*)d_in[3];
    float* out = (float*)d_out;

    void* pp; cudaGetSymbolAddress(&pp, g_proj);
    float* proj = (float*)pp;

    void* v_ah; cudaGetSymbolAddress(&v_ah, g_Ah);
    void* v_wp; cudaGetSymbolAddress(&v_wp, g_Wp);
    void* v_wo; cudaGetSymbolAddress(&v_wo, g_Wo);
    void* v_xh; cudaGetSymbolAddress(&v_xh, g_Xh);
    void* v_qh; cudaGetSymbolAddress(&v_qh, g_Qh);
    void* v_ql; cudaGetSymbolAddress(&v_ql, g_Ql);
    void* v_kh; cudaGetSymbolAddress(&v_kh, g_Kh);
    void* v_vh; cudaGetSymbolAddress(&v_vh, g_Vh);
    void* v_vl; cudaGetSymbolAddress(&v_vl, g_Vl);

    cudaFuncSetAttribute(gemm_f16, cudaFuncAttributeMaxDynamicSharedMemorySize, GEMM_SMEM);
    cudaFuncSetAttribute(flash_attn_hmma, cudaFuncAttributeMaxDynamicSharedMemorySize, ATT_SMEM);

    // 0) operand prep: everything rounded to fp16 once
    {
        int n8 = TOK * HID / 8;
        conv_f16<<<(n8 + 255) / 256, 256>>>(hidden, (__half*)v_ah, n8);
        int w8 = PROJ3 * HID / 8;
        conv_f16<<<(w8 + 255) / 256, 256>>>(W_pack, (__half*)v_wp, w8);
        int o8 = HID * HID / 8;
        conv_f16<<<(o8 + 255) / 256, 256>>>(W_o, (__half*)v_wo, o8);
    }

    // 1) QKV projection: proj = hidden @ W_pack^T
    {
        dim3 grid(PROJ3 / BN, TOK / BM);  // 96 x 32
        gemm_f16<<<grid, 256, GEMM_SMEM>>>((const __half*)v_ah, (const __half*)v_wp,
                                           proj, PROJ3, HID);
    }

    // 2) RoPE + fp16 conversion to head-major layout
    {
        int total = TOK * NH * 64;
        rope_split<<<total / 256, 256>>>(proj, positions,
                                         (__half*)v_qh, (__half*)v_ql, (__half*)v_kh,
                                         (__half*)v_vh, (__half*)v_vl);
    }

    // 3) Causal attention on tensor cores; writes Xh directly
    {
        dim3 grid(S_SZ / 128, B_SZ * NH);  // 16 x 64
        flash_attn_hmma<<<grid, 256, ATT_SMEM>>>((const __half*)v_qh, (const __half*)v_ql,
                                                 (const __half*)v_kh,
                                                 (const __half*)v_vh, (const __half*)v_vl,
                                                 (__half*)v_xh);
    }

    // 4) out = attn @ W_o^T
    {
        dim3 grid(HID / BN, TOK / BM);  // 32 x 32
        gemm_f16<<<grid, 256, GEMM_SMEM>>>((const __half*)v_xh, (const __half*)v_wo,
                                           out, HID, HID);
    }
}

// round 8
// speedup vs baseline: 8.0898x; 1.1837x over previous
#include <cuda_runtime.h>
#include <cuda_fp16.h>
#include <math.h>
#include <stdint.h>

// Problem constants
#define B_SZ 2
#define S_SZ 2048
#define HID 4096
#define NH 32
#define HD 128
#define TOK (B_SZ * S_SZ)          // 4096 tokens
#define PROJ3 (3 * HID)            // 12288

// Scratch (static device globals — allocation-free rule)
__device__ float g_proj[(size_t)TOK * PROJ3];   // [4096, 12288] q|k|v (fp32)
__device__ __half g_Ah[(size_t)TOK * HID];
__device__ __half g_Wp[(size_t)PROJ3 * HID];
__device__ __half g_Wo[(size_t)HID * HID];
__device__ __half g_Xh[(size_t)TOK * HID];
// head-major fp16 attention operands [b*NH+h][s][d]
__device__ __half g_Qh[(size_t)TOK * HID];
__device__ __half g_Ql[(size_t)TOK * HID];
__device__ __half g_Kh[(size_t)TOK * HID];
__device__ __half g_Vh[(size_t)TOK * HID];

// ---------------------------------------------------------------------------
// Inline PTX helpers
// ---------------------------------------------------------------------------
__device__ __forceinline__ uint32_t smem_u32(const void* p) {
    uint32_t a;
    asm("{ .reg .u64 t; cvta.to.shared.u64 t, %1; cvt.u32.u64 %0, t; }" : "=r"(a) : "l"(p));
    return a;
}
__device__ __forceinline__ void cp16(uint32_t dst, const void* src) {
    asm volatile("cp.async.cg.shared.global [%0], [%1], 16;" :: "r"(dst), "l"(src) : "memory");
}
__device__ __forceinline__ void cp_commit() { asm volatile("cp.async.commit_group;" ::: "memory"); }
template <int N>
__device__ __forceinline__ void cp_wait() {
    asm volatile("cp.async.wait_group %0;" :: "n"(N) : "memory");
}
__device__ __forceinline__ void ldsm4(uint32_t r[4], uint32_t addr) {
    asm volatile("ldmatrix.sync.aligned.m8n8.x4.shared.b16 {%0,%1,%2,%3}, [%4];"
                 : "=r"(r[0]), "=r"(r[1]), "=r"(r[2]), "=r"(r[3]) : "r"(addr));
}
__device__ __forceinline__ void ldsm4t(uint32_t r[4], uint32_t addr) {
    asm volatile("ldmatrix.sync.aligned.m8n8.x4.trans.shared.b16 {%0,%1,%2,%3}, [%4];"
                 : "=r"(r[0]), "=r"(r[1]), "=r"(r[2]), "=r"(r[3]) : "r"(addr));
}
__device__ __forceinline__ void mma16816(float c[4], const uint32_t a[4], const uint32_t b[2]) {
    asm volatile(
        "mma.sync.aligned.m16n8k16.row.col.f32.f16.f16.f32 "
        "{%0,%1,%2,%3}, {%4,%5,%6,%7}, {%8,%9}, {%0,%1,%2,%3};"
        : "+f"(c[0]), "+f"(c[1]), "+f"(c[2]), "+f"(c[3])
        : "r"(a[0]), "r"(a[1]), "r"(a[2]), "r"(a[3]), "r"(b[0]), "r"(b[1]));
}
__device__ __forceinline__ uint32_t packh2(float a, float b) {
    __half2 h = __floats2half2_rn(a, b);
    return *(uint32_t*)&h;
}

// ---------------------------------------------------------------------------
// fp32 -> fp16 round. 8 elements/thread.
// ---------------------------------------------------------------------------
__global__ void conv_f16(const float* __restrict__ x, __half* __restrict__ y, int n8)
{
    int i = blockIdx.x * blockDim.x + threadIdx.x;
    if (i >= n8) return;
    const float4* xp = (const float4*)x + (size_t)i * 2;
    float4 a = xp[0], b = xp[1];
    float v[8] = {a.x, a.y, a.z, a.w, b.x, b.y, b.z, b.w};
    __half h[8];
#pragma unroll
    for (int j = 0; j < 8; j++) h[j] = __float2half_rn(v[j]);
    *((uint4*)y + i) = *(const uint4*)h;
}

// ---------------------------------------------------------------------------
// HMMA fp16 GEMM: C[M,N] = A[M,K] @ B[N,K]^T, fp32 accum.
// CTA tile 128x128, BK=64, 3-stage cp.async, 8 warps (2x4), warp tile 64x32.
// 2 CTAs per SM. One barrier per chunk.
// ---------------------------------------------------------------------------
#define BM 128
#define BN 128
#define BK 64
#define STAGES 3
#define PADK 72                        // halves per smem row (64 + 8 pad)
#define TILEA (128 * PADK * 2)         // 18432 B
#define STAGEB (2 * TILEA)             // 36864 B
#define GEMM_SMEM (STAGES * STAGEB)    // 110592 B

__global__ __launch_bounds__(256, 2)
void gemm_f16(const __half* __restrict__ Ah, const __half* __restrict__ Bh,
              float* __restrict__ C, int N, int K)
{
    extern __shared__ char smraw[];
    const uint32_t sbase = smem_u32(smraw);

    const int tid = threadIdx.x;
    const int wid = tid >> 5;
    const int lane = tid & 31;
    const int wm = wid >> 2;          // 0..1 (64 rows)
    const int wn = wid & 3;           // 0..3 (32 cols)
    const int m0 = blockIdx.y * BM;
    const int n0 = blockIdx.x * BN;
    const int NCH = K >> 6;

    auto load_chunk = [&](int c, int stg) {
        const uint32_t sb = sbase + stg * STAGEB;
        const int kc = c * BK;
#pragma unroll
        for (int i = 0; i < 4; i++) {
            int op = tid + i * 256;       // 0..1023
            int row = op >> 3;            // 0..127
            int ck = op & 7;              // 16B chunk in 128B row
            uint32_t soff = (uint32_t)(row * PADK * 2 + ck * 16);
            cp16(sb + soff, Ah + (size_t)(m0 + row) * K + kc + ck * 8);
            cp16(sb + TILEA + soff, Bh + (size_t)(n0 + row) * K + kc + ck * 8);
        }
        cp_commit();
    };

    float c[4][4][4];
#pragma unroll
    for (int i = 0; i < 4; i++)
#pragma unroll
        for (int j = 0; j < 4; j++)
#pragma unroll
            for (int q = 0; q < 4; q++) c[i][j][q] = 0.f;

    load_chunk(0, 0);
    load_chunk(1, 1);

    const int a_row = (lane & 15);
    const int a_col = ((lane >> 4) & 1) * 8;
    const int b_row = (lane & 7) + ((lane & 16) ? 8 : 0);
    const int b_col = ((lane & 8) ? 8 : 0);

    for (int cch = 0; cch < NCH; cch++) {
        cp_wait<1>();
        __syncthreads();
        // Stage (cch%3) is being read this iteration; its refill (chunk cch+3)
        // is issued only after next iteration's barrier, so no trailing sync.
        if (cch + 2 < NCH) load_chunk(cch + 2, (cch + 2) % 3);
        else cp_commit();

        const uint32_t sb = sbase + (cch % 3) * STAGEB;
        const uint32_t sA = sb;
        const uint32_t sB = sb + TILEA;

#pragma unroll
        for (int s = 0; s < 4; s++) {
            uint32_t af[16], bf[8];
#pragma unroll
            for (int i = 0; i < 4; i++) {
                int row = wm * 64 + i * 16 + a_row;
                uint32_t off = (uint32_t)((row * PADK + s * 16 + a_col) * 2);
                ldsm4(&af[i * 4], sA + off);
            }
#pragma unroll
            for (int j2 = 0; j2 < 2; j2++) {
                int row = wn * 32 + j2 * 16 + b_row;
                uint32_t off = (uint32_t)((row * PADK + s * 16 + b_col) * 2);
                ldsm4(&bf[j2 * 4], sB + off);
            }
#pragma unroll
            for (int i = 0; i < 4; i++)
#pragma unroll
                for (int j = 0; j < 4; j++)
                    mma16816(c[i][j], &af[i * 4], &bf[j * 2]);
        }
        __syncthreads();
    }

    const int g = lane >> 2;
    const int tq = lane & 3;
#pragma unroll
    for (int i = 0; i < 4; i++) {
        int row0 = m0 + wm * 64 + i * 16 + g;
#pragma unroll
        for (int j = 0; j < 4; j++) {
            int col = n0 + wn * 32 + j * 8 + tq * 2;
            float2 v0 = {c[i][j][0], c[i][j][1]};
            float2 v1 = {c[i][j][2], c[i][j][3]};
            *(float2*)&C[(size_t)row0 * N + col] = v0;
            *(float2*)&C[(size_t)(row0 + 8) * N + col] = v1;
        }
    }
}

// ---------------------------------------------------------------------------
// RoPE + head-major fp16 conversion (Q hi/lo, K rounded, V rounded).
// ---------------------------------------------------------------------------
__global__ void rope_split(const float* __restrict__ proj, const int* __restrict__ positions,
                           __half* __restrict__ Qh, __half* __restrict__ Ql,
                           __half* __restrict__ Kh, __half* __restrict__ Vh)
{
    int idx = blockIdx.x * blockDim.x + threadIdx.x;
    int i = idx & 63;
    int h = (idx >> 6) & 31;
    int t = idx >> 11;                 // token 0..4095
    int b = t >> 11;
    int s = t & 2047;

    int pos = positions[t];
    float inv = exp2f(-(float)i * (13.287712379549449f / 64.0f));
    float freq = (float)pos * inv;
    float sn, cs;
    sincosf(freq, &sn, &cs);

    const float scale = 0.08838834764831845f;  // 1/sqrt(128)

    size_t src = (size_t)t * PROJ3 + (size_t)h * HD + i;
    size_t dst = ((size_t)(b * NH + h) * S_SZ + s) * HD + i;

    {
        float x1 = proj[src], x2 = proj[src + 64];
        float r1 = (x1 * cs - x2 * sn) * scale;
        float r2 = (x2 * cs + x1 * sn) * scale;
        __half h1 = __float2half_rn(r1), h2 = __float2half_rn(r2);
        Qh[dst] = h1; Qh[dst + 64] = h2;
        Ql[dst] = __float2half_rn(r1 - __half2float(h1));
        Ql[dst + 64] = __float2half_rn(r2 - __half2float(h2));
    }
    {
        float x1 = proj[src + HID], x2 = proj[src + HID + 64];
        Kh[dst] = __float2half_rn(x1 * cs - x2 * sn);
        Kh[dst + 64] = __float2half_rn(x2 * cs + x1 * sn);
    }
    {
        Vh[dst] = __float2half_rn(proj[src + 2 * HID]);
        Vh[dst + 64] = __float2half_rn(proj[src + 2 * HID + 64]);
    }
}

// ---------------------------------------------------------------------------
// HMMA flash attention, causal. Br=128 (8 warps x 16 rows), Bc=64.
// S = (Qh+Ql) @ Kh^T ; O = P @ Vh. Epilogue writes Xh (fp16 rounded).
// ---------------------------------------------------------------------------
#define ATT_PAD 136
#define KVROWB (ATT_PAD * 2)            // 272 bytes
#define KTILE (64 * KVROWB)             // 17408
#define ASTG (2 * KTILE)                // K, V
#define ATT_SMEM (3 * ASTG)             // 104448

__global__ __launch_bounds__(256, 1)
void flash_attn_hmma(const __half* __restrict__ Qh, const __half* __restrict__ Ql,
                     const __half* __restrict__ Kh, const __half* __restrict__ Vh,
                     __half* __restrict__ Xh)
{
    extern __shared__ char smraw[];
    const uint32_t sbase = smem_u32(smraw);

    const int tid = threadIdx.x;
    const int wid = tid >> 5;
    const int lane = tid & 31;
    const int g = lane >> 2;
    const int tq = lane & 3;

    const int qb = 15 - (int)blockIdx.x;
    const int bh = blockIdx.y;
    const int b = bh >> 5;
    const int h = bh & 31;
    const size_t hb = (size_t)bh * S_SZ * HD;
    const int row0 = qb * 128;
    const int wr = wid * 16;
    const int nkb = 2 * qb + 2;

    uint32_t qhf[8][4], qlf[8][4];
    {
        const __half* qsrc[2] = {Qh + hb + (size_t)row0 * HD, Ql + hb + (size_t)row0 * HD};
#pragma unroll
        for (int t2 = 0; t2 < 2; t2++) {
#pragma unroll
            for (int i = 0; i < 8; i++) {
                int op = tid + i * 256;
                int r = op >> 4;
                int ck = op & 15;
                cp16(sbase + (uint32_t)(r * KVROWB + ck * 16),
                     qsrc[t2] + (size_t)r * HD + ck * 8);
            }
            cp_commit();
            cp_wait<0>();
            __syncthreads();
#pragma unroll
            for (int ks = 0; ks < 8; ks++) {
                uint32_t off = (uint32_t)((wr + (lane & 15)) * KVROWB +
                                          (ks * 16 + ((lane >> 4) << 3)) * 2);
                ldsm4(t2 ? qlf[ks] : qhf[ks], sbase + off);
            }
            __syncthreads();
        }
    }

    float o[16][4];
#pragma unroll
    for (int j = 0; j < 16; j++)
#pragma unroll
        for (int q = 0; q < 4; q++) o[j][q] = 0.f;
    float m_old0 = -1e30f, m_old1 = -1e30f, l0 = 0.f, l1 = 0.f;

    auto kvload = [&](int kb, int stg) {
        const uint32_t sb = sbase + stg * ASTG;
        const size_t src0 = hb + (size_t)kb * 64 * HD;
#pragma unroll
        for (int i = 0; i < 4; i++) {
            int op = tid + i * 256;
            int r = op >> 4;
            int ck = op & 15;
            uint32_t soff = (uint32_t)(r * KVROWB + ck * 16);
            size_t goff = src0 + (size_t)r * HD + ck * 8;
            cp16(sb + soff, Kh + goff);
            cp16(sb + KTILE + soff, Vh + goff);
        }
        cp_commit();
    };

    kvload(0, 0);
    kvload(1, 1);

    const int r_g = row0 + wr + g;

    for (int kb = 0; kb < nkb; kb++) {
        cp_wait<1>();
        __syncthreads();
        if (kb + 2 < nkb) kvload(kb + 2, (kb + 2) % 3);
        else cp_commit();

        const uint32_t sK = sbase + (kb % 3) * ASTG;
        const uint32_t sV = sK + KTILE;

        float s[8][4];
#pragma unroll
        for (int j = 0; j < 8; j++)
#pragma unroll
            for (int q = 0; q < 4; q++) s[j][q] = 0.f;

#pragma unroll
        for (int ks = 0; ks < 8; ks++) {
            uint32_t bk[16];
#pragma unroll
            for (int j2 = 0; j2 < 4; j2++) {
                int r = j2 * 16 + (lane & 7) + ((lane & 16) ? 8 : 0);
                uint32_t off = (uint32_t)(r * KVROWB + (ks * 16 + ((lane & 8) ? 8 : 0)) * 2);
                ldsm4(&bk[j2 * 4], sK + off);
            }
#pragma unroll
            for (int j = 0; j < 8; j++) mma16816(s[j], qhf[ks], &bk[j * 2]);
#pragma unroll
            for (int j = 0; j < 8; j++) mma16816(s[j], qlf[ks], &bk[j * 2]);
        }

        const int kv0 = kb * 64;
        if (kv0 + 63 > row0 + wr) {
#pragma unroll
            for (int j = 0; j < 8; j++) {
                int cc = kv0 + j * 8 + 2 * tq;
                if (cc > r_g) s[j][0] = -1e30f;
                if (cc + 1 > r_g) s[j][1] = -1e30f;
                if (cc > r_g + 8) s[j][2] = -1e30f;
                if (cc + 1 > r_g + 8) s[j][3] = -1e30f;
            }
        }

        float mx0 = -1e30f, mx1 = -1e30f;
#pragma unroll
        for (int j = 0; j < 8; j++) {
            mx0 = fmaxf(mx0, fmaxf(s[j][0], s[j][1]));
            mx1 = fmaxf(mx1, fmaxf(s[j][2], s[j][3]));
        }
        mx0 = fmaxf(mx0, __shfl_xor_sync(0xffffffffu, mx0, 1));
        mx0 = fmaxf(mx0, __shfl_xor_sync(0xffffffffu, mx0, 2));
        mx1 = fmaxf(mx1, __shfl_xor_sync(0xffffffffu, mx1, 1));
        mx1 = fmaxf(mx1, __shfl_xor_sync(0xffffffffu, mx1, 2));

        float mn0 = fmaxf(m_old0, mx0);
        float mn1 = fmaxf(m_old1, mx1);
        float a0 = __expf(m_old0 - mn0);
        float a1 = __expf(m_old1 - mn1);

        float sum0 = 0.f, sum1 = 0.f;
        uint32_t pa[4][4];
#pragma unroll
        for (int ks = 0; ks < 4; ks++) {
            float p00 = __expf(s[2 * ks][0] - mn0);
            float p01 = __expf(s[2 * ks][1] - mn0);
            float p02 = __expf(s[2 * ks][2] - mn1);
            float p03 = __expf(s[2 * ks][3] - mn1);
            float p10 = __expf(s[2 * ks + 1][0] - mn0);
            float p11 = __expf(s[2 * ks + 1][1] - mn0);
            float p12 = __expf(s[2 * ks + 1][2] - mn1);
            float p13 = __expf(s[2 * ks + 1][3] - mn1);
            sum0 += p00 + p01 + p10 + p11;
            sum1 += p02 + p03 + p12 + p13;
            pa[ks][0] = packh2(p00, p01);
            pa[ks][1] = packh2(p02, p03);
            pa[ks][2] = packh2(p10, p11);
            pa[ks][3] = packh2(p12, p13);
        }
        sum0 += __shfl_xor_sync(0xffffffffu, sum0, 1);
        sum0 += __shfl_xor_sync(0xffffffffu, sum0, 2);
        sum1 += __shfl_xor_sync(0xffffffffu, sum1, 1);
        sum1 += __shfl_xor_sync(0xffffffffu, sum1, 2);

        l0 = l0 * a0 + sum0;
        l1 = l1 * a1 + sum1;
        m_old0 = mn0;
        m_old1 = mn1;

#pragma unroll
        for (int j = 0; j < 16; j++) {
            o[j][0] *= a0; o[j][1] *= a0;
            o[j][2] *= a1; o[j][3] *= a1;
        }

#pragma unroll
        for (int ks = 0; ks < 4; ks++) {
#pragma unroll
            for (int jj = 0; jj < 8; jj++) {
                int krow = ks * 16 + (lane & 15);
                uint32_t off = (uint32_t)(krow * KVROWB + (jj * 16 + ((lane & 16) ? 8 : 0)) * 2);
                uint32_t bv[4];
                ldsm4t(bv, sV + off);
                mma16816(o[jj * 2], pa[ks], &bv[0]);
                mma16816(o[jj * 2 + 1], pa[ks], &bv[2]);
            }
        }
    }

    const float il0 = 1.f / l0;
    const float il1 = 1.f / l1;
    const int tok0 = b * S_SZ + row0 + wr;
#pragma unroll
    for (int j = 0; j < 16; j++) {
        int col = h * HD + j * 8 + 2 * tq;
        size_t i0 = (size_t)(tok0 + g) * HID + col;
        size_t i1 = (size_t)(tok0 + g + 8) * HID + col;
        *(uint32_t*)&Xh[i0] = packh2(o[j][0] * il0, o[j][1] * il0);
        *(uint32_t*)&Xh[i1] = packh2(o[j][2] * il1, o[j][3] * il1);
    }
}

// ---------------------------------------------------------------------------
// Launch
// ---------------------------------------------------------------------------
extern "C" void kernel_launch(void* const* d_in, const int* in_sizes, int n_in,
                              void* d_out, int out_size)
{
    const float* hidden = (const float*)d_in[0];
    const int* positions = (const int*)d_in[1];
    const float* W_pack = (const float*)d_in[2];
    const float* W_o = (const float*)d_in[3];
    float* out = (float*)d_out;

    void* pp; cudaGetSymbolAddress(&pp, g_proj);
    float* proj = (float*)pp;

    void* v_ah; cudaGetSymbolAddress(&v_ah, g_Ah);
    void* v_wp; cudaGetSymbolAddress(&v_wp, g_Wp);
    void* v_wo; cudaGetSymbolAddress(&v_wo, g_Wo);
    void* v_xh; cudaGetSymbolAddress(&v_xh, g_Xh);
    void* v_qh; cudaGetSymbolAddress(&v_qh, g_Qh);
    void* v_ql; cudaGetSymbolAddress(&v_ql, g_Ql);
    void* v_kh; cudaGetSymbolAddress(&v_kh, g_Kh);
    void* v_vh; cudaGetSymbolAddress(&v_vh, g_Vh);

    cudaFuncSetAttribute(gemm_f16, cudaFuncAttributeMaxDynamicSharedMemorySize, GEMM_SMEM);
    cudaFuncSetAttribute(flash_attn_hmma, cudaFuncAttributeMaxDynamicSharedMemorySize, ATT_SMEM);

    // 0) operand prep
    {
        int n8 = TOK * HID / 8;
        conv_f16<<<(n8 + 255) / 256, 256>>>(hidden, (__half*)v_ah, n8);
        int w8 = PROJ3 * HID / 8;
        conv_f16<<<(w8 + 255) / 256, 256>>>(W_pack, (__half*)v_wp, w8);
        int o8 = HID * HID / 8;
        conv_f16<<<(o8 + 255) / 256, 256>>>(W_o, (__half*)v_wo, o8);
    }

    // 1) QKV projection: proj = hidden @ W_pack^T
    {
        dim3 grid(PROJ3 / BN, TOK / BM);  // 96 x 32
        gemm_f16<<<grid, 256, GEMM_SMEM>>>((const __half*)v_ah, (const __half*)v_wp,
                                           proj, PROJ3, HID);
    }

    // 2) RoPE + fp16 conversion to head-major layout
    {
        int total = TOK * NH * 64;
        rope_split<<<total / 256, 256>>>(proj, positions,
                                         (__half*)v_qh, (__half*)v_ql,
                                         (__half*)v_kh, (__half*)v_vh);
    }

    // 3) Causal attention on tensor cores; writes Xh directly
    {
        dim3 grid(S_SZ / 128, B_SZ * NH);  // 16 x 64
        flash_attn_hmma<<<grid, 256, ATT_SMEM>>>((const __half*)v_qh, (const __half*)v_ql,
                                                 (const __half*)v_kh, (const __half*)v_vh,
                                                 (__half*)v_xh);
    }

    // 4) out = attn @ W_o^T
    {
        dim3 grid(HID / BN, TOK / BM);  // 32 x 32
        gemm_f16<<<grid, 256, GEMM_SMEM>>>((const __half*)v_xh, (const __half*)v_wo,
                                           out, HID, HID);
    }
}

// round 9
// speedup vs baseline: 8.1182x; 1.0035x over previous
#include <cuda_runtime.h>
#include <cuda_fp16.h>
#include <math.h>
#include <stdint.h>

// Problem constants
#define B_SZ 2
#define S_SZ 2048
#define HID 4096
#define NH 32
#define HD 128
#define TOK (B_SZ * S_SZ)          // 4096 tokens
#define PROJ3 (3 * HID)            // 12288

// Scratch (static device globals — allocation-free rule)
__device__ float g_proj[(size_t)TOK * PROJ3];   // [4096, 12288] q|k|v (fp32)
__device__ __half g_Ah[(size_t)TOK * HID];
__device__ __half g_Wp[(size_t)PROJ3 * HID];
__device__ __half g_Wo[(size_t)HID * HID];
__device__ __half g_Xh[(size_t)TOK * HID];
// head-major fp16 attention operands [b*NH+h][s][d]
__device__ __half g_Qh[(size_t)TOK * HID];
__device__ __half g_Kh[(size_t)TOK * HID];
__device__ __half g_Vh[(size_t)TOK * HID];

// ---------------------------------------------------------------------------
// Inline PTX helpers
// ---------------------------------------------------------------------------
__device__ __forceinline__ uint32_t smem_u32(const void* p) {
    uint32_t a;
    asm("{ .reg .u64 t; cvta.to.shared.u64 t, %1; cvt.u32.u64 %0, t; }" : "=r"(a) : "l"(p));
    return a;
}
__device__ __forceinline__ void cp16(uint32_t dst, const void* src) {
    asm volatile("cp.async.cg.shared.global [%0], [%1], 16;" :: "r"(dst), "l"(src) : "memory");
}
__device__ __forceinline__ void cp_commit() { asm volatile("cp.async.commit_group;" ::: "memory"); }
template <int N>
__device__ __forceinline__ void cp_wait() {
    asm volatile("cp.async.wait_group %0;" :: "n"(N) : "memory");
}
__device__ __forceinline__ void ldsm4(uint32_t r[4], uint32_t addr) {
    asm volatile("ldmatrix.sync.aligned.m8n8.x4.shared.b16 {%0,%1,%2,%3}, [%4];"
                 : "=r"(r[0]), "=r"(r[1]), "=r"(r[2]), "=r"(r[3]) : "r"(addr));
}
__device__ __forceinline__ void ldsm4t(uint32_t r[4], uint32_t addr) {
    asm volatile("ldmatrix.sync.aligned.m8n8.x4.trans.shared.b16 {%0,%1,%2,%3}, [%4];"
                 : "=r"(r[0]), "=r"(r[1]), "=r"(r[2]), "=r"(r[3]) : "r"(addr));
}
__device__ __forceinline__ void mma16816(float c[4], const uint32_t a[4], const uint32_t b[2]) {
    asm volatile(
        "mma.sync.aligned.m16n8k16.row.col.f32.f16.f16.f32 "
        "{%0,%1,%2,%3}, {%4,%5,%6,%7}, {%8,%9}, {%0,%1,%2,%3};"
        : "+f"(c[0]), "+f"(c[1]), "+f"(c[2]), "+f"(c[3])
        : "r"(a[0]), "r"(a[1]), "r"(a[2]), "r"(a[3]), "r"(b[0]), "r"(b[1]));
}
__device__ __forceinline__ uint32_t packh2(float a, float b) {
    __half2 h = __floats2half2_rn(a, b);
    return *(uint32_t*)&h;
}

// ---------------------------------------------------------------------------
// fp32 -> fp16 round. 8 elements/thread.
// ---------------------------------------------------------------------------
__global__ void conv_f16(const float* __restrict__ x, __half* __restrict__ y, int n8)
{
    int i = blockIdx.x * blockDim.x + threadIdx.x;
    if (i >= n8) return;
    const float4* xp = (const float4*)x + (size_t)i * 2;
    float4 a = xp[0], b = xp[1];
    float v[8] = {a.x, a.y, a.z, a.w, b.x, b.y, b.z, b.w};
    __half h[8];
#pragma unroll
    for (int j = 0; j < 8; j++) h[j] = __float2half_rn(v[j]);
    *((uint4*)y + i) = *(const uint4*)h;
}

// ---------------------------------------------------------------------------
// HMMA fp16 GEMM: C[M,N] = A[M,K] @ B[N,K]^T, fp32 accum.
// CTA tile 128x128, BK=64, 3-stage cp.async, 4 warps (2x2), warp tile 64x64.
// 2 CTAs per SM, one barrier per chunk.
// ---------------------------------------------------------------------------
#define BM 128
#define BN 128
#define BK 64
#define STAGES 3
#define PADK 72                        // halves per smem row (64 + 8 pad)
#define TILEA (128 * PADK * 2)         // 18432 B
#define STAGEB (2 * TILEA)             // 36864 B
#define GEMM_SMEM (STAGES * STAGEB)    // 110592 B

__global__ __launch_bounds__(128, 2)
void gemm_f16(const __half* __restrict__ Ah, const __half* __restrict__ Bh,
              float* __restrict__ C, int N, int K)
{
    extern __shared__ char smraw[];
    const uint32_t sbase = smem_u32(smraw);

    const int tid = threadIdx.x;
    const int wid = tid >> 5;
    const int lane = tid & 31;
    const int wm = wid >> 1;          // 0..1 (64 rows)
    const int wn = wid & 1;           // 0..1 (64 cols)
    const int m0 = blockIdx.y * BM;
    const int n0 = blockIdx.x * BN;
    const int NCH = K >> 6;

    auto load_chunk = [&](int c, int stg) {
        const uint32_t sb = sbase + stg * STAGEB;
        const int kc = c * BK;
#pragma unroll
        for (int i = 0; i < 8; i++) {
            int op = tid + i * 128;       // 0..1023
            int row = op >> 3;            // 0..127
            int ck = op & 7;              // 16B chunk in 128B row
            uint32_t soff = (uint32_t)(row * PADK * 2 + ck * 16);
            cp16(sb + soff, Ah + (size_t)(m0 + row) * K + kc + ck * 8);
            cp16(sb + TILEA + soff, Bh + (size_t)(n0 + row) * K + kc + ck * 8);
        }
        cp_commit();
    };

    float c[4][8][4];
#pragma unroll
    for (int i = 0; i < 4; i++)
#pragma unroll
        for (int j = 0; j < 8; j++)
#pragma unroll
            for (int q = 0; q < 4; q++) c[i][j][q] = 0.f;

    load_chunk(0, 0);
    load_chunk(1, 1);

    const int a_row = (lane & 15);
    const int a_col = ((lane >> 4) & 1) * 8;
    const int b_row = (lane & 7) + ((lane & 16) ? 8 : 0);
    const int b_col = ((lane & 8) ? 8 : 0);

    for (int cch = 0; cch < NCH; cch++) {
        cp_wait<1>();
        __syncthreads();
        // Top barrier of iteration cch ensures all warps finished reading
        // stage (cch-1)%3 (done in body cch-1), so refilling stage (cch+2)%3
        // here is safe without a trailing barrier.
        if (cch + 2 < NCH) load_chunk(cch + 2, (cch + 2) % 3);
        else cp_commit();

        const uint32_t sb = sbase + (cch % 3) * STAGEB;
        const uint32_t sA = sb;
        const uint32_t sB = sb + TILEA;

#pragma unroll
        for (int s = 0; s < 4; s++) {
            uint32_t af[16], bf[16];
#pragma unroll
            for (int i = 0; i < 4; i++) {
                int row = wm * 64 + i * 16 + a_row;
                uint32_t off = (uint32_t)((row * PADK + s * 16 + a_col) * 2);
                ldsm4(&af[i * 4], sA + off);
            }
#pragma unroll
            for (int j2 = 0; j2 < 4; j2++) {
                int row = wn * 64 + j2 * 16 + b_row;
                uint32_t off = (uint32_t)((row * PADK + s * 16 + b_col) * 2);
                ldsm4(&bf[j2 * 4], sB + off);
            }
#pragma unroll
            for (int i = 0; i < 4; i++)
#pragma unroll
                for (int j = 0; j < 8; j++)
                    mma16816(c[i][j], &af[i * 4], &bf[j * 2]);
        }
    }

    const int g = lane >> 2;
    const int tq = lane & 3;
#pragma unroll
    for (int i = 0; i < 4; i++) {
        int row0 = m0 + wm * 64 + i * 16 + g;
#pragma unroll
        for (int j = 0; j < 8; j++) {
            int col = n0 + wn * 64 + j * 8 + tq * 2;
            float2 v0 = {c[i][j][0], c[i][j][1]};
            float2 v1 = {c[i][j][2], c[i][j][3]};
            *(float2*)&C[(size_t)row0 * N + col] = v0;
            *(float2*)&C[(size_t)(row0 + 8) * N + col] = v1;
        }
    }
}

// ---------------------------------------------------------------------------
// RoPE + head-major fp16 conversion (Q scaled+rounded, K rounded, V rounded).
// ---------------------------------------------------------------------------
__global__ void rope_split(const float* __restrict__ proj, const int* __restrict__ positions,
                           __half* __restrict__ Qh, __half* __restrict__ Kh,
                           __half* __restrict__ Vh)
{
    int idx = blockIdx.x * blockDim.x + threadIdx.x;
    int i = idx & 63;
    int h = (idx >> 6) & 31;
    int t = idx >> 11;                 // token 0..4095
    int b = t >> 11;
    int s = t & 2047;

    int pos = positions[t];
    float inv = exp2f(-(float)i * (13.287712379549449f / 64.0f));
    float freq = (float)pos * inv;
    float sn, cs;
    sincosf(freq, &sn, &cs);

    const float scale = 0.08838834764831845f;  // 1/sqrt(128)

    size_t src = (size_t)t * PROJ3 + (size_t)h * HD + i;
    size_t dst = ((size_t)(b * NH + h) * S_SZ + s) * HD + i;

    {
        float x1 = proj[src], x2 = proj[src + 64];
        Qh[dst] = __float2half_rn((x1 * cs - x2 * sn) * scale);
        Qh[dst + 64] = __float2half_rn((x2 * cs + x1 * sn) * scale);
    }
    {
        float x1 = proj[src + HID], x2 = proj[src + HID + 64];
        Kh[dst] = __float2half_rn(x1 * cs - x2 * sn);
        Kh[dst + 64] = __float2half_rn(x2 * cs + x1 * sn);
    }
    {
        Vh[dst] = __float2half_rn(proj[src + 2 * HID]);
        Vh[dst + 64] = __float2half_rn(proj[src + 2 * HID + 64]);
    }
}

// ---------------------------------------------------------------------------
// HMMA flash attention, causal. Br=128 (8 warps x 16 rows), Bc=64.
// S = Qh @ Kh^T ; O = P @ Vh. Epilogue writes Xh (fp16 rounded).
// ---------------------------------------------------------------------------
#define ATT_PAD 136
#define KVROWB (ATT_PAD * 2)            // 272 bytes
#define KTILE (64 * KVROWB)             // 17408
#define ASTG (2 * KTILE)                // K, V
#define ATT_SMEM (3 * ASTG)             // 104448

__global__ __launch_bounds__(256, 1)
void flash_attn_hmma(const __half* __restrict__ Qh, const __half* __restrict__ Kh,
                     const __half* __restrict__ Vh, __half* __restrict__ Xh)
{
    extern __shared__ char smraw[];
    const uint32_t sbase = smem_u32(smraw);

    const int tid = threadIdx.x;
    const int wid = tid >> 5;
    const int lane = tid & 31;
    const int g = lane >> 2;
    const int tq = lane & 3;

    const int qb = 15 - (int)blockIdx.x;
    const int bh = blockIdx.y;
    const int b = bh >> 5;
    const int h = bh & 31;
    const size_t hb = (size_t)bh * S_SZ * HD;
    const int row0 = qb * 128;
    const int wr = wid * 16;
    const int nkb = 2 * qb + 2;

    uint32_t qhf[8][4];
    {
        const __half* qsrc = Qh + hb + (size_t)row0 * HD;
#pragma unroll
        for (int i = 0; i < 8; i++) {
            int op = tid + i * 256;
            int r = op >> 4;
            int ck = op & 15;
            cp16(sbase + (uint32_t)(r * KVROWB + ck * 16), qsrc + (size_t)r * HD + ck * 8);
        }
        cp_commit();
        cp_wait<0>();
        __syncthreads();
#pragma unroll
        for (int ks = 0; ks < 8; ks++) {
            uint32_t off = (uint32_t)((wr + (lane & 15)) * KVROWB +
                                      (ks * 16 + ((lane >> 4) << 3)) * 2);
            ldsm4(qhf[ks], sbase + off);
        }
        __syncthreads();
    }

    float o[16][4];
#pragma unroll
    for (int j = 0; j < 16; j++)
#pragma unroll
        for (int q = 0; q < 4; q++) o[j][q] = 0.f;
    float m_old0 = -1e30f, m_old1 = -1e30f, l0 = 0.f, l1 = 0.f;

    auto kvload = [&](int kb, int stg) {
        const uint32_t sb = sbase + stg * ASTG;
        const size_t src0 = hb + (size_t)kb * 64 * HD;
#pragma unroll
        for (int i = 0; i < 4; i++) {
            int op = tid + i * 256;
            int r = op >> 4;
            int ck = op & 15;
            uint32_t soff = (uint32_t)(r * KVROWB + ck * 16);
            size_t goff = src0 + (size_t)r * HD + ck * 8;
            cp16(sb + soff, Kh + goff);
            cp16(sb + KTILE + soff, Vh + goff);
        }
        cp_commit();
    };

    kvload(0, 0);
    kvload(1, 1);

    const int r_g = row0 + wr + g;

    for (int kb = 0; kb < nkb; kb++) {
        cp_wait<1>();
        __syncthreads();
        if (kb + 2 < nkb) kvload(kb + 2, (kb + 2) % 3);
        else cp_commit();

        const uint32_t sK = sbase + (kb % 3) * ASTG;
        const uint32_t sV = sK + KTILE;

        float s[8][4];
#pragma unroll
        for (int j = 0; j < 8; j++)
#pragma unroll
            for (int q = 0; q < 4; q++) s[j][q] = 0.f;

#pragma unroll
        for (int ks = 0; ks < 8; ks++) {
            uint32_t bk[16];
#pragma unroll
            for (int j2 = 0; j2 < 4; j2++) {
                int r = j2 * 16 + (lane & 7) + ((lane & 16) ? 8 : 0);
                uint32_t off = (uint32_t)(r * KVROWB + (ks * 16 + ((lane & 8) ? 8 : 0)) * 2);
                ldsm4(&bk[j2 * 4], sK + off);
            }
#pragma unroll
            for (int j = 0; j < 8; j++) mma16816(s[j], qhf[ks], &bk[j * 2]);
        }

        const int kv0 = kb * 64;
        if (kv0 + 63 > row0 + wr) {
#pragma unroll
            for (int j = 0; j < 8; j++) {
                int cc = kv0 + j * 8 + 2 * tq;
                if (cc > r_g) s[j][0] = -1e30f;
                if (cc + 1 > r_g) s[j][1] = -1e30f;
                if (cc > r_g + 8) s[j][2] = -1e30f;
                if (cc + 1 > r_g + 8) s[j][3] = -1e30f;
            }
        }

        float mx0 = -1e30f, mx1 = -1e30f;
#pragma unroll
        for (int j = 0; j < 8; j++) {
            mx0 = fmaxf(mx0, fmaxf(s[j][0], s[j][1]));
            mx1 = fmaxf(mx1, fmaxf(s[j][2], s[j][3]));
        }
        mx0 = fmaxf(mx0, __shfl_xor_sync(0xffffffffu, mx0, 1));
        mx0 = fmaxf(mx0, __shfl_xor_sync(0xffffffffu, mx0, 2));
        mx1 = fmaxf(mx1, __shfl_xor_sync(0xffffffffu, mx1, 1));
        mx1 = fmaxf(mx1, __shfl_xor_sync(0xffffffffu, mx1, 2));

        float mn0 = fmaxf(m_old0, mx0);
        float mn1 = fmaxf(m_old1, mx1);
        float a0 = __expf(m_old0 - mn0);
        float a1 = __expf(m_old1 - mn1);

        float sum0 = 0.f, sum1 = 0.f;
        uint32_t pa[4][4];
#pragma unroll
        for (int ks = 0; ks < 4; ks++) {
            float p00 = __expf(s[2 * ks][0] - mn0);
            float p01 = __expf(s[2 * ks][1] - mn0);
            float p02 = __expf(s[2 * ks][2] - mn1);
            float p03 = __expf(s[2 * ks][3] - mn1);
            float p10 = __expf(s[2 * ks + 1][0] - mn0);
            float p11 = __expf(s[2 * ks + 1][1] - mn0);
            float p12 = __expf(s[2 * ks + 1][2] - mn1);
            float p13 = __expf(s[2 * ks + 1][3] - mn1);
            sum0 += p00 + p01 + p10 + p11;
            sum1 += p02 + p03 + p12 + p13;
            pa[ks][0] = packh2(p00, p01);
            pa[ks][1] = packh2(p02, p03);
            pa[ks][2] = packh2(p10, p11);
            pa[ks][3] = packh2(p12, p13);
        }
        sum0 += __shfl_xor_sync(0xffffffffu, sum0, 1);
        sum0 += __shfl_xor_sync(0xffffffffu, sum0, 2);
        sum1 += __shfl_xor_sync(0xffffffffu, sum1, 1);
        sum1 += __shfl_xor_sync(0xffffffffu, sum1, 2);

        l0 = l0 * a0 + sum0;
        l1 = l1 * a1 + sum1;
        m_old0 = mn0;
        m_old1 = mn1;

#pragma unroll
        for (int j = 0; j < 16; j++) {
            o[j][0] *= a0; o[j][1] *= a0;
            o[j][2] *= a1; o[j][3] *= a1;
        }

#pragma unroll
        for (int ks = 0; ks < 4; ks++) {
#pragma unroll
            for (int jj = 0; jj < 8; jj++) {
                int krow = ks * 16 + (lane & 15);
                uint32_t off = (uint32_t)(krow * KVROWB + (jj * 16 + ((lane & 16) ? 8 : 0)) * 2);
                uint32_t bv[4];
                ldsm4t(bv, sV + off);
                mma16816(o[jj * 2], pa[ks], &bv[0]);
                mma16816(o[jj * 2 + 1], pa[ks], &bv[2]);
            }
        }
    }

    const float il0 = 1.f / l0;
    const float il1 = 1.f / l1;
    const int tok0 = b * S_SZ + row0 + wr;
#pragma unroll
    for (int j = 0; j < 16; j++) {
        int col = h * HD + j * 8 + 2 * tq;
        size_t i0 = (size_t)(tok0 + g) * HID + col;
        size_t i1 = (size_t)(tok0 + g + 8) * HID + col;
        *(uint32_t*)&Xh[i0] = packh2(o[j][0] * il0, o[j][1] * il0);
        *(uint32_t*)&Xh[i1] = packh2(o[j][2] * il1, o[j][3] * il1);
    }
}

// ---------------------------------------------------------------------------
// Launch
// ---------------------------------------------------------------------------
extern "C" void kernel_launch(void* const* d_in, const int* in_sizes, int n_in,
                              void* d_out, int out_size)
{
    const float* hidden = (const float*)d_in[0];
    const int* positions = (const int*)d_in[1];
    const float* W_pack = (const float*)d_in[2];
    const float* W_o = (const float*)d_in[3];
    float* out = (float*)d_out;

    void* pp; cudaGetSymbolAddress(&pp, g_proj);
    float* proj = (float*)pp;

    void* v_ah; cudaGetSymbolAddress(&v_ah, g_Ah);
    void* v_wp; cudaGetSymbolAddress(&v_wp, g_Wp);
    void* v_wo; cudaGetSymbolAddress(&v_wo, g_Wo);
    void* v_xh; cudaGetSymbolAddress(&v_xh, g_Xh);
    void* v_qh; cudaGetSymbolAddress(&v_qh, g_Qh);
    void* v_kh; cudaGetSymbolAddress(&v_kh, g_Kh);
    void* v_vh; cudaGetSymbolAddress(&v_vh, g_Vh);

    cudaFuncSetAttribute(gemm_f16, cudaFuncAttributeMaxDynamicSharedMemorySize, GEMM_SMEM);
    cudaFuncSetAttribute(flash_attn_hmma, cudaFuncAttributeMaxDynamicSharedMemorySize, ATT_SMEM);

    // 0) operand prep
    {
        int n8 = TOK * HID / 8;
        conv_f16<<<(n8 + 255) / 256, 256>>>(hidden, (__half*)v_ah, n8);
        int w8 = PROJ3 * HID / 8;
        conv_f16<<<(w8 + 255) / 256, 256>>>(W_pack, (__half*)v_wp, w8);
        int o8 = HID * HID / 8;
        conv_f16<<<(o8 + 255) / 256, 256>>>(W_o, (__half*)v_wo, o8);
    }

    // 1) QKV projection: proj = hidden @ W_pack^T
    {
        dim3 grid(PROJ3 / BN, TOK / BM);  // 96 x 32
        gemm_f16<<<grid, 128, GEMM_SMEM>>>((const __half*)v_ah, (const __half*)v_wp,
                                           proj, PROJ3, HID);
    }

    // 2) RoPE + fp16 conversion to head-major layout
    {
        int total = TOK * NH * 64;
        rope_split<<<total / 256, 256>>>(proj, positions,
                                         (__half*)v_qh, (__half*)v_kh, (__half*)v_vh);
    }

    // 3) Causal attention on tensor cores; writes Xh directly
    {
        dim3 grid(S_SZ / 128, B_SZ * NH);  // 16 x 64
        flash_attn_hmma<<<grid, 256, ATT_SMEM>>>((const __half*)v_qh, (const __half*)v_kh,
                                                 (const __half*)v_vh, (__half*)v_xh);
    }

    // 4) out = attn @ W_o^T
    {
        dim3 grid(HID / BN, TOK / BM);  // 32 x 32
        gemm_f16<<<grid, 128, GEMM_SMEM>>>((const __half*)v_xh, (const __half*)v_wo,
                                           out, HID, HID);
    }
}

// round 10
// speedup vs baseline: 8.5761x; 1.0564x over previous
#include <cuda_runtime.h>
#include <cuda_fp16.h>
#include <math.h>
#include <stdint.h>

// Problem constants
#define B_SZ 2
#define S_SZ 2048
#define HID 4096
#define NH 32
#define HD 128
#define TOK (B_SZ * S_SZ)          // 4096 tokens
#define PROJ3 (3 * HID)            // 12288

// Scratch (static device globals — allocation-free rule)
__device__ __half g_Ah[(size_t)TOK * HID];
__device__ __half g_Wp[(size_t)PROJ3 * HID];
__device__ __half g_Wo[(size_t)HID * HID];
__device__ __half g_Xh[(size_t)TOK * HID];
// head-major fp16 attention operands [b*NH+h][s][d]
__device__ __half g_Qh[(size_t)TOK * HID];
__device__ __half g_Kh[(size_t)TOK * HID];
__device__ __half g_Vh[(size_t)TOK * HID];

// ---------------------------------------------------------------------------
// Inline PTX helpers
// ---------------------------------------------------------------------------
__device__ __forceinline__ uint32_t smem_u32(const void* p) {
    uint32_t a;
    asm("{ .reg .u64 t; cvta.to.shared.u64 t, %1; cvt.u32.u64 %0, t; }" : "=r"(a) : "l"(p));
    return a;
}
__device__ __forceinline__ void cp16(uint32_t dst, const void* src) {
    asm volatile("cp.async.cg.shared.global [%0], [%1], 16;" :: "r"(dst), "l"(src) : "memory");
}
__device__ __forceinline__ void cp_commit() { asm volatile("cp.async.commit_group;" ::: "memory"); }
template <int N>
__device__ __forceinline__ void cp_wait() {
    asm volatile("cp.async.wait_group %0;" :: "n"(N) : "memory");
}
__device__ __forceinline__ void ldsm4(uint32_t r[4], uint32_t addr) {
    asm volatile("ldmatrix.sync.aligned.m8n8.x4.shared.b16 {%0,%1,%2,%3}, [%4];"
                 : "=r"(r[0]), "=r"(r[1]), "=r"(r[2]), "=r"(r[3]) : "r"(addr));
}
__device__ __forceinline__ void ldsm4t(uint32_t r[4], uint32_t addr) {
    asm volatile("ldmatrix.sync.aligned.m8n8.x4.trans.shared.b16 {%0,%1,%2,%3}, [%4];"
                 : "=r"(r[0]), "=r"(r[1]), "=r"(r[2]), "=r"(r[3]) : "r"(addr));
}
__device__ __forceinline__ void mma16816(float c[4], const uint32_t a[4], const uint32_t b[2]) {
    asm volatile(
        "mma.sync.aligned.m16n8k16.row.col.f32.f16.f16.f32 "
        "{%0,%1,%2,%3}, {%4,%5,%6,%7}, {%8,%9}, {%0,%1,%2,%3};"
        : "+f"(c[0]), "+f"(c[1]), "+f"(c[2]), "+f"(c[3])
        : "r"(a[0]), "r"(a[1]), "r"(a[2]), "r"(a[3]), "r"(b[0]), "r"(b[1]));
}
__device__ __forceinline__ uint32_t packh2(float a, float b) {
    __half2 h = __floats2half2_rn(a, b);
    return *(uint32_t*)&h;
}

// ---------------------------------------------------------------------------
// fp32 -> fp16 round. 8 elements/thread.
// ---------------------------------------------------------------------------
__global__ void conv_f16(const float* __restrict__ x, __half* __restrict__ y, int n8)
{
    int i = blockIdx.x * blockDim.x + threadIdx.x;
    if (i >= n8) return;
    const float4* xp = (const float4*)x + (size_t)i * 2;
    float4 a = xp[0], b = xp[1];
    float v[8] = {a.x, a.y, a.z, a.w, b.x, b.y, b.z, b.w};
    __half h[8];
#pragma unroll
    for (int j = 0; j < 8; j++) h[j] = __float2half_rn(v[j]);
    *((uint4*)y + i) = *(const uint4*)h;
}

// ---------------------------------------------------------------------------
// Shared GEMM mainloop config: CTA 128x128, BK=64, 3-stage cp.async,
// 8 warps (2x4), warp tile 64x32, 2 CTAs/SM, one barrier per chunk.
// ---------------------------------------------------------------------------
#define BM 128
#define BN 128
#define BK 64
#define PADK 72                        // halves per smem row (64 + 8 pad)
#define TILEA (128 * PADK * 2)         // 18432 B
#define STAGEB (2 * TILEA)             // 36864 B
#define GEMM_SMEM (3 * STAGEB)         // 110592 B

// Mainloop macro body (shared by gemm_f16 and gemm_qkv).
// Defines/uses: c[4][4][4] accumulators, sbase, tid/wid/lane/wm/wn, m0/n0.
#define GEMM_MAINLOOP(Aptr, Bptr, Kval)                                          \
    const int NCH = (Kval) >> 6;                                                 \
    auto load_chunk = [&](int cc, int stg) {                                     \
        const uint32_t sb = sbase + stg * STAGEB;                                \
        const int kc = cc * BK;                                                  \
        _Pragma("unroll")                                                        \
        for (int i = 0; i < 4; i++) {                                            \
            int op = tid + i * 256;                                              \
            int row = op >> 3;                                                   \
            int ck = op & 7;                                                     \
            uint32_t soff = (uint32_t)(row * PADK * 2 + ck * 16);                \
            cp16(sb + soff, (Aptr) + (size_t)(m0 + row) * (Kval) + kc + ck * 8); \
            cp16(sb + TILEA + soff,                                              \
                 (Bptr) + (size_t)(n0 + row) * (Kval) + kc + ck * 8);            \
        }                                                                        \
        cp_commit();                                                             \
    };                                                                           \
    load_chunk(0, 0);                                                            \
    load_chunk(1, 1);                                                            \
    const int a_row = (lane & 15);                                               \
    const int a_col = ((lane >> 4) & 1) * 8;                                     \
    const int b_row = (lane & 7) + ((lane & 16) ? 8 : 0);                        \
    const int b_col = ((lane & 8) ? 8 : 0);                                      \
    for (int cch = 0; cch < NCH; cch++) {                                        \
        cp_wait<1>();                                                            \
        __syncthreads();                                                         \
        if (cch + 2 < NCH) load_chunk(cch + 2, (cch + 2) % 3);                   \
        else cp_commit();                                                        \
        const uint32_t sb = sbase + (cch % 3) * STAGEB;                          \
        const uint32_t sA = sb;                                                  \
        const uint32_t sB = sb + TILEA;                                          \
        _Pragma("unroll")                                                        \
        for (int s = 0; s < 4; s++) {                                            \
            uint32_t af[16], bf[8];                                              \
            _Pragma("unroll")                                                    \
            for (int i = 0; i < 4; i++) {                                        \
                int row = wm * 64 + i * 16 + a_row;                              \
                uint32_t off = (uint32_t)((row * PADK + s * 16 + a_col) * 2);    \
                ldsm4(&af[i * 4], sA + off);                                     \
            }                                                                    \
            _Pragma("unroll")                                                    \
            for (int j2 = 0; j2 < 2; j2++) {                                     \
                int row = wn * 32 + j2 * 16 + b_row;                             \
                uint32_t off = (uint32_t)((row * PADK + s * 16 + b_col) * 2);    \
                ldsm4(&bf[j2 * 4], sB + off);                                    \
            }                                                                    \
            _Pragma("unroll")                                                    \
            for (int i = 0; i < 4; i++)                                          \
                _Pragma("unroll")                                                \
                for (int j = 0; j < 4; j++)                                      \
                    mma16816(c[i][j], &af[i * 4], &bf[j * 2]);                   \
        }                                                                        \
    }

// ---------------------------------------------------------------------------
// Plain GEMM: C[M,N] = A @ B^T, fp32 out (used for O-projection).
// ---------------------------------------------------------------------------
__global__ __launch_bounds__(256, 2)
void gemm_f16(const __half* __restrict__ Ah, const __half* __restrict__ Bh,
              float* __restrict__ C, int N, int K)
{
    extern __shared__ char smraw[];
    const uint32_t sbase = smem_u32(smraw);

    const int tid = threadIdx.x;
    const int wid = tid >> 5;
    const int lane = tid & 31;
    const int wm = wid >> 2;
    const int wn = wid & 3;
    const int m0 = blockIdx.y * BM;
    const int n0 = blockIdx.x * BN;

    float c[4][4][4];
#pragma unroll
    for (int i = 0; i < 4; i++)
#pragma unroll
        for (int j = 0; j < 4; j++)
#pragma unroll
            for (int q = 0; q < 4; q++) c[i][j][q] = 0.f;

    GEMM_MAINLOOP(Ah, Bh, K)

    const int g = lane >> 2;
    const int tq = lane & 3;
#pragma unroll
    for (int i = 0; i < 4; i++) {
        int row0 = m0 + wm * 64 + i * 16 + g;
#pragma unroll
        for (int j = 0; j < 4; j++) {
            int col = n0 + wn * 32 + j * 8 + tq * 2;
            float2 v0 = {c[i][j][0], c[i][j][1]};
            float2 v1 = {c[i][j][2], c[i][j][3]};
            *(float2*)&C[(size_t)row0 * N + col] = v0;
            *(float2*)&C[(size_t)(row0 + 8) * N + col] = v1;
        }
    }
}

// ---------------------------------------------------------------------------
// QKV GEMM with fused RoPE + fp16 head-major epilogue.
// Each CTA tile (128 tokens x 128 proj cols) is exactly one head of q|k|v.
// Accumulators staged in smem fp32, then RoPE'd and written to Qh/Kh/Vh.
// ---------------------------------------------------------------------------
#define SCPAD 132   // fp32 row stride in epilogue smem

__global__ __launch_bounds__(256, 2)
void gemm_qkv(const __half* __restrict__ Ah, const __half* __restrict__ Bh,
              const int* __restrict__ positions,
              __half* __restrict__ Qh, __half* __restrict__ Kh,
              __half* __restrict__ Vh, int N, int K)
{
    extern __shared__ char smraw[];
    const uint32_t sbase = smem_u32(smraw);

    const int tid = threadIdx.x;
    const int wid = tid >> 5;
    const int lane = tid & 31;
    const int wm = wid >> 2;
    const int wn = wid & 3;
    const int m0 = blockIdx.y * BM;
    const int n0 = blockIdx.x * BN;

    float c[4][4][4];
#pragma unroll
    for (int i = 0; i < 4; i++)
#pragma unroll
        for (int j = 0; j < 4; j++)
#pragma unroll
            for (int q = 0; q < 4; q++) c[i][j][q] = 0.f;

    GEMM_MAINLOOP(Ah, Bh, K)

    // ---- fused epilogue: stage fp32 tile in smem ----
    cp_wait<0>();
    __syncthreads();                 // all warps done with pipeline smem
    float* sc = (float*)smraw;       // [128][SCPAD]

    const int g = lane >> 2;
    const int tq = lane & 3;
#pragma unroll
    for (int i = 0; i < 4; i++) {
        int r0 = wm * 64 + i * 16 + g;
#pragma unroll
        for (int j = 0; j < 4; j++) {
            int col = wn * 32 + j * 8 + tq * 2;
            *(float2*)&sc[r0 * SCPAD + col] = make_float2(c[i][j][0], c[i][j][1]);
            *(float2*)&sc[(r0 + 8) * SCPAD + col] = make_float2(c[i][j][2], c[i][j][3]);
        }
    }
    __syncthreads();

    // region: 0=q, 1=k, 2=v ; head index within region
    const int region = n0 >> 12;
    const int h = (n0 & 4095) >> 7;
    const float qscale = (region == 0) ? 0.08838834764831845f : 1.0f;
    __half* outp = (region == 0) ? Qh : (region == 1 ? Kh : Vh);

    // thread map: (tid&15) -> 4 consecutive pair-indices, (tid>>4) -> row group
    const int i0 = (tid & 15) * 4;
    const int rbase = tid >> 4;

#pragma unroll 1
    for (int rr = 0; rr < 8; rr++) {
        int row = rbase + rr * 16;
        int t = m0 + row;
        int pos = positions[t];
        int bb = t >> 11;            // S=2048
        int ss = t & 2047;
        __half* dp = outp + ((size_t)(bb * NH + h) * S_SZ + ss) * HD;

        float r1v[4], r2v[4];
#pragma unroll
        for (int ii = 0; ii < 4; ii++) {
            int i = i0 + ii;
            float x1 = sc[row * SCPAD + i];
            float x2 = sc[row * SCPAD + i + 64];
            float cs, sn;
            if (region < 2) {
                float f = (float)pos * exp2f(-(float)i * (13.287712379549449f / 64.0f));
                sincosf(f, &sn, &cs);
            } else { cs = 1.f; sn = 0.f; }
            r1v[ii] = (x1 * cs - x2 * sn) * qscale;
            r2v[ii] = (x2 * cs + x1 * sn) * qscale;
        }
        *(uint32_t*)&dp[i0]     = packh2(r1v[0], r1v[1]);
        *(uint32_t*)&dp[i0 + 2] = packh2(r1v[2], r1v[3]);
        *(uint32_t*)&dp[i0 + 64] = packh2(r2v[0], r2v[1]);
        *(uint32_t*)&dp[i0 + 66] = packh2(r2v[2], r2v[3]);
    }
}

// ---------------------------------------------------------------------------
// HMMA flash attention, causal. Br=128 (8 warps x 16 rows), Bc=64.
// S = Qh @ Kh^T ; O = P @ Vh. Epilogue writes Xh (fp16 rounded).
// ---------------------------------------------------------------------------
#define ATT_PAD 136
#define KVROWB (ATT_PAD * 2)            // 272 bytes
#define KTILE (64 * KVROWB)             // 17408
#define ASTG (2 * KTILE)                // K, V
#define ATT_SMEM (3 * ASTG)             // 104448

__global__ __launch_bounds__(256, 1)
void flash_attn_hmma(const __half* __restrict__ Qh, const __half* __restrict__ Kh,
                     const __half* __restrict__ Vh, __half* __restrict__ Xh)
{
    extern __shared__ char smraw[];
    const uint32_t sbase = smem_u32(smraw);

    const int tid = threadIdx.x;
    const int wid = tid >> 5;
    const int lane = tid & 31;
    const int g = lane >> 2;
    const int tq = lane & 3;

    const int qb = 15 - (int)blockIdx.x;
    const int bh = blockIdx.y;
    const int b = bh >> 5;
    const int h = bh & 31;
    const size_t hb = (size_t)bh * S_SZ * HD;
    const int row0 = qb * 128;
    const int wr = wid * 16;
    const int nkb = 2 * qb + 2;

    uint32_t qhf[8][4];
    {
        const __half* qsrc = Qh + hb + (size_t)row0 * HD;
#pragma unroll
        for (int i = 0; i < 8; i++) {
            int op = tid + i * 256;
            int r = op >> 4;
            int ck = op & 15;
            cp16(sbase + (uint32_t)(r * KVROWB + ck * 16), qsrc + (size_t)r * HD + ck * 8);
        }
        cp_commit();
        cp_wait<0>();
        __syncthreads();
#pragma unroll
        for (int ks = 0; ks < 8; ks++) {
            uint32_t off = (uint32_t)((wr + (lane & 15)) * KVROWB +
                                      (ks * 16 + ((lane >> 4) << 3)) * 2);
            ldsm4(qhf[ks], sbase + off);
        }
        __syncthreads();
    }

    float o[16][4];
#pragma unroll
    for (int j = 0; j < 16; j++)
#pragma unroll
        for (int q = 0; q < 4; q++) o[j][q] = 0.f;
    float m_old0 = -1e30f, m_old1 = -1e30f, l0 = 0.f, l1 = 0.f;

    auto kvload = [&](int kb, int stg) {
        const uint32_t sb = sbase + stg * ASTG;
        const size_t src0 = hb + (size_t)kb * 64 * HD;
#pragma unroll
        for (int i = 0; i < 4; i++) {
            int op = tid + i * 256;
            int r = op >> 4;
            int ck = op & 15;
            uint32_t soff = (uint32_t)(r * KVROWB + ck * 16);
            size_t goff = src0 + (size_t)r * HD + ck * 8;
            cp16(sb + soff, Kh + goff);
            cp16(sb + KTILE + soff, Vh + goff);
        }
        cp_commit();
    };

    kvload(0, 0);
    kvload(1, 1);

    const int r_g = row0 + wr + g;

    for (int kb = 0; kb < nkb; kb++) {
        cp_wait<1>();
        __syncthreads();
        if (kb + 2 < nkb) kvload(kb + 2, (kb + 2) % 3);
        else cp_commit();

        const uint32_t sK = sbase + (kb % 3) * ASTG;
        const uint32_t sV = sK + KTILE;

        float s[8][4];
#pragma unroll
        for (int j = 0; j < 8; j++)
#pragma unroll
            for (int q = 0; q < 4; q++) s[j][q] = 0.f;

#pragma unroll
        for (int ks = 0; ks < 8; ks++) {
            uint32_t bk[16];
#pragma unroll
            for (int j2 = 0; j2 < 4; j2++) {
                int r = j2 * 16 + (lane & 7) + ((lane & 16) ? 8 : 0);
                uint32_t off = (uint32_t)(r * KVROWB + (ks * 16 + ((lane & 8) ? 8 : 0)) * 2);
                ldsm4(&bk[j2 * 4], sK + off);
            }
#pragma unroll
            for (int j = 0; j < 8; j++) mma16816(s[j], qhf[ks], &bk[j * 2]);
        }

        const int kv0 = kb * 64;
        if (kv0 + 63 > row0 + wr) {
#pragma unroll
            for (int j = 0; j < 8; j++) {
                int cc = kv0 + j * 8 + 2 * tq;
                if (cc > r_g) s[j][0] = -1e30f;
                if (cc + 1 > r_g) s[j][1] = -1e30f;
                if (cc > r_g + 8) s[j][2] = -1e30f;
                if (cc + 1 > r_g + 8) s[j][3] = -1e30f;
            }
        }

        float mx0 = -1e30f, mx1 = -1e30f;
#pragma unroll
        for (int j = 0; j < 8; j++) {
            mx0 = fmaxf(mx0, fmaxf(s[j][0], s[j][1]));
            mx1 = fmaxf(mx1, fmaxf(s[j][2], s[j][3]));
        }
        mx0 = fmaxf(mx0, __shfl_xor_sync(0xffffffffu, mx0, 1));
        mx0 = fmaxf(mx0, __shfl_xor_sync(0xffffffffu, mx0, 2));
        mx1 = fmaxf(mx1, __shfl_xor_sync(0xffffffffu, mx1, 1));
        mx1 = fmaxf(mx1, __shfl_xor_sync(0xffffffffu, mx1, 2));

        float mn0 = fmaxf(m_old0, mx0);
        float mn1 = fmaxf(m_old1, mx1);
        float a0 = __expf(m_old0 - mn0);
        float a1 = __expf(m_old1 - mn1);

        float sum0 = 0.f, sum1 = 0.f;
        uint32_t pa[4][4];
#pragma unroll
        for (int ks = 0; ks < 4; ks++) {
            float p00 = __expf(s[2 * ks][0] - mn0);
            float p01 = __expf(s[2 * ks][1] - mn0);
            float p02 = __expf(s[2 * ks][2] - mn1);
            float p03 = __expf(s[2 * ks][3] - mn1);
            float p10 = __expf(s[2 * ks + 1][0] - mn0);
            float p11 = __expf(s[2 * ks + 1][1] - mn0);
            float p12 = __expf(s[2 * ks + 1][2] - mn1);
            float p13 = __expf(s[2 * ks + 1][3] - mn1);
            sum0 += p00 + p01 + p10 + p11;
            sum1 += p02 + p03 + p12 + p13;
            pa[ks][0] = packh2(p00, p01);
            pa[ks][1] = packh2(p02, p03);
            pa[ks][2] = packh2(p10, p11);
            pa[ks][3] = packh2(p12, p13);
        }
        sum0 += __shfl_xor_sync(0xffffffffu, sum0, 1);
        sum0 += __shfl_xor_sync(0xffffffffu, sum0, 2);
        sum1 += __shfl_xor_sync(0xffffffffu, sum1, 1);
        sum1 += __shfl_xor_sync(0xffffffffu, sum1, 2);

        l0 = l0 * a0 + sum0;
        l1 = l1 * a1 + sum1;
        m_old0 = mn0;
        m_old1 = mn1;

#pragma unroll
        for (int j = 0; j < 16; j++) {
            o[j][0] *= a0; o[j][1] *= a0;
            o[j][2] *= a1; o[j][3] *= a1;
        }

#pragma unroll
        for (int ks = 0; ks < 4; ks++) {
#pragma unroll
            for (int jj = 0; jj < 8; jj++) {
                int krow = ks * 16 + (lane & 15);
                uint32_t off = (uint32_t)(krow * KVROWB + (jj * 16 + ((lane & 16) ? 8 : 0)) * 2);
                uint32_t bv[4];
                ldsm4t(bv, sV + off);
                mma16816(o[jj * 2], pa[ks], &bv[0]);
                mma16816(o[jj * 2 + 1], pa[ks], &bv[2]);
            }
        }
    }

    const float il0 = 1.f / l0;
    const float il1 = 1.f / l1;
    const int tok0 = b * S_SZ + row0 + wr;
#pragma unroll
    for (int j = 0; j < 16; j++) {
        int col = h * HD + j * 8 + 2 * tq;
        size_t i0 = (size_t)(tok0 + g) * HID + col;
        size_t i1 = (size_t)(tok0 + g + 8) * HID + col;
        *(uint32_t*)&Xh[i0] = packh2(o[j][0] * il0, o[j][1] * il0);
        *(uint32_t*)&Xh[i1] = packh2(o[j][2] * il1, o[j][3] * il1);
    }
}

// ---------------------------------------------------------------------------
// Launch
// ---------------------------------------------------------------------------
extern "C" void kernel_launch(void* const* d_in, const int* in_sizes, int n_in,
                              void* d_out, int out_size)
{
    const float* hidden = (const float*)d_in[0];
    const int* positions = (const int*)d_in[1];
    const float* W_pack = (const float*)d_in[2];
    const float* W_o = (const float*)d_in[3];
    float* out = (float*)d_out;

    void* v_ah; cudaGetSymbolAddress(&v_ah, g_Ah);
    void* v_wp; cudaGetSymbolAddress(&v_wp, g_Wp);
    void* v_wo; cudaGetSymbolAddress(&v_wo, g_Wo);
    void* v_xh; cudaGetSymbolAddress(&v_xh, g_Xh);
    void* v_qh; cudaGetSymbolAddress(&v_qh, g_Qh);
    void* v_kh; cudaGetSymbolAddress(&v_kh, g_Kh);
    void* v_vh; cudaGetSymbolAddress(&v_vh, g_Vh);

    cudaFuncSetAttribute(gemm_f16, cudaFuncAttributeMaxDynamicSharedMemorySize, GEMM_SMEM);
    cudaFuncSetAttribute(gemm_qkv, cudaFuncAttributeMaxDynamicSharedMemorySize, GEMM_SMEM);
    cudaFuncSetAttribute(flash_attn_hmma, cudaFuncAttributeMaxDynamicSharedMemorySize, ATT_SMEM);

    // 0) operand prep
    {
        int n8 = TOK * HID / 8;
        conv_f16<<<(n8 + 255) / 256, 256>>>(hidden, (__half*)v_ah, n8);
        int w8 = PROJ3 * HID / 8;
        conv_f16<<<(w8 + 255) / 256, 256>>>(W_pack, (__half*)v_wp, w8);
        int o8 = HID * HID / 8;
        conv_f16<<<(o8 + 255) / 256, 256>>>(W_o, (__half*)v_wo, o8);
    }

    // 1) QKV projection + fused RoPE + fp16 head-major conversion
    {
        dim3 grid(PROJ3 / BN, TOK / BM);  // 96 x 32
        gemm_qkv<<<grid, 256, GEMM_SMEM>>>((const __half*)v_ah, (const __half*)v_wp,
                                           positions,
                                           (__half*)v_qh, (__half*)v_kh, (__half*)v_vh,
                                           PROJ3, HID);
    }

    // 2) Causal attention on tensor cores; writes Xh directly
    {
        dim3 grid(S_SZ / 128, B_SZ * NH);  // 16 x 64
        flash_attn_hmma<<<grid, 256, ATT_SMEM>>>((const __half*)v_qh, (const __half*)v_kh,
                                                 (const __half*)v_vh, (__half*)v_xh);
    }

    // 3) out = attn @ W_o^T
    {
        dim3 grid(HID / BN, TOK / BM);  // 32 x 32
        gemm_f16<<<grid, 256, GEMM_SMEM>>>((const __half*)v_xh, (const __half*)v_wo,
                                           out, HID, HID);
    }
}